// round 3
// baseline (speedup 1.0000x reference)
#include <cuda_runtime.h>
#include <math.h>

constexpr int B = 4, T = 4096, S = 4096, E = 16;
constexpr int NH = 16, H = 4, MDNH = 16, FFNH = 64;
constexpr int MD = 256, FF = 1024, OUT = 16;
constexpr int NTOK = B * T;

// Scratch (static device allocations — no cudaMalloc allowed)
__device__ int   g_idx[NTOK * NH];                 // 1 MB
__device__ float g_oflat[(size_t)NTOK * MD];       // 16.8 MB (L2-resident)

__device__ __forceinline__ float gelu_exact(float x) { return x * normcdff(x); }

// ---------------------------------------------------------------------------
// K1: 16-nearest-neighbor selection. One thread per target point.
// Register-resident sorted list; fully predicated insertion (no local mem).
// Stable: ascending dist2, ties keep lower source index (matches top_k).
// ---------------------------------------------------------------------------
__global__ __launch_bounds__(64) void knn_kernel(const float* __restrict__ ct,
                                                 const float* __restrict__ cs) {
    __shared__ float2 scs[S];  // 32 KB
    const int b = blockIdx.y;
    const float* csb = cs + (size_t)b * S * 2;
    for (int i = threadIdx.x; i < S; i += 64)
        scs[i] = make_float2(csb[2 * i], csb[2 * i + 1]);
    __syncthreads();

    const int t = blockIdx.x * 64 + threadIdx.x;
    const float tx = ct[((size_t)b * T + t) * 2 + 0];
    const float ty = ct[((size_t)b * T + t) * 2 + 1];

    float bd[NH];
    int   bi[NH];
#pragma unroll
    for (int i = 0; i < NH; i++) { bd[i] = 3.4e38f; bi[i] = 0; }
    float worst = 3.4e38f;

#pragma unroll 4
    for (int s = 0; s < S; s++) {
        float2 c = scs[s];
        float dx = tx - c.x, dy = ty - c.y;
        float d2 = fmaf(dy, dy, dx * dx);
        if (d2 < worst) {
            float cd = d2; int ci = s;
            bool ins = false;
#pragma unroll
            for (int j = 0; j < NH; j++) {
                bool sm = ins | (cd < bd[j]);
                float td = bd[j]; int ti = bi[j];
                bd[j] = sm ? cd : td;
                bi[j] = sm ? ci : ti;
                cd = sm ? td : cd;
                ci = sm ? ti : ci;
                ins = sm;
            }
            worst = bd[NH - 1];
        }
    }
    const int base = (b * T + t) * NH;
#pragma unroll
    for (int i = 0; i < NH; i++) g_idx[base + i] = bi[i];
}

// ---------------------------------------------------------------------------
// K2: per-token local pipeline. 16 lanes per token (2 tokens per warp),
// neighbor exchange via width-16 shuffles.
// ---------------------------------------------------------------------------
constexpr int O_PEW1 = 0;      // 2*64
constexpr int O_PEB1 = 128;    // 64
constexpr int O_PEW2 = 192;    // 64*16
constexpr int O_PEB2 = 1216;   // 16
constexpr int O_LNG  = 1232;   // 16
constexpr int O_LNB  = 1248;   // 16
constexpr int O_QW   = 1264;   // 256
constexpr int O_KW   = 1520;   // 256
constexpr int O_VW   = 1776;   // 256
constexpr int O_OW   = 2032;   // 256
constexpr int O_MW1  = 2288;   // 16*64
constexpr int O_MB1  = 3312;   // 64
constexpr int O_MW2  = 3376;   // 64
constexpr int O_MB2  = 3440;   // 1
constexpr int O_SC   = 3441;   // 4
constexpr int SM_TOT = 3448;

__device__ __forceinline__ void mat16(const float* __restrict__ Wsh,
                                      const float* __restrict__ vin,
                                      float* __restrict__ vout) {
#pragma unroll
    for (int k = 0; k < 16; k++) {
        const float hv = vin[k];
#pragma unroll
        for (int dq = 0; dq < 4; dq++) {
            float4 w = *reinterpret_cast<const float4*>(Wsh + k * 16 + dq * 4);
            vout[dq * 4 + 0] = fmaf(hv, w.x, vout[dq * 4 + 0]);
            vout[dq * 4 + 1] = fmaf(hv, w.y, vout[dq * 4 + 1]);
            vout[dq * 4 + 2] = fmaf(hv, w.z, vout[dq * 4 + 2]);
            vout[dq * 4 + 3] = fmaf(hv, w.w, vout[dq * 4 + 3]);
        }
    }
}

__global__ __launch_bounds__(256) void token_kernel(
    const float* __restrict__ x, const float* __restrict__ ct, const float* __restrict__ cs,
    const float* __restrict__ pe_w1, const float* __restrict__ pe_b1,
    const float* __restrict__ pe_w2, const float* __restrict__ pe_b2,
    const float* __restrict__ ln_g, const float* __restrict__ ln_b,
    const float* __restrict__ q_w, const float* __restrict__ k_w,
    const float* __restrict__ v_w, const float* __restrict__ lscale,
    const float* __restrict__ out_w,
    const float* __restrict__ mnh_w1, const float* __restrict__ mnh_b1,
    const float* __restrict__ mnh_w2, const float* __restrict__ mnh_b2) {
    __shared__ float sm[SM_TOT];
    const int tid = threadIdx.x;
    for (int i = tid; i < 128;  i += 256) sm[O_PEW1 + i] = pe_w1[i];
    for (int i = tid; i < 64;   i += 256) sm[O_PEB1 + i] = pe_b1[i];
    for (int i = tid; i < 1024; i += 256) sm[O_PEW2 + i] = pe_w2[i];
    for (int i = tid; i < 16;   i += 256) sm[O_PEB2 + i] = pe_b2[i];
    for (int i = tid; i < 16;   i += 256) sm[O_LNG + i]  = ln_g[i];
    for (int i = tid; i < 16;   i += 256) sm[O_LNB + i]  = ln_b[i];
    for (int i = tid; i < 256;  i += 256) sm[O_QW + i]   = q_w[i];
    for (int i = tid; i < 256;  i += 256) sm[O_KW + i]   = k_w[i];
    for (int i = tid; i < 256;  i += 256) sm[O_VW + i]   = v_w[i];
    for (int i = tid; i < 256;  i += 256) sm[O_OW + i]   = out_w[i];
    for (int i = tid; i < 1024; i += 256) sm[O_MW1 + i]  = mnh_w1[i];
    for (int i = tid; i < 64;   i += 256) sm[O_MB1 + i]  = mnh_b1[i];
    for (int i = tid; i < 64;   i += 256) sm[O_MW2 + i]  = mnh_w2[i];
    if (tid == 0) sm[O_MB2] = mnh_b2[0];
    if (tid < 4)  sm[O_SC + tid] = expf(fminf(lscale[tid], 4.6051702f));
    __syncthreads();

    const int tok = blockIdx.x * 16 + (tid >> 4);
    const int i   = tid & 15;
    const int b   = tok / T;
    const int nidx = g_idx[tok * NH + i];

    float xr[16];
    const float4* xrow = reinterpret_cast<const float4*>(x + ((size_t)b * S + nidx) * E);
#pragma unroll
    for (int q4 = 0; q4 < 4; q4++) {
        float4 v4 = __ldg(xrow + q4);
        xr[q4 * 4 + 0] = v4.x; xr[q4 * 4 + 1] = v4.y;
        xr[q4 * 4 + 2] = v4.z; xr[q4 * 4 + 3] = v4.w;
    }
    const float2 scoord = __ldg(reinterpret_cast<const float2*>(cs) + (size_t)b * S + nidx);
    const float2 tcoord = __ldg(reinterpret_cast<const float2*>(ct) + tok);
    const float c0 = scoord.x - tcoord.x, c1 = scoord.y - tcoord.y;

    float h[16];
#pragma unroll
    for (int d = 0; d < 16; d++) h[d] = sm[O_PEB2 + d];
#pragma unroll
    for (int j = 0; j < FFNH; j++) {
        float z = fmaf(c0, sm[O_PEW1 + j], fmaf(c1, sm[O_PEW1 + 64 + j], sm[O_PEB1 + j]));
        z = gelu_exact(z);
#pragma unroll
        for (int dq = 0; dq < 4; dq++) {
            float4 w = *reinterpret_cast<const float4*>(sm + O_PEW2 + j * 16 + dq * 4);
            h[dq * 4 + 0] = fmaf(z, w.x, h[dq * 4 + 0]);
            h[dq * 4 + 1] = fmaf(z, w.y, h[dq * 4 + 1]);
            h[dq * 4 + 2] = fmaf(z, w.z, h[dq * 4 + 2]);
            h[dq * 4 + 3] = fmaf(z, w.w, h[dq * 4 + 3]);
        }
    }

    float mu = 0.f;
#pragma unroll
    for (int d = 0; d < 16; d++) { h[d] += xr[d]; mu += h[d]; }
    mu *= (1.f / 16.f);
    float var = 0.f;
#pragma unroll
    for (int d = 0; d < 16; d++) { float c = h[d] - mu; var = fmaf(c, c, var); }
    var *= (1.f / 16.f);
    const float rstd = 1.f / sqrtf(var + 1e-5f);
#pragma unroll
    for (int d = 0; d < 16; d++)
        h[d] = (h[d] - mu) * rstd * sm[O_LNG + d] + sm[O_LNB + d];

    float q[16], k[16], v[16];
#pragma unroll
    for (int d = 0; d < 16; d++) { q[d] = 0.f; k[d] = 0.f; v[d] = 0.f; }
    mat16(sm + O_QW, h, q);
    mat16(sm + O_KW, h, k);
    mat16(sm + O_VW, xr, v);

    float o[16];
#pragma unroll
    for (int hh = 0; hh < H; hh++) {
        float qh[4], kh[4], vh[4];
#pragma unroll
        for (int c = 0; c < 4; c++) {
            qh[c] = q[hh * 4 + c]; kh[c] = k[hh * 4 + c]; vh[c] = v[hh * 4 + c];
        }
        float qs = fmaf(qh[3], qh[3], fmaf(qh[2], qh[2], fmaf(qh[1], qh[1], qh[0] * qh[0])));
        float ks = fmaf(kh[3], kh[3], fmaf(kh[2], kh[2], fmaf(kh[1], kh[1], kh[0] * kh[0])));
        const float qi = 1.f / (sqrtf(qs) + 1e-6f);
        const float ki = 1.f / (sqrtf(ks) + 1e-6f);
#pragma unroll
        for (int c = 0; c < 4; c++) { qh[c] *= qi; kh[c] *= ki; }

        const float scl = sm[O_SC + hh];
        float lg[16];
#pragma unroll
        for (int j = 0; j < 16; j++) {
            float dot = 0.f;
#pragma unroll
            for (int c = 0; c < 4; c++) {
                float kj = __shfl_sync(0xffffffffu, kh[c], j, 16);
                dot = fmaf(qh[c], kj, dot);
            }
            lg[j] = dot * scl;
        }
        float mx = lg[0];
#pragma unroll
        for (int j = 1; j < 16; j++) mx = fmaxf(mx, lg[j]);
        float ssum = 0.f;
#pragma unroll
        for (int j = 0; j < 16; j++) { lg[j] = expf(lg[j] - mx); ssum += lg[j]; }
        const float inv = 1.f / ssum;
        float oh[4] = {0.f, 0.f, 0.f, 0.f};
#pragma unroll
        for (int j = 0; j < 16; j++) {
            const float a = lg[j] * inv;
#pragma unroll
            for (int c = 0; c < 4; c++) {
                float vj = __shfl_sync(0xffffffffu, vh[c], j, 16);
                oh[c] = fmaf(a, vj, oh[c]);
            }
        }
#pragma unroll
        for (int c = 0; c < 4; c++) o[hh * 4 + c] = oh[c];
    }

    float o2[16];
#pragma unroll
    for (int d = 0; d < 16; d++) o2[d] = 0.f;
    mat16(sm + O_OW, o, o2);

    float acc2 = 0.f;
#pragma unroll
    for (int j = 0; j < FFNH; j++) {
        float z = sm[O_MB1 + j];
#pragma unroll
        for (int kk = 0; kk < 16; kk++)
            z = fmaf(o2[kk], sm[O_MW1 + kk * 64 + j], z);
        acc2 = fmaf(gelu_exact(z), sm[O_MW2 + j], acc2);
    }
    const float m = gelu_exact(acc2 + sm[O_MB2]);

    float4* dst = reinterpret_cast<float4*>(g_oflat + (size_t)tok * MD + i * 16);
#pragma unroll
    for (int dq = 0; dq < 4; dq++)
        dst[dq] = make_float4(o2[dq * 4 + 0] + m, o2[dq * 4 + 1] + m,
                              o2[dq * 4 + 2] + m, o2[dq * 4 + 3] + m);
}

// ---------------------------------------------------------------------------
// K3 (fused): out = gelu(gelu(o_flat @ W1 + b1) @ W2 + b2).
// Per block: 64 rows. Loop 16 chunks of 64 FF-cols:
//   - tiled GEMM (64x64x256, BK=32) -> acc
//   - bias+gelu -> Cs smem
//   - contract Cs(64x64) x W2chunk(64x16) into per-thread out accumulators
// No h1 round-trip (saves 134 MB DRAM traffic + the whole mlp2 kernel).
// ---------------------------------------------------------------------------
__global__ __launch_bounds__(256, 2) void fused_mlp_kernel(
    const float* __restrict__ W1, const float* __restrict__ b1,
    const float* __restrict__ W2, const float* __restrict__ b2,
    float* __restrict__ out) {
    __shared__ float As[32][68];    // [k][row], padded
    __shared__ float Bs[32][64];    // [k][col]
    __shared__ float Cs[64][68];    // gelu(h1) chunk, padded
    __shared__ float W2s[64][16];   // W2 chunk

    const int tid = threadIdx.x;
    const int row0 = blockIdx.x * 64;
    const int tx = tid & 15, ty = tid >> 4;

    // A-load mapping: row = tid&63 (conflict-free transposed STS), kq = tid>>6
    const int ar  = tid & 63;
    const int akq = tid >> 6;          // 0..3 -> k offset akq*8
    // B-load mapping
    const int bkk = tid >> 3;          // 0..31
    const int bc  = (tid & 7) * 8;     // 0..56
    // phase-2 mapping: row = tid>>2, n-group = (tid&3)*4
    const int p2row = tid >> 2;
    const int p2n   = (tid & 3) * 4;

    float out_acc[4] = {0.f, 0.f, 0.f, 0.f};
    const float* arow = g_oflat + (size_t)(row0 + ar) * MD;

    for (int ch = 0; ch < 16; ch++) {
        const int col0 = ch * 64;
        float acc[4][4];
#pragma unroll
        for (int a = 0; a < 4; a++)
#pragma unroll
            for (int c = 0; c < 4; c++) acc[a][c] = 0.f;

#pragma unroll 1
        for (int kt = 0; kt < MD; kt += 32) {
            float4 a0 = *reinterpret_cast<const float4*>(arow + kt + akq * 8);
            float4 a1 = *reinterpret_cast<const float4*>(arow + kt + akq * 8 + 4);
            float4 bv0 = *reinterpret_cast<const float4*>(
                W1 + (size_t)(kt + bkk) * FF + col0 + bc);
            float4 bv1 = *reinterpret_cast<const float4*>(
                W1 + (size_t)(kt + bkk) * FF + col0 + bc + 4);
            __syncthreads();   // previous compute / phase-2 done before overwrite
            As[akq * 8 + 0][ar] = a0.x; As[akq * 8 + 1][ar] = a0.y;
            As[akq * 8 + 2][ar] = a0.z; As[akq * 8 + 3][ar] = a0.w;
            As[akq * 8 + 4][ar] = a1.x; As[akq * 8 + 5][ar] = a1.y;
            As[akq * 8 + 6][ar] = a1.z; As[akq * 8 + 7][ar] = a1.w;
            *reinterpret_cast<float4*>(&Bs[bkk][bc])     = bv0;
            *reinterpret_cast<float4*>(&Bs[bkk][bc + 4]) = bv1;
            __syncthreads();
#pragma unroll
            for (int kk = 0; kk < 32; kk++) {
                const float4 av = *reinterpret_cast<const float4*>(&As[kk][ty * 4]);
                const float4 bb = *reinterpret_cast<const float4*>(&Bs[kk][tx * 4]);
                acc[0][0] = fmaf(av.x, bb.x, acc[0][0]); acc[0][1] = fmaf(av.x, bb.y, acc[0][1]);
                acc[0][2] = fmaf(av.x, bb.z, acc[0][2]); acc[0][3] = fmaf(av.x, bb.w, acc[0][3]);
                acc[1][0] = fmaf(av.y, bb.x, acc[1][0]); acc[1][1] = fmaf(av.y, bb.y, acc[1][1]);
                acc[1][2] = fmaf(av.y, bb.z, acc[1][2]); acc[1][3] = fmaf(av.y, bb.w, acc[1][3]);
                acc[2][0] = fmaf(av.z, bb.x, acc[2][0]); acc[2][1] = fmaf(av.z, bb.y, acc[2][1]);
                acc[2][2] = fmaf(av.z, bb.z, acc[2][2]); acc[2][3] = fmaf(av.z, bb.w, acc[2][3]);
                acc[3][0] = fmaf(av.w, bb.x, acc[3][0]); acc[3][1] = fmaf(av.w, bb.y, acc[3][1]);
                acc[3][2] = fmaf(av.w, bb.z, acc[3][2]); acc[3][3] = fmaf(av.w, bb.w, acc[3][3]);
            }
        }

        // bias + gelu -> Cs; load W2 chunk
        const float4 bsv = *reinterpret_cast<const float4*>(b1 + col0 + tx * 4);
#pragma unroll
        for (int a = 0; a < 4; a++) {
            float4 cv;
            cv.x = gelu_exact(acc[a][0] + bsv.x);
            cv.y = gelu_exact(acc[a][1] + bsv.y);
            cv.z = gelu_exact(acc[a][2] + bsv.z);
            cv.w = gelu_exact(acc[a][3] + bsv.w);
            *reinterpret_cast<float4*>(&Cs[ty * 4 + a][tx * 4]) = cv;
        }
        reinterpret_cast<float4*>(&W2s[0][0])[tid] =
            *reinterpret_cast<const float4*>(W2 + (size_t)col0 * 16 + tid * 4);
        __syncthreads();

        // phase 2: out_acc += Cs(64x64) @ W2s(64x16), this thread: 1 row x 4 n
#pragma unroll 16
        for (int c = 0; c < 64; c++) {
            const float cv = Cs[p2row][c];
            const float4 w = *reinterpret_cast<const float4*>(&W2s[c][p2n]);
            out_acc[0] = fmaf(cv, w.x, out_acc[0]);
            out_acc[1] = fmaf(cv, w.y, out_acc[1]);
            out_acc[2] = fmaf(cv, w.z, out_acc[2]);
            out_acc[3] = fmaf(cv, w.w, out_acc[3]);
        }
        // next chunk's first __syncthreads() guards Cs/W2s reuse
    }

    const float4 b2v = *reinterpret_cast<const float4*>(b2 + p2n);
    float4 ov;
    ov.x = gelu_exact(out_acc[0] + b2v.x);
    ov.y = gelu_exact(out_acc[1] + b2v.y);
    ov.z = gelu_exact(out_acc[2] + b2v.z);
    ov.w = gelu_exact(out_acc[3] + b2v.w);
    *reinterpret_cast<float4*>(out + (size_t)(row0 + p2row) * OUT + p2n) = ov;
}

// ---------------------------------------------------------------------------
extern "C" void kernel_launch(void* const* d_in, const int* in_sizes, int n_in,
                              void* d_out, int out_size) {
    const float* x      = (const float*)d_in[0];
    const float* ct     = (const float*)d_in[1];
    const float* cs     = (const float*)d_in[2];
    const float* pe_w1  = (const float*)d_in[3];
    const float* pe_b1  = (const float*)d_in[4];
    const float* pe_w2  = (const float*)d_in[5];
    const float* pe_b2  = (const float*)d_in[6];
    const float* ln_g   = (const float*)d_in[7];
    const float* ln_b   = (const float*)d_in[8];
    const float* q_w    = (const float*)d_in[9];
    const float* k_w    = (const float*)d_in[10];
    const float* v_w    = (const float*)d_in[11];
    const float* ls     = (const float*)d_in[12];
    const float* out_w  = (const float*)d_in[13];
    const float* mnh_w1 = (const float*)d_in[14];
    const float* mnh_b1 = (const float*)d_in[15];
    const float* mnh_w2 = (const float*)d_in[16];
    const float* mnh_b2 = (const float*)d_in[17];
    const float* mo_w1  = (const float*)d_in[18];
    const float* mo_b1  = (const float*)d_in[19];
    const float* mo_w2  = (const float*)d_in[20];
    const float* mo_b2  = (const float*)d_in[21];

    knn_kernel<<<dim3(T / 64, B), 64>>>(ct, cs);
    token_kernel<<<NTOK / 16, 256>>>(x, ct, cs, pe_w1, pe_b1, pe_w2, pe_b2,
                                     ln_g, ln_b, q_w, k_w, v_w, ls, out_w,
                                     mnh_w1, mnh_b1, mnh_w2, mnh_b2);
    fused_mlp_kernel<<<NTOK / 64, 256>>>(mo_w1, mo_b1, mo_w2, mo_b2, (float*)d_out);
}

// round 5
// speedup vs baseline: 1.2334x; 1.2334x over previous
#include <cuda_runtime.h>
#include <math.h>
#include <stdint.h>

constexpr int B = 4, T = 4096, S = 4096, E = 16;
constexpr int NH = 16, H = 4, MDNH = 16, FFNH = 64;
constexpr int MD = 256, FF = 1024, OUT = 16;
constexpr int NTOK = B * T;

// Scratch (static device allocations — no cudaMalloc allowed)
__device__ int   g_idx[NTOK * NH];                 // 1 MB
__device__ float g_oflat[(size_t)NTOK * MD];       // 16.8 MB (L2-resident)

__device__ __forceinline__ float gelu_exact(float x) { return x * normcdff(x); }

__device__ __forceinline__ uint32_t f2tf32(float f) {
    uint32_t u;
    asm("cvt.rna.tf32.f32 %0, %1;" : "=r"(u) : "f"(f));
    return u;
}

// ---------------------------------------------------------------------------
// K1: 16-NN. 4 threads per target, each scans a contiguous S/4 chunk
// (contiguous => tie-stability preserved), then width-4 shuffle merge.
// ---------------------------------------------------------------------------
__global__ __launch_bounds__(256) void knn_kernel(const float* __restrict__ ct,
                                                  const float* __restrict__ cs) {
    __shared__ float2 scs[S];  // transposed: scs[i*4 + c] = source (c*1024 + i)
    const int b = blockIdx.y;
    const float* csb = cs + (size_t)b * S * 2;
    for (int s = threadIdx.x; s < S; s += 256)
        scs[((s & 1023) << 2) | (s >> 10)] = make_float2(csb[2 * s], csb[2 * s + 1]);
    __syncthreads();

    const int g = threadIdx.x >> 2;      // target within block (0..63)
    const int c = threadIdx.x & 3;       // chunk (0..3)
    const int t = blockIdx.x * 64 + g;
    const float tx = ct[((size_t)b * T + t) * 2 + 0];
    const float ty = ct[((size_t)b * T + t) * 2 + 1];

    float bd[NH];
    int   bi[NH];
#pragma unroll
    for (int i = 0; i < NH; i++) { bd[i] = 3.4e38f; bi[i] = 0; }
    float worst = 3.4e38f;
    const int s0 = c << 10;

#pragma unroll 4
    for (int i = 0; i < 1024; i++) {
        float2 cc = scs[(i << 2) | c];
        float dx = tx - cc.x, dy = ty - cc.y;
        float d2 = fmaf(dy, dy, dx * dx);
        if (d2 < worst) {
            float cd = d2; int ci = s0 + i;
            bool ins = false;
#pragma unroll
            for (int j = 0; j < NH; j++) {
                bool sm = ins | (cd < bd[j]);
                float td = bd[j]; int ti = bi[j];
                bd[j] = sm ? cd : td;
                bi[j] = sm ? ci : ti;
                cd = sm ? td : cd;
                ci = sm ? ti : ci;
                ins = sm;
            }
            worst = bd[NH - 1];
        }
    }

    // merge the 4 chunk lists (chunk order = ascending index => stable ties)
    float md[NH];
    int   mi[NH];
#pragma unroll
    for (int i = 0; i < NH; i++) { md[i] = 3.4e38f; mi[i] = 0; }
    float worst2 = 3.4e38f;
#pragma unroll
    for (int p = 0; p < 4; p++) {
#pragma unroll
        for (int j = 0; j < NH; j++) {
            float cd = __shfl_sync(0xffffffffu, bd[j], p, 4);
            int   ci = __shfl_sync(0xffffffffu, bi[j], p, 4);
            if (cd < worst2) {
                bool ins = false;
#pragma unroll
                for (int q = 0; q < NH; q++) {
                    bool sm = ins | (cd < md[q]);
                    float td = md[q]; int ti = mi[q];
                    md[q] = sm ? cd : td;
                    mi[q] = sm ? ci : ti;
                    cd = sm ? td : cd;
                    ci = sm ? ti : ci;
                    ins = sm;
                }
                worst2 = md[NH - 1];
            }
        }
    }

    if (c == 0) {
        const int base = (b * T + t) * NH;
#pragma unroll
        for (int i = 0; i < NH; i++) g_idx[base + i] = mi[i];
    }
}

// ---------------------------------------------------------------------------
// K2: per-token local pipeline. 16 lanes/token, width-16 shuffles. (unchanged)
// ---------------------------------------------------------------------------
constexpr int O_PEW1 = 0;
constexpr int O_PEB1 = 128;
constexpr int O_PEW2 = 192;
constexpr int O_PEB2 = 1216;
constexpr int O_LNG  = 1232;
constexpr int O_LNB  = 1248;
constexpr int O_QW   = 1264;
constexpr int O_KW   = 1520;
constexpr int O_VW   = 1776;
constexpr int O_OW   = 2032;
constexpr int O_MW1  = 2288;
constexpr int O_MB1  = 3312;
constexpr int O_MW2  = 3376;
constexpr int O_MB2  = 3440;
constexpr int O_SC   = 3441;
constexpr int SM_TOT = 3448;

__device__ __forceinline__ void mat16(const float* __restrict__ Wsh,
                                      const float* __restrict__ vin,
                                      float* __restrict__ vout) {
#pragma unroll
    for (int k = 0; k < 16; k++) {
        const float hv = vin[k];
#pragma unroll
        for (int dq = 0; dq < 4; dq++) {
            float4 w = *reinterpret_cast<const float4*>(Wsh + k * 16 + dq * 4);
            vout[dq * 4 + 0] = fmaf(hv, w.x, vout[dq * 4 + 0]);
            vout[dq * 4 + 1] = fmaf(hv, w.y, vout[dq * 4 + 1]);
            vout[dq * 4 + 2] = fmaf(hv, w.z, vout[dq * 4 + 2]);
            vout[dq * 4 + 3] = fmaf(hv, w.w, vout[dq * 4 + 3]);
        }
    }
}

__global__ __launch_bounds__(256) void token_kernel(
    const float* __restrict__ x, const float* __restrict__ ct, const float* __restrict__ cs,
    const float* __restrict__ pe_w1, const float* __restrict__ pe_b1,
    const float* __restrict__ pe_w2, const float* __restrict__ pe_b2,
    const float* __restrict__ ln_g, const float* __restrict__ ln_b,
    const float* __restrict__ q_w, const float* __restrict__ k_w,
    const float* __restrict__ v_w, const float* __restrict__ lscale,
    const float* __restrict__ out_w,
    const float* __restrict__ mnh_w1, const float* __restrict__ mnh_b1,
    const float* __restrict__ mnh_w2, const float* __restrict__ mnh_b2) {
    __shared__ float sm[SM_TOT];
    const int tid = threadIdx.x;
    for (int i = tid; i < 128;  i += 256) sm[O_PEW1 + i] = pe_w1[i];
    for (int i = tid; i < 64;   i += 256) sm[O_PEB1 + i] = pe_b1[i];
    for (int i = tid; i < 1024; i += 256) sm[O_PEW2 + i] = pe_w2[i];
    for (int i = tid; i < 16;   i += 256) sm[O_PEB2 + i] = pe_b2[i];
    for (int i = tid; i < 16;   i += 256) sm[O_LNG + i]  = ln_g[i];
    for (int i = tid; i < 16;   i += 256) sm[O_LNB + i]  = ln_b[i];
    for (int i = tid; i < 256;  i += 256) sm[O_QW + i]   = q_w[i];
    for (int i = tid; i < 256;  i += 256) sm[O_KW + i]   = k_w[i];
    for (int i = tid; i < 256;  i += 256) sm[O_VW + i]   = v_w[i];
    for (int i = tid; i < 256;  i += 256) sm[O_OW + i]   = out_w[i];
    for (int i = tid; i < 1024; i += 256) sm[O_MW1 + i]  = mnh_w1[i];
    for (int i = tid; i < 64;   i += 256) sm[O_MB1 + i]  = mnh_b1[i];
    for (int i = tid; i < 64;   i += 256) sm[O_MW2 + i]  = mnh_w2[i];
    if (tid == 0) sm[O_MB2] = mnh_b2[0];
    if (tid < 4)  sm[O_SC + tid] = expf(fminf(lscale[tid], 4.6051702f));
    __syncthreads();

    const int tok = blockIdx.x * 16 + (tid >> 4);
    const int i   = tid & 15;
    const int b   = tok / T;
    const int nidx = g_idx[tok * NH + i];

    float xr[16];
    const float4* xrow = reinterpret_cast<const float4*>(x + ((size_t)b * S + nidx) * E);
#pragma unroll
    for (int q4 = 0; q4 < 4; q4++) {
        float4 v4 = __ldg(xrow + q4);
        xr[q4 * 4 + 0] = v4.x; xr[q4 * 4 + 1] = v4.y;
        xr[q4 * 4 + 2] = v4.z; xr[q4 * 4 + 3] = v4.w;
    }
    const float2 scoord = __ldg(reinterpret_cast<const float2*>(cs) + (size_t)b * S + nidx);
    const float2 tcoord = __ldg(reinterpret_cast<const float2*>(ct) + tok);
    const float c0 = scoord.x - tcoord.x, c1 = scoord.y - tcoord.y;

    float h[16];
#pragma unroll
    for (int d = 0; d < 16; d++) h[d] = sm[O_PEB2 + d];
#pragma unroll
    for (int j = 0; j < FFNH; j++) {
        float z = fmaf(c0, sm[O_PEW1 + j], fmaf(c1, sm[O_PEW1 + 64 + j], sm[O_PEB1 + j]));
        z = gelu_exact(z);
#pragma unroll
        for (int dq = 0; dq < 4; dq++) {
            float4 w = *reinterpret_cast<const float4*>(sm + O_PEW2 + j * 16 + dq * 4);
            h[dq * 4 + 0] = fmaf(z, w.x, h[dq * 4 + 0]);
            h[dq * 4 + 1] = fmaf(z, w.y, h[dq * 4 + 1]);
            h[dq * 4 + 2] = fmaf(z, w.z, h[dq * 4 + 2]);
            h[dq * 4 + 3] = fmaf(z, w.w, h[dq * 4 + 3]);
        }
    }

    float mu = 0.f;
#pragma unroll
    for (int d = 0; d < 16; d++) { h[d] += xr[d]; mu += h[d]; }
    mu *= (1.f / 16.f);
    float var = 0.f;
#pragma unroll
    for (int d = 0; d < 16; d++) { float c = h[d] - mu; var = fmaf(c, c, var); }
    var *= (1.f / 16.f);
    const float rstd = 1.f / sqrtf(var + 1e-5f);
#pragma unroll
    for (int d = 0; d < 16; d++)
        h[d] = (h[d] - mu) * rstd * sm[O_LNG + d] + sm[O_LNB + d];

    float q[16], k[16], v[16];
#pragma unroll
    for (int d = 0; d < 16; d++) { q[d] = 0.f; k[d] = 0.f; v[d] = 0.f; }
    mat16(sm + O_QW, h, q);
    mat16(sm + O_KW, h, k);
    mat16(sm + O_VW, xr, v);

    float o[16];
#pragma unroll
    for (int hh = 0; hh < H; hh++) {
        float qh[4], kh[4], vh[4];
#pragma unroll
        for (int c = 0; c < 4; c++) {
            qh[c] = q[hh * 4 + c]; kh[c] = k[hh * 4 + c]; vh[c] = v[hh * 4 + c];
        }
        float qs = fmaf(qh[3], qh[3], fmaf(qh[2], qh[2], fmaf(qh[1], qh[1], qh[0] * qh[0])));
        float ks = fmaf(kh[3], kh[3], fmaf(kh[2], kh[2], fmaf(kh[1], kh[1], kh[0] * kh[0])));
        const float qi = 1.f / (sqrtf(qs) + 1e-6f);
        const float ki = 1.f / (sqrtf(ks) + 1e-6f);
#pragma unroll
        for (int c = 0; c < 4; c++) { qh[c] *= qi; kh[c] *= ki; }

        const float scl = sm[O_SC + hh];
        float lg[16];
#pragma unroll
        for (int j = 0; j < 16; j++) {
            float dot = 0.f;
#pragma unroll
            for (int c = 0; c < 4; c++) {
                float kj = __shfl_sync(0xffffffffu, kh[c], j, 16);
                dot = fmaf(qh[c], kj, dot);
            }
            lg[j] = dot * scl;
        }
        float mx = lg[0];
#pragma unroll
        for (int j = 1; j < 16; j++) mx = fmaxf(mx, lg[j]);
        float ssum = 0.f;
#pragma unroll
        for (int j = 0; j < 16; j++) { lg[j] = expf(lg[j] - mx); ssum += lg[j]; }
        const float inv = 1.f / ssum;
        float oh[4] = {0.f, 0.f, 0.f, 0.f};
#pragma unroll
        for (int j = 0; j < 16; j++) {
            const float a = lg[j] * inv;
#pragma unroll
            for (int c = 0; c < 4; c++) {
                float vj = __shfl_sync(0xffffffffu, vh[c], j, 16);
                oh[c] = fmaf(a, vj, oh[c]);
            }
        }
#pragma unroll
        for (int c = 0; c < 4; c++) o[hh * 4 + c] = oh[c];
    }

    float o2[16];
#pragma unroll
    for (int d = 0; d < 16; d++) o2[d] = 0.f;
    mat16(sm + O_OW, o, o2);

    float acc2 = 0.f;
#pragma unroll
    for (int j = 0; j < FFNH; j++) {
        float z = sm[O_MB1 + j];
#pragma unroll
        for (int kk = 0; kk < 16; kk++)
            z = fmaf(o2[kk], sm[O_MW1 + kk * 64 + j], z);
        acc2 = fmaf(gelu_exact(z), sm[O_MW2 + j], acc2);
    }
    const float m = gelu_exact(acc2 + sm[O_MB2]);

    float4* dst = reinterpret_cast<float4*>(g_oflat + (size_t)tok * MD + i * 16);
#pragma unroll
    for (int dq = 0; dq < 4; dq++)
        dst[dq] = make_float4(o2[dq * 4 + 0] + m, o2[dq * 4 + 1] + m,
                              o2[dq * 4 + 2] + m, o2[dq * 4 + 3] + m);
}

// ---------------------------------------------------------------------------
// K3 (fused, tf32 tensor cores):
//   out = gelu(gelu(o_flat[16384,256] @ W1[256,1024] + b1) @ W2[1024,16] + b2)
// Block: 128 rows. Loop 16 chunks of 64 FF-cols:
//   phase1: tf32 mma.sync m16n8k8, warp tile 32x32 (2m x 4n atoms), K=256
//   epilogue: bias+gelu -> Cs (aliased over A/B tiles)
//   phase2: out_acc += Cs(128x64) @ W2chunk(64x16), fp32 SIMT
// ---------------------------------------------------------------------------
__device__ __forceinline__ void mma_tf32(float* c, const uint32_t* a, const uint32_t* bb) {
    asm volatile(
        "mma.sync.aligned.m16n8k8.row.col.f32.tf32.tf32.f32 "
        "{%0,%1,%2,%3}, {%4,%5,%6,%7}, {%8,%9}, {%0,%1,%2,%3};"
        : "+f"(c[0]), "+f"(c[1]), "+f"(c[2]), "+f"(c[3])
        : "r"(a[0]), "r"(a[1]), "r"(a[2]), "r"(a[3]), "r"(bb[0]), "r"(bb[1]));
}

constexpr int APAD = 36;   // As row stride
constexpr int BPAD = 72;   // Bs row stride
constexpr int CPAD = 66;   // Cs row stride

__global__ __launch_bounds__(256) void fused_mlp_kernel(
    const float* __restrict__ W1, const float* __restrict__ b1,
    const float* __restrict__ W2, const float* __restrict__ b2,
    float* __restrict__ out) {
    __shared__ __align__(16) uint32_t smem_u[9472];            // 37888 B union
    uint32_t* As = smem_u;                                     // [128][36] tf32
    uint32_t* Bs = smem_u + 128 * APAD;                        // [32][72] tf32
    float* Cs  = reinterpret_cast<float*>(smem_u);             // [128][66] f32
    float* W2s = reinterpret_cast<float*>(smem_u) + 128 * CPAD;// [64][16] f32

    const int tid  = threadIdx.x;
    const int lane = tid & 31;
    const int wid  = tid >> 5;
    const int warp_m = wid & 3;          // 0..3 -> 32 rows each
    const int warp_n = wid >> 2;         // 0..1 -> 32 cols each
    const int row0 = blockIdx.x * 128;

    // global-load mappings
    const int a_row  = tid >> 1;                 // 0..127 (16 floats/thread)
    const int a_kofs = (tid & 1) * 16;
    const int b_krow = tid >> 3;                 // 0..31 (8 floats/thread)
    const int b_ncol = (tid & 7) * 8;            // 0..56
    // phase-2 mapping
    const int p2row = tid >> 1;                  // 0..127
    const int p2n   = (tid & 1) * 8;

    const float* arow_g = g_oflat + (size_t)(row0 + a_row) * MD + a_kofs;

    float out_acc[8];
#pragma unroll
    for (int i = 0; i < 8; i++) out_acc[i] = 0.f;

    for (int ch = 0; ch < 16; ch++) {
        const int col0 = ch * 64;
        float cfr[2][4][4];
#pragma unroll
        for (int ma = 0; ma < 2; ma++)
#pragma unroll
            for (int na = 0; na < 4; na++)
#pragma unroll
                for (int i = 0; i < 4; i++) cfr[ma][na][i] = 0.f;

#pragma unroll 1
        for (int kt = 0; kt < 8; kt++) {
            // prefetch global: A 16 floats/thread, B 8 floats/thread
            float4 av[4], bv[2];
#pragma unroll
            for (int q = 0; q < 4; q++)
                av[q] = *reinterpret_cast<const float4*>(arow_g + kt * 32 + q * 4);
#pragma unroll
            for (int q = 0; q < 2; q++)
                bv[q] = *reinterpret_cast<const float4*>(
                    W1 + (size_t)(kt * 32 + b_krow) * FF + col0 + b_ncol + q * 4);
            __syncthreads();  // prior smem reads (frags / phase2) complete
#pragma unroll
            for (int q = 0; q < 4; q++) {
                uint4 at = make_uint4(f2tf32(av[q].x), f2tf32(av[q].y),
                                      f2tf32(av[q].z), f2tf32(av[q].w));
                *reinterpret_cast<uint4*>(&As[a_row * APAD + a_kofs + q * 4]) = at;
            }
#pragma unroll
            for (int q = 0; q < 2; q++) {
                uint4 bt = make_uint4(f2tf32(bv[q].x), f2tf32(bv[q].y),
                                      f2tf32(bv[q].z), f2tf32(bv[q].w));
                *reinterpret_cast<uint4*>(&Bs[b_krow * BPAD + b_ncol + q * 4]) = bt;
            }
            __syncthreads();

#pragma unroll
            for (int ks = 0; ks < 4; ks++) {
                const int k0 = ks * 8;
                uint32_t afr[2][4];
#pragma unroll
                for (int ma = 0; ma < 2; ma++) {
                    const int r = warp_m * 32 + ma * 16 + (lane >> 2);
                    const int kc = k0 + (lane & 3);
                    afr[ma][0] = As[r * APAD + kc];
                    afr[ma][1] = As[(r + 8) * APAD + kc];
                    afr[ma][2] = As[r * APAD + kc + 4];
                    afr[ma][3] = As[(r + 8) * APAD + kc + 4];
                }
                uint32_t bfr[4][2];
#pragma unroll
                for (int na = 0; na < 4; na++) {
                    const int n = warp_n * 32 + na * 8 + (lane >> 2);
                    const int kc = k0 + (lane & 3);
                    bfr[na][0] = Bs[kc * BPAD + n];
                    bfr[na][1] = Bs[(kc + 4) * BPAD + n];
                }
#pragma unroll
                for (int ma = 0; ma < 2; ma++)
#pragma unroll
                    for (int na = 0; na < 4; na++)
                        mma_tf32(cfr[ma][na], afr[ma], bfr[na]);
            }
        }

        __syncthreads();   // all frag reads done before Cs aliases As/Bs

        // epilogue: bias + gelu -> Cs; stage W2 chunk
#pragma unroll
        for (int ma = 0; ma < 2; ma++) {
            const int r0 = warp_m * 32 + ma * 16 + (lane >> 2);
#pragma unroll
            for (int na = 0; na < 4; na++) {
                const int cl = warp_n * 32 + na * 8 + 2 * (lane & 3);
                const float bb0 = __ldg(b1 + col0 + cl);
                const float bb1 = __ldg(b1 + col0 + cl + 1);
                float2 v0, v1;
                v0.x = gelu_exact(cfr[ma][na][0] + bb0);
                v0.y = gelu_exact(cfr[ma][na][1] + bb1);
                v1.x = gelu_exact(cfr[ma][na][2] + bb0);
                v1.y = gelu_exact(cfr[ma][na][3] + bb1);
                *reinterpret_cast<float2*>(&Cs[r0 * CPAD + cl]) = v0;
                *reinterpret_cast<float2*>(&Cs[(r0 + 8) * CPAD + cl]) = v1;
            }
        }
        *reinterpret_cast<float4*>(&W2s[(tid >> 2) * 16 + (tid & 3) * 4]) =
            *reinterpret_cast<const float4*>(W2 + (size_t)(col0 + (tid >> 2)) * 16 + (tid & 3) * 4);
        __syncthreads();

        // phase 2: out_acc += Cs(128x64) @ W2s(64x16); thread: 1 row x 8 cols
#pragma unroll 8
        for (int c = 0; c < 64; c++) {
            const float cv = Cs[p2row * CPAD + c];
            const float4 wa = *reinterpret_cast<const float4*>(&W2s[c * 16 + p2n]);
            const float4 wb = *reinterpret_cast<const float4*>(&W2s[c * 16 + p2n + 4]);
            out_acc[0] = fmaf(cv, wa.x, out_acc[0]);
            out_acc[1] = fmaf(cv, wa.y, out_acc[1]);
            out_acc[2] = fmaf(cv, wa.z, out_acc[2]);
            out_acc[3] = fmaf(cv, wa.w, out_acc[3]);
            out_acc[4] = fmaf(cv, wb.x, out_acc[4]);
            out_acc[5] = fmaf(cv, wb.y, out_acc[5]);
            out_acc[6] = fmaf(cv, wb.z, out_acc[6]);
            out_acc[7] = fmaf(cv, wb.w, out_acc[7]);
        }
        // next chunk's first __syncthreads() guards Cs/W2s reuse
    }

    const float4 b2a = *reinterpret_cast<const float4*>(b2 + p2n);
    const float4 b2b = *reinterpret_cast<const float4*>(b2 + p2n + 4);
    float4 oa, ob;
    oa.x = gelu_exact(out_acc[0] + b2a.x);
    oa.y = gelu_exact(out_acc[1] + b2a.y);
    oa.z = gelu_exact(out_acc[2] + b2a.z);
    oa.w = gelu_exact(out_acc[3] + b2a.w);
    ob.x = gelu_exact(out_acc[4] + b2b.x);
    ob.y = gelu_exact(out_acc[5] + b2b.y);
    ob.z = gelu_exact(out_acc[6] + b2b.z);
    ob.w = gelu_exact(out_acc[7] + b2b.w);
    float* orow = out + (size_t)(row0 + p2row) * OUT + p2n;
    *reinterpret_cast<float4*>(orow)     = oa;
    *reinterpret_cast<float4*>(orow + 4) = ob;
}

// ---------------------------------------------------------------------------
extern "C" void kernel_launch(void* const* d_in, const int* in_sizes, int n_in,
                              void* d_out, int out_size) {
    const float* x      = (const float*)d_in[0];
    const float* ct     = (const float*)d_in[1];
    const float* cs     = (const float*)d_in[2];
    const float* pe_w1  = (const float*)d_in[3];
    const float* pe_b1  = (const float*)d_in[4];
    const float* pe_w2  = (const float*)d_in[5];
    const float* pe_b2  = (const float*)d_in[6];
    const float* ln_g   = (const float*)d_in[7];
    const float* ln_b   = (const float*)d_in[8];
    const float* q_w    = (const float*)d_in[9];
    const float* k_w    = (const float*)d_in[10];
    const float* v_w    = (const float*)d_in[11];
    const float* ls     = (const float*)d_in[12];
    const float* out_w  = (const float*)d_in[13];
    const float* mnh_w1 = (const float*)d_in[14];
    const float* mnh_b1 = (const float*)d_in[15];
    const float* mnh_w2 = (const float*)d_in[16];
    const float* mnh_b2 = (const float*)d_in[17];
    const float* mo_w1  = (const float*)d_in[18];
    const float* mo_b1  = (const float*)d_in[19];
    const float* mo_w2  = (const float*)d_in[20];
    const float* mo_b2  = (const float*)d_in[21];

    knn_kernel<<<dim3(T / 64, B), 256>>>(ct, cs);
    token_kernel<<<NTOK / 16, 256>>>(x, ct, cs, pe_w1, pe_b1, pe_w2, pe_b2,
                                     ln_g, ln_b, q_w, k_w, v_w, ls, out_w,
                                     mnh_w1, mnh_b1, mnh_w2, mnh_b2);
    fused_mlp_kernel<<<NTOK / 128, 256>>>(mo_w1, mo_b1, mo_w2, mo_b2, (float*)d_out);
}

// round 6
// speedup vs baseline: 1.7137x; 1.3894x over previous
#include <cuda_runtime.h>
#include <math.h>
#include <stdint.h>

constexpr int B = 4, T = 4096, S = 4096, E = 16;
constexpr int NH = 16, H = 4, MDNH = 16, FFNH = 64;
constexpr int MD = 256, FF = 1024, OUT = 16;
constexpr int NTOK = B * T;
constexpr int GC = 16;                 // grid cells per axis

// Scratch (static device allocations — no cudaMalloc allowed)
__device__ int    g_idx[NTOK * NH];                // 1 MB
__device__ float  g_oflat[(size_t)NTOK * MD];      // 16.8 MB (L2-resident)
__device__ float2 g_gxy[B][S];                     // grid-sorted source coords
__device__ int    g_gid[B][S];                     // grid-sorted source indices
__device__ int    g_cstart[B][GC * GC + 1];        // cell start offsets

__device__ __forceinline__ float gelu_exact(float x) { return x * normcdff(x); }

__device__ __forceinline__ uint32_t f2tf32(float f) {
    uint32_t u;
    asm("cvt.rna.tf32.f32 %0, %1;" : "=r"(u) : "f"(f));
    return u;
}

// ---------------------------------------------------------------------------
// K0: bin sources into a 16x16 uniform grid (counting sort). One block/batch.
// Within-cell order is nondeterministic (atomics) but the kNN selection is
// order-independent (lexicographic (d2, idx) keys) so output is deterministic.
// ---------------------------------------------------------------------------
__global__ __launch_bounds__(256) void grid_build(const float* __restrict__ cs) {
    __shared__ int cnt[GC * GC];
    __shared__ int start[GC * GC + 1];
    const int b = blockIdx.x, tid = threadIdx.x;
    cnt[tid] = 0;
    __syncthreads();
    const float2* csb = reinterpret_cast<const float2*>(cs) + (size_t)b * S;
    for (int i = tid; i < S; i += 256) {
        float2 c = csb[i];
        int cx = min(GC - 1, (int)(c.x * GC));
        int cy = min(GC - 1, (int)(c.y * GC));
        atomicAdd(&cnt[cy * GC + cx], 1);
    }
    __syncthreads();
    if (tid == 0) {
        int acc = 0;
        for (int i = 0; i < GC * GC; i++) { start[i] = acc; acc += cnt[i]; }
        start[GC * GC] = acc;
    }
    __syncthreads();
    cnt[tid] = start[tid];                   // cursors
    g_cstart[b][tid] = start[tid];
    if (tid == 0) g_cstart[b][GC * GC] = start[GC * GC];
    __syncthreads();
    for (int i = tid; i < S; i += 256) {
        float2 c = csb[i];
        int cx = min(GC - 1, (int)(c.x * GC));
        int cy = min(GC - 1, (int)(c.y * GC));
        int pos = atomicAdd(&cnt[cy * GC + cx], 1);
        g_gxy[b][pos] = c;
        g_gid[b][pos] = i;
    }
}

// ---------------------------------------------------------------------------
// K1: exact 16-NN via expanding grid rings. One thread per target.
// Key = (d2_bits << 32) | idx : float bits monotonic for d2 >= 0, so u64
// ascending order == (d2 asc, idx asc) == jax.lax.top_k stable order.
// Stop: after ring rho, unseen points are >= rho*h away -> stop when
// worst_d2 < (rho*h)^2 (strict: equal-distance smaller-idx points matter).
// ---------------------------------------------------------------------------
__global__ __launch_bounds__(128) void knn_kernel(const float* __restrict__ ct) {
    const int b = blockIdx.y;
    const int t = blockIdx.x * 128 + threadIdx.x;
    const float tx = ct[((size_t)b * T + t) * 2 + 0];
    const float ty = ct[((size_t)b * T + t) * 2 + 1];
    const int cx = min(GC - 1, (int)(tx * GC));
    const int cy = min(GC - 1, (int)(ty * GC));

    const float2* __restrict__ gxy = g_gxy[b];
    const int*    __restrict__ gid = g_gid[b];
    const int*    __restrict__ cst = g_cstart[b];
    constexpr float hcell = 1.0f / GC;
    constexpr unsigned long long KMAX = 0xFFFFFFFFFFFFFFFFull;

    unsigned long long key[NH];
#pragma unroll
    for (int i = 0; i < NH; i++) key[i] = KMAX;

    for (int rho = 0; rho <= GC - 1; rho++) {
        if (rho > 1 && key[NH - 1] != KMAX) {
            const float wd2 = __uint_as_float((unsigned)(key[NH - 1] >> 32));
            const float bound = (rho - 1) * hcell;
            if (wd2 < bound * bound) break;
        }
        const int ylo = max(cy - rho, 0), yhi = min(cy + rho, GC - 1);
        for (int ay = ylo; ay <= yhi; ay++) {
            const bool fullrow = (ay == cy - rho) || (ay == cy + rho);
            const int step = fullrow ? 1 : (rho > 0 ? 2 * rho : 1);
            for (int ax = cx - rho; ax <= cx + rho; ax += step) {
                if (ax < 0 || ax >= GC) continue;
                const int cell = ay * GC + ax;
                const int c1 = cst[cell + 1];
                for (int j = cst[cell]; j < c1; j++) {
                    const float2 p = gxy[j];
                    const float dxx = tx - p.x, dyy = ty - p.y;
                    const float d2 = fmaf(dyy, dyy, dxx * dxx);
                    unsigned long long ck =
                        ((unsigned long long)__float_as_uint(d2) << 32) |
                        (unsigned)gid[j];
                    if (ck < key[NH - 1]) {
                        bool ins = false;
#pragma unroll
                        for (int q = 0; q < NH; q++) {
                            bool sm = ins | (ck < key[q]);
                            unsigned long long tk = key[q];
                            key[q] = sm ? ck : tk;
                            ck = sm ? tk : ck;
                            ins = sm;
                        }
                    }
                }
            }
        }
    }

    const int base = (b * T + t) * NH;
#pragma unroll
    for (int i = 0; i < NH; i++)
        g_idx[base + i] = (int)(key[i] & 0xFFFFFFFFull);
}

// ---------------------------------------------------------------------------
// K2: per-token local pipeline. 16 lanes/token, width-16 shuffles. (unchanged)
// ---------------------------------------------------------------------------
constexpr int O_PEW1 = 0;
constexpr int O_PEB1 = 128;
constexpr int O_PEW2 = 192;
constexpr int O_PEB2 = 1216;
constexpr int O_LNG  = 1232;
constexpr int O_LNB  = 1248;
constexpr int O_QW   = 1264;
constexpr int O_KW   = 1520;
constexpr int O_VW   = 1776;
constexpr int O_OW   = 2032;
constexpr int O_MW1  = 2288;
constexpr int O_MB1  = 3312;
constexpr int O_MW2  = 3376;
constexpr int O_MB2  = 3440;
constexpr int O_SC   = 3441;
constexpr int SM_TOT = 3448;

__device__ __forceinline__ void mat16(const float* __restrict__ Wsh,
                                      const float* __restrict__ vin,
                                      float* __restrict__ vout) {
#pragma unroll
    for (int k = 0; k < 16; k++) {
        const float hv = vin[k];
#pragma unroll
        for (int dq = 0; dq < 4; dq++) {
            float4 w = *reinterpret_cast<const float4*>(Wsh + k * 16 + dq * 4);
            vout[dq * 4 + 0] = fmaf(hv, w.x, vout[dq * 4 + 0]);
            vout[dq * 4 + 1] = fmaf(hv, w.y, vout[dq * 4 + 1]);
            vout[dq * 4 + 2] = fmaf(hv, w.z, vout[dq * 4 + 2]);
            vout[dq * 4 + 3] = fmaf(hv, w.w, vout[dq * 4 + 3]);
        }
    }
}

__global__ __launch_bounds__(256) void token_kernel(
    const float* __restrict__ x, const float* __restrict__ ct, const float* __restrict__ cs,
    const float* __restrict__ pe_w1, const float* __restrict__ pe_b1,
    const float* __restrict__ pe_w2, const float* __restrict__ pe_b2,
    const float* __restrict__ ln_g, const float* __restrict__ ln_b,
    const float* __restrict__ q_w, const float* __restrict__ k_w,
    const float* __restrict__ v_w, const float* __restrict__ lscale,
    const float* __restrict__ out_w,
    const float* __restrict__ mnh_w1, const float* __restrict__ mnh_b1,
    const float* __restrict__ mnh_w2, const float* __restrict__ mnh_b2) {
    __shared__ float sm[SM_TOT];
    const int tid = threadIdx.x;
    for (int i = tid; i < 128;  i += 256) sm[O_PEW1 + i] = pe_w1[i];
    for (int i = tid; i < 64;   i += 256) sm[O_PEB1 + i] = pe_b1[i];
    for (int i = tid; i < 1024; i += 256) sm[O_PEW2 + i] = pe_w2[i];
    for (int i = tid; i < 16;   i += 256) sm[O_PEB2 + i] = pe_b2[i];
    for (int i = tid; i < 16;   i += 256) sm[O_LNG + i]  = ln_g[i];
    for (int i = tid; i < 16;   i += 256) sm[O_LNB + i]  = ln_b[i];
    for (int i = tid; i < 256;  i += 256) sm[O_QW + i]   = q_w[i];
    for (int i = tid; i < 256;  i += 256) sm[O_KW + i]   = k_w[i];
    for (int i = tid; i < 256;  i += 256) sm[O_VW + i]   = v_w[i];
    for (int i = tid; i < 256;  i += 256) sm[O_OW + i]   = out_w[i];
    for (int i = tid; i < 1024; i += 256) sm[O_MW1 + i]  = mnh_w1[i];
    for (int i = tid; i < 64;   i += 256) sm[O_MB1 + i]  = mnh_b1[i];
    for (int i = tid; i < 64;   i += 256) sm[O_MW2 + i]  = mnh_w2[i];
    if (tid == 0) sm[O_MB2] = mnh_b2[0];
    if (tid < 4)  sm[O_SC + tid] = expf(fminf(lscale[tid], 4.6051702f));
    __syncthreads();

    const int tok = blockIdx.x * 16 + (tid >> 4);
    const int i   = tid & 15;
    const int b   = tok / T;
    const int nidx = g_idx[tok * NH + i];

    float xr[16];
    const float4* xrow = reinterpret_cast<const float4*>(x + ((size_t)b * S + nidx) * E);
#pragma unroll
    for (int q4 = 0; q4 < 4; q4++) {
        float4 v4 = __ldg(xrow + q4);
        xr[q4 * 4 + 0] = v4.x; xr[q4 * 4 + 1] = v4.y;
        xr[q4 * 4 + 2] = v4.z; xr[q4 * 4 + 3] = v4.w;
    }
    const float2 scoord = __ldg(reinterpret_cast<const float2*>(cs) + (size_t)b * S + nidx);
    const float2 tcoord = __ldg(reinterpret_cast<const float2*>(ct) + tok);
    const float c0 = scoord.x - tcoord.x, c1 = scoord.y - tcoord.y;

    float h[16];
#pragma unroll
    for (int d = 0; d < 16; d++) h[d] = sm[O_PEB2 + d];
#pragma unroll
    for (int j = 0; j < FFNH; j++) {
        float z = fmaf(c0, sm[O_PEW1 + j], fmaf(c1, sm[O_PEW1 + 64 + j], sm[O_PEB1 + j]));
        z = gelu_exact(z);
#pragma unroll
        for (int dq = 0; dq < 4; dq++) {
            float4 w = *reinterpret_cast<const float4*>(sm + O_PEW2 + j * 16 + dq * 4);
            h[dq * 4 + 0] = fmaf(z, w.x, h[dq * 4 + 0]);
            h[dq * 4 + 1] = fmaf(z, w.y, h[dq * 4 + 1]);
            h[dq * 4 + 2] = fmaf(z, w.z, h[dq * 4 + 2]);
            h[dq * 4 + 3] = fmaf(z, w.w, h[dq * 4 + 3]);
        }
    }

    float mu = 0.f;
#pragma unroll
    for (int d = 0; d < 16; d++) { h[d] += xr[d]; mu += h[d]; }
    mu *= (1.f / 16.f);
    float var = 0.f;
#pragma unroll
    for (int d = 0; d < 16; d++) { float c = h[d] - mu; var = fmaf(c, c, var); }
    var *= (1.f / 16.f);
    const float rstd = 1.f / sqrtf(var + 1e-5f);
#pragma unroll
    for (int d = 0; d < 16; d++)
        h[d] = (h[d] - mu) * rstd * sm[O_LNG + d] + sm[O_LNB + d];

    float q[16], k[16], v[16];
#pragma unroll
    for (int d = 0; d < 16; d++) { q[d] = 0.f; k[d] = 0.f; v[d] = 0.f; }
    mat16(sm + O_QW, h, q);
    mat16(sm + O_KW, h, k);
    mat16(sm + O_VW, xr, v);

    float o[16];
#pragma unroll
    for (int hh = 0; hh < H; hh++) {
        float qh[4], kh[4], vh[4];
#pragma unroll
        for (int c = 0; c < 4; c++) {
            qh[c] = q[hh * 4 + c]; kh[c] = k[hh * 4 + c]; vh[c] = v[hh * 4 + c];
        }
        float qs = fmaf(qh[3], qh[3], fmaf(qh[2], qh[2], fmaf(qh[1], qh[1], qh[0] * qh[0])));
        float ks = fmaf(kh[3], kh[3], fmaf(kh[2], kh[2], fmaf(kh[1], kh[1], kh[0] * kh[0])));
        const float qi = 1.f / (sqrtf(qs) + 1e-6f);
        const float ki = 1.f / (sqrtf(ks) + 1e-6f);
#pragma unroll
        for (int c = 0; c < 4; c++) { qh[c] *= qi; kh[c] *= ki; }

        const float scl = sm[O_SC + hh];
        float lg[16];
#pragma unroll
        for (int j = 0; j < 16; j++) {
            float dot = 0.f;
#pragma unroll
            for (int c = 0; c < 4; c++) {
                float kj = __shfl_sync(0xffffffffu, kh[c], j, 16);
                dot = fmaf(qh[c], kj, dot);
            }
            lg[j] = dot * scl;
        }
        float mx = lg[0];
#pragma unroll
        for (int j = 1; j < 16; j++) mx = fmaxf(mx, lg[j]);
        float ssum = 0.f;
#pragma unroll
        for (int j = 0; j < 16; j++) { lg[j] = expf(lg[j] - mx); ssum += lg[j]; }
        const float inv = 1.f / ssum;
        float oh[4] = {0.f, 0.f, 0.f, 0.f};
#pragma unroll
        for (int j = 0; j < 16; j++) {
            const float a = lg[j] * inv;
#pragma unroll
            for (int c = 0; c < 4; c++) {
                float vj = __shfl_sync(0xffffffffu, vh[c], j, 16);
                oh[c] = fmaf(a, vj, oh[c]);
            }
        }
#pragma unroll
        for (int c = 0; c < 4; c++) o[hh * 4 + c] = oh[c];
    }

    float o2[16];
#pragma unroll
    for (int d = 0; d < 16; d++) o2[d] = 0.f;
    mat16(sm + O_OW, o, o2);

    float acc2 = 0.f;
#pragma unroll
    for (int j = 0; j < FFNH; j++) {
        float z = sm[O_MB1 + j];
#pragma unroll
        for (int kk = 0; kk < 16; kk++)
            z = fmaf(o2[kk], sm[O_MW1 + kk * 64 + j], z);
        acc2 = fmaf(gelu_exact(z), sm[O_MW2 + j], acc2);
    }
    const float m = gelu_exact(acc2 + sm[O_MB2]);

    float4* dst = reinterpret_cast<float4*>(g_oflat + (size_t)tok * MD + i * 16);
#pragma unroll
    for (int dq = 0; dq < 4; dq++)
        dst[dq] = make_float4(o2[dq * 4 + 0] + m, o2[dq * 4 + 1] + m,
                              o2[dq * 4 + 2] + m, o2[dq * 4 + 3] + m);
}

// ---------------------------------------------------------------------------
// K3 (fused, tf32 tensor cores): unchanged from round 5 (passing).
// ---------------------------------------------------------------------------
__device__ __forceinline__ void mma_tf32(float* c, const uint32_t* a, const uint32_t* bb) {
    asm volatile(
        "mma.sync.aligned.m16n8k8.row.col.f32.tf32.tf32.f32 "
        "{%0,%1,%2,%3}, {%4,%5,%6,%7}, {%8,%9}, {%0,%1,%2,%3};"
        : "+f"(c[0]), "+f"(c[1]), "+f"(c[2]), "+f"(c[3])
        : "r"(a[0]), "r"(a[1]), "r"(a[2]), "r"(a[3]), "r"(bb[0]), "r"(bb[1]));
}

constexpr int APAD = 36;
constexpr int BPAD = 72;
constexpr int CPAD = 66;

__global__ __launch_bounds__(256) void fused_mlp_kernel(
    const float* __restrict__ W1, const float* __restrict__ b1,
    const float* __restrict__ W2, const float* __restrict__ b2,
    float* __restrict__ out) {
    __shared__ __align__(16) uint32_t smem_u[9472];            // 37888 B union
    uint32_t* As = smem_u;                                     // [128][36] tf32
    uint32_t* Bs = smem_u + 128 * APAD;                        // [32][72] tf32
    float* Cs  = reinterpret_cast<float*>(smem_u);             // [128][66] f32
    float* W2s = reinterpret_cast<float*>(smem_u) + 128 * CPAD;// [64][16] f32

    const int tid  = threadIdx.x;
    const int lane = tid & 31;
    const int wid  = tid >> 5;
    const int warp_m = wid & 3;
    const int warp_n = wid >> 2;
    const int row0 = blockIdx.x * 128;

    const int a_row  = tid >> 1;
    const int a_kofs = (tid & 1) * 16;
    const int b_krow = tid >> 3;
    const int b_ncol = (tid & 7) * 8;
    const int p2row = tid >> 1;
    const int p2n   = (tid & 1) * 8;

    const float* arow_g = g_oflat + (size_t)(row0 + a_row) * MD + a_kofs;

    float out_acc[8];
#pragma unroll
    for (int i = 0; i < 8; i++) out_acc[i] = 0.f;

    for (int ch = 0; ch < 16; ch++) {
        const int col0 = ch * 64;
        float cfr[2][4][4];
#pragma unroll
        for (int ma = 0; ma < 2; ma++)
#pragma unroll
            for (int na = 0; na < 4; na++)
#pragma unroll
                for (int i = 0; i < 4; i++) cfr[ma][na][i] = 0.f;

#pragma unroll 1
        for (int kt = 0; kt < 8; kt++) {
            float4 av[4], bv[2];
#pragma unroll
            for (int q = 0; q < 4; q++)
                av[q] = *reinterpret_cast<const float4*>(arow_g + kt * 32 + q * 4);
#pragma unroll
            for (int q = 0; q < 2; q++)
                bv[q] = *reinterpret_cast<const float4*>(
                    W1 + (size_t)(kt * 32 + b_krow) * FF + col0 + b_ncol + q * 4);
            __syncthreads();
#pragma unroll
            for (int q = 0; q < 4; q++) {
                uint4 at = make_uint4(f2tf32(av[q].x), f2tf32(av[q].y),
                                      f2tf32(av[q].z), f2tf32(av[q].w));
                *reinterpret_cast<uint4*>(&As[a_row * APAD + a_kofs + q * 4]) = at;
            }
#pragma unroll
            for (int q = 0; q < 2; q++) {
                uint4 bt = make_uint4(f2tf32(bv[q].x), f2tf32(bv[q].y),
                                      f2tf32(bv[q].z), f2tf32(bv[q].w));
                *reinterpret_cast<uint4*>(&Bs[b_krow * BPAD + b_ncol + q * 4]) = bt;
            }
            __syncthreads();

#pragma unroll
            for (int ks = 0; ks < 4; ks++) {
                const int k0 = ks * 8;
                uint32_t afr[2][4];
#pragma unroll
                for (int ma = 0; ma < 2; ma++) {
                    const int r = warp_m * 32 + ma * 16 + (lane >> 2);
                    const int kc = k0 + (lane & 3);
                    afr[ma][0] = As[r * APAD + kc];
                    afr[ma][1] = As[(r + 8) * APAD + kc];
                    afr[ma][2] = As[r * APAD + kc + 4];
                    afr[ma][3] = As[(r + 8) * APAD + kc + 4];
                }
                uint32_t bfr[4][2];
#pragma unroll
                for (int na = 0; na < 4; na++) {
                    const int n = warp_n * 32 + na * 8 + (lane >> 2);
                    const int kc = k0 + (lane & 3);
                    bfr[na][0] = Bs[kc * BPAD + n];
                    bfr[na][1] = Bs[(kc + 4) * BPAD + n];
                }
#pragma unroll
                for (int ma = 0; ma < 2; ma++)
#pragma unroll
                    for (int na = 0; na < 4; na++)
                        mma_tf32(cfr[ma][na], afr[ma], bfr[na]);
            }
        }

        __syncthreads();

#pragma unroll
        for (int ma = 0; ma < 2; ma++) {
            const int r0 = warp_m * 32 + ma * 16 + (lane >> 2);
#pragma unroll
            for (int na = 0; na < 4; na++) {
                const int cl = warp_n * 32 + na * 8 + 2 * (lane & 3);
                const float bb0 = __ldg(b1 + col0 + cl);
                const float bb1 = __ldg(b1 + col0 + cl + 1);
                float2 v0, v1;
                v0.x = gelu_exact(cfr[ma][na][0] + bb0);
                v0.y = gelu_exact(cfr[ma][na][1] + bb1);
                v1.x = gelu_exact(cfr[ma][na][2] + bb0);
                v1.y = gelu_exact(cfr[ma][na][3] + bb1);
                *reinterpret_cast<float2*>(&Cs[r0 * CPAD + cl]) = v0;
                *reinterpret_cast<float2*>(&Cs[(r0 + 8) * CPAD + cl]) = v1;
            }
        }
        *reinterpret_cast<float4*>(&W2s[(tid >> 2) * 16 + (tid & 3) * 4]) =
            *reinterpret_cast<const float4*>(W2 + (size_t)(col0 + (tid >> 2)) * 16 + (tid & 3) * 4);
        __syncthreads();

#pragma unroll 8
        for (int c = 0; c < 64; c++) {
            const float cv = Cs[p2row * CPAD + c];
            const float4 wa = *reinterpret_cast<const float4*>(&W2s[c * 16 + p2n]);
            const float4 wb = *reinterpret_cast<const float4*>(&W2s[c * 16 + p2n + 4]);
            out_acc[0] = fmaf(cv, wa.x, out_acc[0]);
            out_acc[1] = fmaf(cv, wa.y, out_acc[1]);
            out_acc[2] = fmaf(cv, wa.z, out_acc[2]);
            out_acc[3] = fmaf(cv, wa.w, out_acc[3]);
            out_acc[4] = fmaf(cv, wb.x, out_acc[4]);
            out_acc[5] = fmaf(cv, wb.y, out_acc[5]);
            out_acc[6] = fmaf(cv, wb.z, out_acc[6]);
            out_acc[7] = fmaf(cv, wb.w, out_acc[7]);
        }
    }

    const float4 b2a = *reinterpret_cast<const float4*>(b2 + p2n);
    const float4 b2b = *reinterpret_cast<const float4*>(b2 + p2n + 4);
    float4 oa, ob;
    oa.x = gelu_exact(out_acc[0] + b2a.x);
    oa.y = gelu_exact(out_acc[1] + b2a.y);
    oa.z = gelu_exact(out_acc[2] + b2a.z);
    oa.w = gelu_exact(out_acc[3] + b2a.w);
    ob.x = gelu_exact(out_acc[4] + b2b.x);
    ob.y = gelu_exact(out_acc[5] + b2b.y);
    ob.z = gelu_exact(out_acc[6] + b2b.z);
    ob.w = gelu_exact(out_acc[7] + b2b.w);
    float* orow = out + (size_t)(row0 + p2row) * OUT + p2n;
    *reinterpret_cast<float4*>(orow)     = oa;
    *reinterpret_cast<float4*>(orow + 4) = ob;
}

// ---------------------------------------------------------------------------
extern "C" void kernel_launch(void* const* d_in, const int* in_sizes, int n_in,
                              void* d_out, int out_size) {
    const float* x      = (const float*)d_in[0];
    const float* ct     = (const float*)d_in[1];
    const float* cs     = (const float*)d_in[2];
    const float* pe_w1  = (const float*)d_in[3];
    const float* pe_b1  = (const float*)d_in[4];
    const float* pe_w2  = (const float*)d_in[5];
    const float* pe_b2  = (const float*)d_in[6];
    const float* ln_g   = (const float*)d_in[7];
    const float* ln_b   = (const float*)d_in[8];
    const float* q_w    = (const float*)d_in[9];
    const float* k_w    = (const float*)d_in[10];
    const float* v_w    = (const float*)d_in[11];
    const float* ls     = (const float*)d_in[12];
    const float* out_w  = (const float*)d_in[13];
    const float* mnh_w1 = (const float*)d_in[14];
    const float* mnh_b1 = (const float*)d_in[15];
    const float* mnh_w2 = (const float*)d_in[16];
    const float* mnh_b2 = (const float*)d_in[17];
    const float* mo_w1  = (const float*)d_in[18];
    const float* mo_b1  = (const float*)d_in[19];
    const float* mo_w2  = (const float*)d_in[20];
    const float* mo_b2  = (const float*)d_in[21];

    grid_build<<<B, 256>>>(cs);
    knn_kernel<<<dim3(T / 128, B), 128>>>(ct);
    token_kernel<<<NTOK / 16, 256>>>(x, ct, cs, pe_w1, pe_b1, pe_w2, pe_b2,
                                     ln_g, ln_b, q_w, k_w, v_w, ls, out_w,
                                     mnh_w1, mnh_b1, mnh_w2, mnh_b2);
    fused_mlp_kernel<<<NTOK / 128, 256>>>(mo_w1, mo_b1, mo_w2, mo_b2, (float*)d_out);
}

// round 7
// speedup vs baseline: 1.8576x; 1.0840x over previous
#include <cuda_runtime.h>
#include <math.h>
#include <stdint.h>

constexpr int B = 4, T = 4096, S = 4096, E = 16;
constexpr int NH = 16, H = 4, MDNH = 16, FFNH = 64;
constexpr int MD = 256, FF = 1024, OUT = 16;
constexpr int NTOK = B * T;
constexpr int GC = 16;                 // grid cells per axis
constexpr int NCG = 4;                 // fused-MLP column groups

// Scratch (static device allocations — no cudaMalloc allowed)
__device__ int    g_idx[NTOK * NH];                // 1 MB
__device__ float  g_oflat[(size_t)NTOK * MD];      // 16.8 MB (L2-resident)
__device__ float2 g_gxy[B][S];
__device__ int    g_gid[B][S];
__device__ int    g_cstart[B][GC * GC + 1];
__device__ float  g_partial[NCG][(size_t)NTOK * OUT];  // 4 MB

__device__ __forceinline__ float gelu_exact(float x) { return x * normcdff(x); }

__device__ __forceinline__ uint32_t f2tf32(float f) {
    uint32_t u;
    asm("cvt.rna.tf32.f32 %0, %1;" : "=r"(u) : "f"(f));
    return u;
}

// ---------------------------------------------------------------------------
// K0: bin sources into a 16x16 uniform grid (counting sort). One block/batch.
// ---------------------------------------------------------------------------
__global__ __launch_bounds__(256) void grid_build(const float* __restrict__ cs) {
    __shared__ int cnt[GC * GC];
    __shared__ int start[GC * GC + 1];
    const int b = blockIdx.x, tid = threadIdx.x;
    cnt[tid] = 0;
    __syncthreads();
    const float2* csb = reinterpret_cast<const float2*>(cs) + (size_t)b * S;
    for (int i = tid; i < S; i += 256) {
        float2 c = csb[i];
        int cx = min(GC - 1, (int)(c.x * GC));
        int cy = min(GC - 1, (int)(c.y * GC));
        atomicAdd(&cnt[cy * GC + cx], 1);
    }
    __syncthreads();
    if (tid == 0) {
        int acc = 0;
        for (int i = 0; i < GC * GC; i++) { start[i] = acc; acc += cnt[i]; }
        start[GC * GC] = acc;
    }
    __syncthreads();
    cnt[tid] = start[tid];
    g_cstart[b][tid] = start[tid];
    if (tid == 0) g_cstart[b][GC * GC] = start[GC * GC];
    __syncthreads();
    for (int i = tid; i < S; i += 256) {
        float2 c = csb[i];
        int cx = min(GC - 1, (int)(c.x * GC));
        int cy = min(GC - 1, (int)(c.y * GC));
        int pos = atomicAdd(&cnt[cy * GC + cx], 1);
        g_gxy[b][pos] = c;
        g_gid[b][pos] = i;
    }
}

// ---------------------------------------------------------------------------
// K1: exact 16-NN via expanding grid rings (order-independent (d2,idx) keys).
// ---------------------------------------------------------------------------
__global__ __launch_bounds__(128) void knn_kernel(const float* __restrict__ ct) {
    const int b = blockIdx.y;
    const int t = blockIdx.x * 128 + threadIdx.x;
    const float tx = ct[((size_t)b * T + t) * 2 + 0];
    const float ty = ct[((size_t)b * T + t) * 2 + 1];
    const int cx = min(GC - 1, (int)(tx * GC));
    const int cy = min(GC - 1, (int)(ty * GC));

    const float2* __restrict__ gxy = g_gxy[b];
    const int*    __restrict__ gid = g_gid[b];
    const int*    __restrict__ cst = g_cstart[b];
    constexpr float hcell = 1.0f / GC;
    constexpr unsigned long long KMAX = 0xFFFFFFFFFFFFFFFFull;

    unsigned long long key[NH];
#pragma unroll
    for (int i = 0; i < NH; i++) key[i] = KMAX;

    for (int rho = 0; rho <= GC - 1; rho++) {
        if (rho > 1 && key[NH - 1] != KMAX) {
            const float wd2 = __uint_as_float((unsigned)(key[NH - 1] >> 32));
            const float bound = (rho - 1) * hcell;
            if (wd2 < bound * bound) break;
        }
        const int ylo = max(cy - rho, 0), yhi = min(cy + rho, GC - 1);
        for (int ay = ylo; ay <= yhi; ay++) {
            const bool fullrow = (ay == cy - rho) || (ay == cy + rho);
            const int step = fullrow ? 1 : (rho > 0 ? 2 * rho : 1);
            for (int ax = cx - rho; ax <= cx + rho; ax += step) {
                if (ax < 0 || ax >= GC) continue;
                const int cell = ay * GC + ax;
                const int c1 = cst[cell + 1];
                for (int j = cst[cell]; j < c1; j++) {
                    const float2 p = gxy[j];
                    const float dxx = tx - p.x, dyy = ty - p.y;
                    const float d2 = fmaf(dyy, dyy, dxx * dxx);
                    unsigned long long ck =
                        ((unsigned long long)__float_as_uint(d2) << 32) |
                        (unsigned)gid[j];
                    if (ck < key[NH - 1]) {
                        bool ins = false;
#pragma unroll
                        for (int q = 0; q < NH; q++) {
                            bool sm = ins | (ck < key[q]);
                            unsigned long long tk = key[q];
                            key[q] = sm ? ck : tk;
                            ck = sm ? tk : ck;
                            ins = sm;
                        }
                    }
                }
            }
        }
    }

    const int base = (b * T + t) * NH;
#pragma unroll
    for (int i = 0; i < NH; i++)
        g_idx[base + i] = (int)(key[i] & 0xFFFFFFFFull);
}

// ---------------------------------------------------------------------------
// K2: per-token local pipeline (unchanged, passing).
// ---------------------------------------------------------------------------
constexpr int O_PEW1 = 0;
constexpr int O_PEB1 = 128;
constexpr int O_PEW2 = 192;
constexpr int O_PEB2 = 1216;
constexpr int O_LNG  = 1232;
constexpr int O_LNB  = 1248;
constexpr int O_QW   = 1264;
constexpr int O_KW   = 1520;
constexpr int O_VW   = 1776;
constexpr int O_OW   = 2032;
constexpr int O_MW1  = 2288;
constexpr int O_MB1  = 3312;
constexpr int O_MW2  = 3376;
constexpr int O_MB2  = 3440;
constexpr int O_SC   = 3441;
constexpr int SM_TOT = 3448;

__device__ __forceinline__ void mat16(const float* __restrict__ Wsh,
                                      const float* __restrict__ vin,
                                      float* __restrict__ vout) {
#pragma unroll
    for (int k = 0; k < 16; k++) {
        const float hv = vin[k];
#pragma unroll
        for (int dq = 0; dq < 4; dq++) {
            float4 w = *reinterpret_cast<const float4*>(Wsh + k * 16 + dq * 4);
            vout[dq * 4 + 0] = fmaf(hv, w.x, vout[dq * 4 + 0]);
            vout[dq * 4 + 1] = fmaf(hv, w.y, vout[dq * 4 + 1]);
            vout[dq * 4 + 2] = fmaf(hv, w.z, vout[dq * 4 + 2]);
            vout[dq * 4 + 3] = fmaf(hv, w.w, vout[dq * 4 + 3]);
        }
    }
}

__global__ __launch_bounds__(256) void token_kernel(
    const float* __restrict__ x, const float* __restrict__ ct, const float* __restrict__ cs,
    const float* __restrict__ pe_w1, const float* __restrict__ pe_b1,
    const float* __restrict__ pe_w2, const float* __restrict__ pe_b2,
    const float* __restrict__ ln_g, const float* __restrict__ ln_b,
    const float* __restrict__ q_w, const float* __restrict__ k_w,
    const float* __restrict__ v_w, const float* __restrict__ lscale,
    const float* __restrict__ out_w,
    const float* __restrict__ mnh_w1, const float* __restrict__ mnh_b1,
    const float* __restrict__ mnh_w2, const float* __restrict__ mnh_b2) {
    __shared__ float sm[SM_TOT];
    const int tid = threadIdx.x;
    for (int i = tid; i < 128;  i += 256) sm[O_PEW1 + i] = pe_w1[i];
    for (int i = tid; i < 64;   i += 256) sm[O_PEB1 + i] = pe_b1[i];
    for (int i = tid; i < 1024; i += 256) sm[O_PEW2 + i] = pe_w2[i];
    for (int i = tid; i < 16;   i += 256) sm[O_PEB2 + i] = pe_b2[i];
    for (int i = tid; i < 16;   i += 256) sm[O_LNG + i]  = ln_g[i];
    for (int i = tid; i < 16;   i += 256) sm[O_LNB + i]  = ln_b[i];
    for (int i = tid; i < 256;  i += 256) sm[O_QW + i]   = q_w[i];
    for (int i = tid; i < 256;  i += 256) sm[O_KW + i]   = k_w[i];
    for (int i = tid; i < 256;  i += 256) sm[O_VW + i]   = v_w[i];
    for (int i = tid; i < 256;  i += 256) sm[O_OW + i]   = out_w[i];
    for (int i = tid; i < 1024; i += 256) sm[O_MW1 + i]  = mnh_w1[i];
    for (int i = tid; i < 64;   i += 256) sm[O_MB1 + i]  = mnh_b1[i];
    for (int i = tid; i < 64;   i += 256) sm[O_MW2 + i]  = mnh_w2[i];
    if (tid == 0) sm[O_MB2] = mnh_b2[0];
    if (tid < 4)  sm[O_SC + tid] = expf(fminf(lscale[tid], 4.6051702f));
    __syncthreads();

    const int tok = blockIdx.x * 16 + (tid >> 4);
    const int i   = tid & 15;
    const int b   = tok / T;
    const int nidx = g_idx[tok * NH + i];

    float xr[16];
    const float4* xrow = reinterpret_cast<const float4*>(x + ((size_t)b * S + nidx) * E);
#pragma unroll
    for (int q4 = 0; q4 < 4; q4++) {
        float4 v4 = __ldg(xrow + q4);
        xr[q4 * 4 + 0] = v4.x; xr[q4 * 4 + 1] = v4.y;
        xr[q4 * 4 + 2] = v4.z; xr[q4 * 4 + 3] = v4.w;
    }
    const float2 scoord = __ldg(reinterpret_cast<const float2*>(cs) + (size_t)b * S + nidx);
    const float2 tcoord = __ldg(reinterpret_cast<const float2*>(ct) + tok);
    const float c0 = scoord.x - tcoord.x, c1 = scoord.y - tcoord.y;

    float h[16];
#pragma unroll
    for (int d = 0; d < 16; d++) h[d] = sm[O_PEB2 + d];
#pragma unroll
    for (int j = 0; j < FFNH; j++) {
        float z = fmaf(c0, sm[O_PEW1 + j], fmaf(c1, sm[O_PEW1 + 64 + j], sm[O_PEB1 + j]));
        z = gelu_exact(z);
#pragma unroll
        for (int dq = 0; dq < 4; dq++) {
            float4 w = *reinterpret_cast<const float4*>(sm + O_PEW2 + j * 16 + dq * 4);
            h[dq * 4 + 0] = fmaf(z, w.x, h[dq * 4 + 0]);
            h[dq * 4 + 1] = fmaf(z, w.y, h[dq * 4 + 1]);
            h[dq * 4 + 2] = fmaf(z, w.z, h[dq * 4 + 2]);
            h[dq * 4 + 3] = fmaf(z, w.w, h[dq * 4 + 3]);
        }
    }

    float mu = 0.f;
#pragma unroll
    for (int d = 0; d < 16; d++) { h[d] += xr[d]; mu += h[d]; }
    mu *= (1.f / 16.f);
    float var = 0.f;
#pragma unroll
    for (int d = 0; d < 16; d++) { float c = h[d] - mu; var = fmaf(c, c, var); }
    var *= (1.f / 16.f);
    const float rstd = 1.f / sqrtf(var + 1e-5f);
#pragma unroll
    for (int d = 0; d < 16; d++)
        h[d] = (h[d] - mu) * rstd * sm[O_LNG + d] + sm[O_LNB + d];

    float q[16], k[16], v[16];
#pragma unroll
    for (int d = 0; d < 16; d++) { q[d] = 0.f; k[d] = 0.f; v[d] = 0.f; }
    mat16(sm + O_QW, h, q);
    mat16(sm + O_KW, h, k);
    mat16(sm + O_VW, xr, v);

    float o[16];
#pragma unroll
    for (int hh = 0; hh < H; hh++) {
        float qh[4], kh[4], vh[4];
#pragma unroll
        for (int c = 0; c < 4; c++) {
            qh[c] = q[hh * 4 + c]; kh[c] = k[hh * 4 + c]; vh[c] = v[hh * 4 + c];
        }
        float qs = fmaf(qh[3], qh[3], fmaf(qh[2], qh[2], fmaf(qh[1], qh[1], qh[0] * qh[0])));
        float ks = fmaf(kh[3], kh[3], fmaf(kh[2], kh[2], fmaf(kh[1], kh[1], kh[0] * kh[0])));
        const float qi = 1.f / (sqrtf(qs) + 1e-6f);
        const float ki = 1.f / (sqrtf(ks) + 1e-6f);
#pragma unroll
        for (int c = 0; c < 4; c++) { qh[c] *= qi; kh[c] *= ki; }

        const float scl = sm[O_SC + hh];
        float lg[16];
#pragma unroll
        for (int j = 0; j < 16; j++) {
            float dot = 0.f;
#pragma unroll
            for (int c = 0; c < 4; c++) {
                float kj = __shfl_sync(0xffffffffu, kh[c], j, 16);
                dot = fmaf(qh[c], kj, dot);
            }
            lg[j] = dot * scl;
        }
        float mx = lg[0];
#pragma unroll
        for (int j = 1; j < 16; j++) mx = fmaxf(mx, lg[j]);
        float ssum = 0.f;
#pragma unroll
        for (int j = 0; j < 16; j++) { lg[j] = expf(lg[j] - mx); ssum += lg[j]; }
        const float inv = 1.f / ssum;
        float oh[4] = {0.f, 0.f, 0.f, 0.f};
#pragma unroll
        for (int j = 0; j < 16; j++) {
            const float a = lg[j] * inv;
#pragma unroll
            for (int c = 0; c < 4; c++) {
                float vj = __shfl_sync(0xffffffffu, vh[c], j, 16);
                oh[c] = fmaf(a, vj, oh[c]);
            }
        }
#pragma unroll
        for (int c = 0; c < 4; c++) o[hh * 4 + c] = oh[c];
    }

    float o2[16];
#pragma unroll
    for (int d = 0; d < 16; d++) o2[d] = 0.f;
    mat16(sm + O_OW, o, o2);

    float acc2 = 0.f;
#pragma unroll
    for (int j = 0; j < FFNH; j++) {
        float z = sm[O_MB1 + j];
#pragma unroll
        for (int kk = 0; kk < 16; kk++)
            z = fmaf(o2[kk], sm[O_MW1 + kk * 64 + j], z);
        acc2 = fmaf(gelu_exact(z), sm[O_MW2 + j], acc2);
    }
    const float m = gelu_exact(acc2 + sm[O_MB2]);

    float4* dst = reinterpret_cast<float4*>(g_oflat + (size_t)tok * MD + i * 16);
#pragma unroll
    for (int dq = 0; dq < 4; dq++)
        dst[dq] = make_float4(o2[dq * 4 + 0] + m, o2[dq * 4 + 1] + m,
                              o2[dq * 4 + 2] + m, o2[dq * 4 + 3] + m);
}

// ---------------------------------------------------------------------------
// K3 (fused, tf32): grid = 128 rowblocks x 4 colgroups. Each colgroup does
// 4 of the 16 column chunks and writes a pre-bias partial of h1@W2 to
// g_partial[cg] (no atomics -> deterministic). K4 reduces + bias + gelu.
// ---------------------------------------------------------------------------
__device__ __forceinline__ void mma_tf32(float* c, const uint32_t* a, const uint32_t* bb) {
    asm volatile(
        "mma.sync.aligned.m16n8k8.row.col.f32.tf32.tf32.f32 "
        "{%0,%1,%2,%3}, {%4,%5,%6,%7}, {%8,%9}, {%0,%1,%2,%3};"
        : "+f"(c[0]), "+f"(c[1]), "+f"(c[2]), "+f"(c[3])
        : "r"(a[0]), "r"(a[1]), "r"(a[2]), "r"(a[3]), "r"(bb[0]), "r"(bb[1]));
}

constexpr int APAD = 36;
constexpr int BPAD = 72;
constexpr int CPAD = 66;

__global__ __launch_bounds__(256) void fused_mlp_kernel(
    const float* __restrict__ W1, const float* __restrict__ b1,
    const float* __restrict__ W2) {
    __shared__ __align__(16) uint32_t smem_u[9472];            // 37888 B union
    uint32_t* As = smem_u;                                     // [128][36] tf32
    uint32_t* Bs = smem_u + 128 * APAD;                        // [32][72] tf32
    float* Cs  = reinterpret_cast<float*>(smem_u);             // [128][66] f32
    float* W2s = reinterpret_cast<float*>(smem_u) + 128 * CPAD;// [64][16] f32

    const int tid  = threadIdx.x;
    const int lane = tid & 31;
    const int wid  = tid >> 5;
    const int warp_m = wid & 3;
    const int warp_n = wid >> 2;
    const int row0 = blockIdx.x * 128;
    const int cg   = blockIdx.y;

    const int a_row  = tid >> 1;
    const int a_kofs = (tid & 1) * 16;
    const int b_krow = tid >> 3;
    const int b_ncol = (tid & 7) * 8;
    const int p2row = tid >> 1;
    const int p2n   = (tid & 1) * 8;

    const float* arow_g = g_oflat + (size_t)(row0 + a_row) * MD + a_kofs;

    float out_acc[8];
#pragma unroll
    for (int i = 0; i < 8; i++) out_acc[i] = 0.f;

    for (int ch = cg * 4; ch < cg * 4 + 4; ch++) {
        const int col0 = ch * 64;
        float cfr[2][4][4];
#pragma unroll
        for (int ma = 0; ma < 2; ma++)
#pragma unroll
            for (int na = 0; na < 4; na++)
#pragma unroll
                for (int i = 0; i < 4; i++) cfr[ma][na][i] = 0.f;

#pragma unroll 1
        for (int kt = 0; kt < 8; kt++) {
            float4 av[4], bv[2];
#pragma unroll
            for (int q = 0; q < 4; q++)
                av[q] = *reinterpret_cast<const float4*>(arow_g + kt * 32 + q * 4);
#pragma unroll
            for (int q = 0; q < 2; q++)
                bv[q] = *reinterpret_cast<const float4*>(
                    W1 + (size_t)(kt * 32 + b_krow) * FF + col0 + b_ncol + q * 4);
            __syncthreads();
#pragma unroll
            for (int q = 0; q < 4; q++) {
                uint4 at = make_uint4(f2tf32(av[q].x), f2tf32(av[q].y),
                                      f2tf32(av[q].z), f2tf32(av[q].w));
                *reinterpret_cast<uint4*>(&As[a_row * APAD + a_kofs + q * 4]) = at;
            }
#pragma unroll
            for (int q = 0; q < 2; q++) {
                uint4 bt = make_uint4(f2tf32(bv[q].x), f2tf32(bv[q].y),
                                      f2tf32(bv[q].z), f2tf32(bv[q].w));
                *reinterpret_cast<uint4*>(&Bs[b_krow * BPAD + b_ncol + q * 4]) = bt;
            }
            __syncthreads();

#pragma unroll
            for (int ks = 0; ks < 4; ks++) {
                const int k0 = ks * 8;
                uint32_t afr[2][4];
#pragma unroll
                for (int ma = 0; ma < 2; ma++) {
                    const int r = warp_m * 32 + ma * 16 + (lane >> 2);
                    const int kc = k0 + (lane & 3);
                    afr[ma][0] = As[r * APAD + kc];
                    afr[ma][1] = As[(r + 8) * APAD + kc];
                    afr[ma][2] = As[r * APAD + kc + 4];
                    afr[ma][3] = As[(r + 8) * APAD + kc + 4];
                }
                uint32_t bfr[4][2];
#pragma unroll
                for (int na = 0; na < 4; na++) {
                    const int n = warp_n * 32 + na * 8 + (lane >> 2);
                    const int kc = k0 + (lane & 3);
                    bfr[na][0] = Bs[kc * BPAD + n];
                    bfr[na][1] = Bs[(kc + 4) * BPAD + n];
                }
#pragma unroll
                for (int ma = 0; ma < 2; ma++)
#pragma unroll
                    for (int na = 0; na < 4; na++)
                        mma_tf32(cfr[ma][na], afr[ma], bfr[na]);
            }
        }

        __syncthreads();

#pragma unroll
        for (int ma = 0; ma < 2; ma++) {
            const int r0 = warp_m * 32 + ma * 16 + (lane >> 2);
#pragma unroll
            for (int na = 0; na < 4; na++) {
                const int cl = warp_n * 32 + na * 8 + 2 * (lane & 3);
                const float bb0 = __ldg(b1 + col0 + cl);
                const float bb1 = __ldg(b1 + col0 + cl + 1);
                float2 v0, v1;
                v0.x = gelu_exact(cfr[ma][na][0] + bb0);
                v0.y = gelu_exact(cfr[ma][na][1] + bb1);
                v1.x = gelu_exact(cfr[ma][na][2] + bb0);
                v1.y = gelu_exact(cfr[ma][na][3] + bb1);
                *reinterpret_cast<float2*>(&Cs[r0 * CPAD + cl]) = v0;
                *reinterpret_cast<float2*>(&Cs[(r0 + 8) * CPAD + cl]) = v1;
            }
        }
        *reinterpret_cast<float4*>(&W2s[(tid >> 2) * 16 + (tid & 3) * 4]) =
            *reinterpret_cast<const float4*>(W2 + (size_t)(col0 + (tid >> 2)) * 16 + (tid & 3) * 4);
        __syncthreads();

#pragma unroll 8
        for (int c = 0; c < 64; c++) {
            const float cv = Cs[p2row * CPAD + c];
            const float4 wa = *reinterpret_cast<const float4*>(&W2s[c * 16 + p2n]);
            const float4 wb = *reinterpret_cast<const float4*>(&W2s[c * 16 + p2n + 4]);
            out_acc[0] = fmaf(cv, wa.x, out_acc[0]);
            out_acc[1] = fmaf(cv, wa.y, out_acc[1]);
            out_acc[2] = fmaf(cv, wa.z, out_acc[2]);
            out_acc[3] = fmaf(cv, wa.w, out_acc[3]);
            out_acc[4] = fmaf(cv, wb.x, out_acc[4]);
            out_acc[5] = fmaf(cv, wb.y, out_acc[5]);
            out_acc[6] = fmaf(cv, wb.z, out_acc[6]);
            out_acc[7] = fmaf(cv, wb.w, out_acc[7]);
        }
    }

    float* prow = &g_partial[cg][(size_t)(row0 + p2row) * OUT + p2n];
    *reinterpret_cast<float4*>(prow)     = make_float4(out_acc[0], out_acc[1], out_acc[2], out_acc[3]);
    *reinterpret_cast<float4*>(prow + 4) = make_float4(out_acc[4], out_acc[5], out_acc[6], out_acc[7]);
}

// ---------------------------------------------------------------------------
// K4: out = gelu(sum_cg partial + b2). Fixed summation order -> deterministic.
// ---------------------------------------------------------------------------
__global__ __launch_bounds__(256) void out_reduce(const float* __restrict__ b2,
                                                  float* __restrict__ out) {
    const int gid = blockIdx.x * 256 + threadIdx.x;
    const int n = gid & (OUT - 1);
    float s = g_partial[0][gid];
    s += g_partial[1][gid];
    s += g_partial[2][gid];
    s += g_partial[3][gid];
    out[gid] = gelu_exact(s + b2[n]);
}

// ---------------------------------------------------------------------------
extern "C" void kernel_launch(void* const* d_in, const int* in_sizes, int n_in,
                              void* d_out, int out_size) {
    const float* x      = (const float*)d_in[0];
    const float* ct     = (const float*)d_in[1];
    const float* cs     = (const float*)d_in[2];
    const float* pe_w1  = (const float*)d_in[3];
    const float* pe_b1  = (const float*)d_in[4];
    const float* pe_w2  = (const float*)d_in[5];
    const float* pe_b2  = (const float*)d_in[6];
    const float* ln_g   = (const float*)d_in[7];
    const float* ln_b   = (const float*)d_in[8];
    const float* q_w    = (const float*)d_in[9];
    const float* k_w    = (const float*)d_in[10];
    const float* v_w    = (const float*)d_in[11];
    const float* ls     = (const float*)d_in[12];
    const float* out_w  = (const float*)d_in[13];
    const float* mnh_w1 = (const float*)d_in[14];
    const float* mnh_b1 = (const float*)d_in[15];
    const float* mnh_w2 = (const float*)d_in[16];
    const float* mnh_b2 = (const float*)d_in[17];
    const float* mo_w1  = (const float*)d_in[18];
    const float* mo_b1  = (const float*)d_in[19];
    const float* mo_w2  = (const float*)d_in[20];
    const float* mo_b2  = (const float*)d_in[21];

    grid_build<<<B, 256>>>(cs);
    knn_kernel<<<dim3(T / 128, B), 128>>>(ct);
    token_kernel<<<NTOK / 16, 256>>>(x, ct, cs, pe_w1, pe_b1, pe_w2, pe_b2,
                                     ln_g, ln_b, q_w, k_w, v_w, ls, out_w,
                                     mnh_w1, mnh_b1, mnh_w2, mnh_b2);
    fused_mlp_kernel<<<dim3(NTOK / 128, NCG), 256>>>(mo_w1, mo_b1, mo_w2);
    out_reduce<<<NTOK * OUT / 256, 256>>>(mo_b2, (float*)d_out);
}

// round 10
// speedup vs baseline: 1.9150x; 1.0309x over previous
#include <cuda_runtime.h>
#include <math.h>
#include <stdint.h>

constexpr int B = 4, T = 4096, S = 4096, E = 16;
constexpr int NH = 16, H = 4, FFNH = 64;
constexpr int MD = 256, FF = 1024, OUT = 16;
constexpr int NTOK = B * T;
constexpr int GC = 16;                 // knn grid cells per axis
constexpr int NCG = 8;                 // fused-MLP column groups

// Scratch (static device allocations — no cudaMalloc allowed)
__device__ int    g_idx[NTOK * NH];                // 1 MB
__device__ float  g_oflat[(size_t)NTOK * MD];      // 16.8 MB (L2-resident)
__device__ float2 g_gxy[B][S];
__device__ int    g_gid[B][S];
__device__ int    g_cstart[B][GC * GC + 1];
__device__ float  g_partial[NCG][(size_t)NTOK * OUT];  // 16 MB

__device__ __forceinline__ float gelu_exact(float x) { return x * normcdff(x); }

__device__ __forceinline__ uint32_t f2tf32(float f) {
    uint32_t u;
    asm("cvt.rna.tf32.f32 %0, %1;" : "=r"(u) : "f"(f));
    return u;
}

// ---------------------------------------------------------------------------
// K0: bin sources into a 16x16 uniform grid (counting sort). One block/batch.
// ---------------------------------------------------------------------------
__global__ __launch_bounds__(256) void grid_build(const float* __restrict__ cs) {
    __shared__ int cnt[GC * GC];
    __shared__ int start[GC * GC + 1];
    const int b = blockIdx.x, tid = threadIdx.x;
    cnt[tid] = 0;
    __syncthreads();
    const float2* csb = reinterpret_cast<const float2*>(cs) + (size_t)b * S;
    for (int i = tid; i < S; i += 256) {
        float2 c = csb[i];
        int cx = min(GC - 1, (int)(c.x * GC));
        int cy = min(GC - 1, (int)(c.y * GC));
        atomicAdd(&cnt[cy * GC + cx], 1);
    }
    __syncthreads();
    if (tid == 0) {
        int acc = 0;
        for (int i = 0; i < GC * GC; i++) { start[i] = acc; acc += cnt[i]; }
        start[GC * GC] = acc;
    }
    __syncthreads();
    cnt[tid] = start[tid];
    g_cstart[b][tid] = start[tid];
    if (tid == 0) g_cstart[b][GC * GC] = start[GC * GC];
    __syncthreads();
    for (int i = tid; i < S; i += 256) {
        float2 c = csb[i];
        int cx = min(GC - 1, (int)(c.x * GC));
        int cy = min(GC - 1, (int)(c.y * GC));
        int pos = atomicAdd(&cnt[cy * GC + cx], 1);
        g_gxy[b][pos] = c;
        g_gid[b][pos] = i;
    }
}

// ---------------------------------------------------------------------------
// K1: exact 16-NN via expanding grid rings. TWO lanes per target, cells
// partitioned by (ax+ay)&1. Merge SNAPSHOTS the partner's keys via shuffles
// BEFORE any insertion (both lists pristine), then inserts -- no mutation race.
// ---------------------------------------------------------------------------
__global__ __launch_bounds__(128) void knn_kernel(const float* __restrict__ ct) {
    const int b = blockIdx.y;
    const int lane = threadIdx.x & 31;
    const int par = threadIdx.x & 1;
    const unsigned pairmask = 3u << (lane & ~1);
    const int t = blockIdx.x * 64 + (threadIdx.x >> 1);
    const float tx = ct[((size_t)b * T + t) * 2 + 0];
    const float ty = ct[((size_t)b * T + t) * 2 + 1];
    const int cx = min(GC - 1, (int)(tx * GC));
    const int cy = min(GC - 1, (int)(ty * GC));

    const float2* __restrict__ gxy = g_gxy[b];
    const int*    __restrict__ gid = g_gid[b];
    const int*    __restrict__ cst = g_cstart[b];
    constexpr float hcell = 1.0f / GC;
    constexpr unsigned long long KMAX = 0xFFFFFFFFFFFFFFFFull;

    unsigned long long key[NH];
#pragma unroll
    for (int i = 0; i < NH; i++) key[i] = KMAX;

    for (int rho = 0; rho <= GC - 1; rho++) {
        if (rho > 1) {
            float wl = __uint_as_float((unsigned)(key[NH - 1] >> 32));
            float wo = __shfl_xor_sync(pairmask, wl, 1);
            float wd2 = fminf(wl, wo);           // NaN-safe: picks the number
            const float bound = (rho - 1) * hcell;
            if (wd2 < bound * bound) break;      // identical for both pair lanes
        }
        const int ylo = max(cy - rho, 0), yhi = min(cy + rho, GC - 1);
        for (int ay = ylo; ay <= yhi; ay++) {
            const bool fullrow = (ay == cy - rho) || (ay == cy + rho);
            const int step = fullrow ? 1 : (rho > 0 ? 2 * rho : 1);
            for (int ax = cx - rho; ax <= cx + rho; ax += step) {
                if (ax < 0 || ax >= GC) continue;
                if (((ax + ay) & 1) != par) continue;
                const int cell = ay * GC + ax;
                const int c1 = cst[cell + 1];
                for (int j = cst[cell]; j < c1; j++) {
                    const float2 p = gxy[j];
                    const float dxx = tx - p.x, dyy = ty - p.y;
                    const float d2 = fmaf(dyy, dyy, dxx * dxx);
                    unsigned long long ck =
                        ((unsigned long long)__float_as_uint(d2) << 32) |
                        (unsigned)gid[j];
                    if (ck < key[NH - 1]) {
                        bool ins = false;
#pragma unroll
                        for (int q = 0; q < NH; q++) {
                            bool sm = ins | (ck < key[q]);
                            unsigned long long tk = key[q];
                            key[q] = sm ? ck : tk;
                            ck = sm ? tk : ck;
                            ins = sm;
                        }
                    }
                }
            }
        }
    }

    // snapshot partner's pristine list FIRST (no mutation during exchange)
    unsigned long long pk[NH];
#pragma unroll
    for (int i = 0; i < NH; i++)
        pk[i] = __shfl_xor_sync(pairmask, key[i], 1);
    // then merge from the snapshot
#pragma unroll
    for (int i = 0; i < NH; i++) {
        unsigned long long ck = pk[i];
        if (ck < key[NH - 1]) {
            bool ins = false;
#pragma unroll
            for (int q = 0; q < NH; q++) {
                bool sm = ins | (ck < key[q]);
                unsigned long long tk = key[q];
                key[q] = sm ? ck : tk;
                ck = sm ? tk : ck;
                ins = sm;
            }
        }
    }

    if (par == 0) {
        const int base = (b * T + t) * NH;
#pragma unroll
        for (int i = 0; i < NH; i++)
            g_idx[base + i] = (int)(key[i] & 0xFFFFFFFFull);
    }
}

// ---------------------------------------------------------------------------
// K2: per-token local pipeline (unchanged, passing).
// ---------------------------------------------------------------------------
constexpr int O_PEW1 = 0;
constexpr int O_PEB1 = 128;
constexpr int O_PEW2 = 192;
constexpr int O_PEB2 = 1216;
constexpr int O_LNG  = 1232;
constexpr int O_LNB  = 1248;
constexpr int O_QW   = 1264;
constexpr int O_KW   = 1520;
constexpr int O_VW   = 1776;
constexpr int O_OW   = 2032;
constexpr int O_MW1  = 2288;
constexpr int O_MB1  = 3312;
constexpr int O_MW2  = 3376;
constexpr int O_MB2  = 3440;
constexpr int O_SC   = 3441;
constexpr int SM_TOT = 3448;

__device__ __forceinline__ void mat16(const float* __restrict__ Wsh,
                                      const float* __restrict__ vin,
                                      float* __restrict__ vout) {
#pragma unroll
    for (int k = 0; k < 16; k++) {
        const float hv = vin[k];
#pragma unroll
        for (int dq = 0; dq < 4; dq++) {
            float4 w = *reinterpret_cast<const float4*>(Wsh + k * 16 + dq * 4);
            vout[dq * 4 + 0] = fmaf(hv, w.x, vout[dq * 4 + 0]);
            vout[dq * 4 + 1] = fmaf(hv, w.y, vout[dq * 4 + 1]);
            vout[dq * 4 + 2] = fmaf(hv, w.z, vout[dq * 4 + 2]);
            vout[dq * 4 + 3] = fmaf(hv, w.w, vout[dq * 4 + 3]);
        }
    }
}

__global__ __launch_bounds__(256) void token_kernel(
    const float* __restrict__ x, const float* __restrict__ ct, const float* __restrict__ cs,
    const float* __restrict__ pe_w1, const float* __restrict__ pe_b1,
    const float* __restrict__ pe_w2, const float* __restrict__ pe_b2,
    const float* __restrict__ ln_g, const float* __restrict__ ln_b,
    const float* __restrict__ q_w, const float* __restrict__ k_w,
    const float* __restrict__ v_w, const float* __restrict__ lscale,
    const float* __restrict__ out_w,
    const float* __restrict__ mnh_w1, const float* __restrict__ mnh_b1,
    const float* __restrict__ mnh_w2, const float* __restrict__ mnh_b2) {
    __shared__ float sm[SM_TOT];
    const int tid = threadIdx.x;
    for (int i = tid; i < 128;  i += 256) sm[O_PEW1 + i] = pe_w1[i];
    for (int i = tid; i < 64;   i += 256) sm[O_PEB1 + i] = pe_b1[i];
    for (int i = tid; i < 1024; i += 256) sm[O_PEW2 + i] = pe_w2[i];
    for (int i = tid; i < 16;   i += 256) sm[O_PEB2 + i] = pe_b2[i];
    for (int i = tid; i < 16;   i += 256) sm[O_LNG + i]  = ln_g[i];
    for (int i = tid; i < 16;   i += 256) sm[O_LNB + i]  = ln_b[i];
    for (int i = tid; i < 256;  i += 256) sm[O_QW + i]   = q_w[i];
    for (int i = tid; i < 256;  i += 256) sm[O_KW + i]   = k_w[i];
    for (int i = tid; i < 256;  i += 256) sm[O_VW + i]   = v_w[i];
    for (int i = tid; i < 256;  i += 256) sm[O_OW + i]   = out_w[i];
    for (int i = tid; i < 1024; i += 256) sm[O_MW1 + i]  = mnh_w1[i];
    for (int i = tid; i < 64;   i += 256) sm[O_MB1 + i]  = mnh_b1[i];
    for (int i = tid; i < 64;   i += 256) sm[O_MW2 + i]  = mnh_w2[i];
    if (tid == 0) sm[O_MB2] = mnh_b2[0];
    if (tid < 4)  sm[O_SC + tid] = expf(fminf(lscale[tid], 4.6051702f));
    __syncthreads();

    const int tok = blockIdx.x * 16 + (tid >> 4);
    const int i   = tid & 15;
    const int b   = tok / T;
    const int nidx = g_idx[tok * NH + i];

    float xr[16];
    const float4* xrow = reinterpret_cast<const float4*>(x + ((size_t)b * S + nidx) * E);
#pragma unroll
    for (int q4 = 0; q4 < 4; q4++) {
        float4 v4 = __ldg(xrow + q4);
        xr[q4 * 4 + 0] = v4.x; xr[q4 * 4 + 1] = v4.y;
        xr[q4 * 4 + 2] = v4.z; xr[q4 * 4 + 3] = v4.w;
    }
    const float2 scoord = __ldg(reinterpret_cast<const float2*>(cs) + (size_t)b * S + nidx);
    const float2 tcoord = __ldg(reinterpret_cast<const float2*>(ct) + tok);
    const float c0 = scoord.x - tcoord.x, c1 = scoord.y - tcoord.y;

    float h[16];
#pragma unroll
    for (int d = 0; d < 16; d++) h[d] = sm[O_PEB2 + d];
#pragma unroll
    for (int j = 0; j < FFNH; j++) {
        float z = fmaf(c0, sm[O_PEW1 + j], fmaf(c1, sm[O_PEW1 + 64 + j], sm[O_PEB1 + j]));
        z = gelu_exact(z);
#pragma unroll
        for (int dq = 0; dq < 4; dq++) {
            float4 w = *reinterpret_cast<const float4*>(sm + O_PEW2 + j * 16 + dq * 4);
            h[dq * 4 + 0] = fmaf(z, w.x, h[dq * 4 + 0]);
            h[dq * 4 + 1] = fmaf(z, w.y, h[dq * 4 + 1]);
            h[dq * 4 + 2] = fmaf(z, w.z, h[dq * 4 + 2]);
            h[dq * 4 + 3] = fmaf(z, w.w, h[dq * 4 + 3]);
        }
    }

    float mu = 0.f;
#pragma unroll
    for (int d = 0; d < 16; d++) { h[d] += xr[d]; mu += h[d]; }
    mu *= (1.f / 16.f);
    float var = 0.f;
#pragma unroll
    for (int d = 0; d < 16; d++) { float c = h[d] - mu; var = fmaf(c, c, var); }
    var *= (1.f / 16.f);
    const float rstd = 1.f / sqrtf(var + 1e-5f);
#pragma unroll
    for (int d = 0; d < 16; d++)
        h[d] = (h[d] - mu) * rstd * sm[O_LNG + d] + sm[O_LNB + d];

    float q[16], k[16], v[16];
#pragma unroll
    for (int d = 0; d < 16; d++) { q[d] = 0.f; k[d] = 0.f; v[d] = 0.f; }
    mat16(sm + O_QW, h, q);
    mat16(sm + O_KW, h, k);
    mat16(sm + O_VW, xr, v);

    float o[16];
#pragma unroll
    for (int hh = 0; hh < H; hh++) {
        float qh[4], kh[4], vh[4];
#pragma unroll
        for (int c = 0; c < 4; c++) {
            qh[c] = q[hh * 4 + c]; kh[c] = k[hh * 4 + c]; vh[c] = v[hh * 4 + c];
        }
        float qs = fmaf(qh[3], qh[3], fmaf(qh[2], qh[2], fmaf(qh[1], qh[1], qh[0] * qh[0])));
        float ks = fmaf(kh[3], kh[3], fmaf(kh[2], kh[2], fmaf(kh[1], kh[1], kh[0] * kh[0])));
        const float qi = 1.f / (sqrtf(qs) + 1e-6f);
        const float ki = 1.f / (sqrtf(ks) + 1e-6f);
#pragma unroll
        for (int c = 0; c < 4; c++) { qh[c] *= qi; kh[c] *= ki; }

        const float scl = sm[O_SC + hh];
        float lg[16];
#pragma unroll
        for (int j = 0; j < 16; j++) {
            float dot = 0.f;
#pragma unroll
            for (int c = 0; c < 4; c++) {
                float kj = __shfl_sync(0xffffffffu, kh[c], j, 16);
                dot = fmaf(qh[c], kj, dot);
            }
            lg[j] = dot * scl;
        }
        float mx = lg[0];
#pragma unroll
        for (int j = 1; j < 16; j++) mx = fmaxf(mx, lg[j]);
        float ssum = 0.f;
#pragma unroll
        for (int j = 0; j < 16; j++) { lg[j] = expf(lg[j] - mx); ssum += lg[j]; }
        const float inv = 1.f / ssum;
        float oh[4] = {0.f, 0.f, 0.f, 0.f};
#pragma unroll
        for (int j = 0; j < 16; j++) {
            const float a = lg[j] * inv;
#pragma unroll
            for (int c = 0; c < 4; c++) {
                float vj = __shfl_sync(0xffffffffu, vh[c], j, 16);
                oh[c] = fmaf(a, vj, oh[c]);
            }
        }
#pragma unroll
        for (int c = 0; c < 4; c++) o[hh * 4 + c] = oh[c];
    }

    float o2[16];
#pragma unroll
    for (int d = 0; d < 16; d++) o2[d] = 0.f;
    mat16(sm + O_OW, o, o2);

    float acc2 = 0.f;
#pragma unroll
    for (int j = 0; j < FFNH; j++) {
        float z = sm[O_MB1 + j];
#pragma unroll
        for (int kk = 0; kk < 16; kk++)
            z = fmaf(o2[kk], sm[O_MW1 + kk * 64 + j], z);
        acc2 = fmaf(gelu_exact(z), sm[O_MW2 + j], acc2);
    }
    const float m = gelu_exact(acc2 + sm[O_MB2]);

    float4* dst = reinterpret_cast<float4*>(g_oflat + (size_t)tok * MD + i * 16);
#pragma unroll
    for (int dq = 0; dq < 4; dq++)
        dst[dq] = make_float4(o2[dq * 4 + 0] + m, o2[dq * 4 + 1] + m,
                              o2[dq * 4 + 2] + m, o2[dq * 4 + 3] + m);
}

// ---------------------------------------------------------------------------
// K3 (fused, tf32, double-buffered DYNAMIC smem): grid = 128 x 8 colgroups,
// 2 chunks per block, one __syncthreads per kt.
// ---------------------------------------------------------------------------
__device__ __forceinline__ void mma_tf32(float* c, const uint32_t* a, const uint32_t* bb) {
    asm volatile(
        "mma.sync.aligned.m16n8k8.row.col.f32.tf32.tf32.f32 "
        "{%0,%1,%2,%3}, {%4,%5,%6,%7}, {%8,%9}, {%0,%1,%2,%3};"
        : "+f"(c[0]), "+f"(c[1]), "+f"(c[2]), "+f"(c[3])
        : "r"(a[0]), "r"(a[1]), "r"(a[2]), "r"(a[3]), "r"(bb[0]), "r"(bb[1]));
}

constexpr int APAD = 36;
constexpr int BPAD = 72;
constexpr int CPAD = 66;
constexpr int BUFU = 128 * APAD + 32 * BPAD;       // 6912 u32 per buffer
constexpr int FUSED_SMEM = 2 * BUFU * 4;           // 55296 B

__global__ __launch_bounds__(256) void fused_mlp_kernel(
    const float* __restrict__ W1, const float* __restrict__ b1,
    const float* __restrict__ W2) {
    extern __shared__ __align__(16) uint32_t smem_u[];         // 2*BUFU u32
    float* Cs  = reinterpret_cast<float*>(smem_u);             // [128][66] f32 (aliases bufs)
    float* W2s = reinterpret_cast<float*>(smem_u) + 128 * CPAD;

    const int tid  = threadIdx.x;
    const int lane = tid & 31;
    const int wid  = tid >> 5;
    const int warp_m = wid & 3;
    const int warp_n = wid >> 2;
    const int row0 = blockIdx.x * 128;
    const int cg   = blockIdx.y;

    const int a_row  = tid >> 1;
    const int a_kofs = (tid & 1) * 16;
    const int b_krow = tid >> 3;
    const int b_ncol = (tid & 7) * 8;
    const int p2row = tid >> 1;
    const int p2n   = (tid & 1) * 8;

    const float* arow_g = g_oflat + (size_t)(row0 + a_row) * MD + a_kofs;

    float out_acc[8];
#pragma unroll
    for (int i = 0; i < 8; i++) out_acc[i] = 0.f;

    for (int ch = cg * 2; ch < cg * 2 + 2; ch++) {
        const int col0 = ch * 64;
        float cfr[2][4][4];
#pragma unroll
        for (int ma = 0; ma < 2; ma++)
#pragma unroll
            for (int na = 0; na < 4; na++)
#pragma unroll
                for (int i = 0; i < 4; i++) cfr[ma][na][i] = 0.f;

#pragma unroll 1
        for (int kt = 0; kt < 8; kt++) {
            uint32_t* buf = smem_u + (kt & 1) * BUFU;
            uint32_t* As = buf;
            uint32_t* Bs = buf + 128 * APAD;

            float4 av[4], bv[2];
#pragma unroll
            for (int q = 0; q < 4; q++)
                av[q] = *reinterpret_cast<const float4*>(arow_g + kt * 32 + q * 4);
#pragma unroll
            for (int q = 0; q < 2; q++)
                bv[q] = *reinterpret_cast<const float4*>(
                    W1 + (size_t)(kt * 32 + b_krow) * FF + col0 + b_ncol + q * 4);
#pragma unroll
            for (int q = 0; q < 4; q++) {
                uint4 at = make_uint4(f2tf32(av[q].x), f2tf32(av[q].y),
                                      f2tf32(av[q].z), f2tf32(av[q].w));
                *reinterpret_cast<uint4*>(&As[a_row * APAD + a_kofs + q * 4]) = at;
            }
#pragma unroll
            for (int q = 0; q < 2; q++) {
                uint4 bt = make_uint4(f2tf32(bv[q].x), f2tf32(bv[q].y),
                                      f2tf32(bv[q].z), f2tf32(bv[q].w));
                *reinterpret_cast<uint4*>(&Bs[b_krow * BPAD + b_ncol + q * 4]) = bt;
            }
            __syncthreads();   // single barrier per kt (double-buffered)

#pragma unroll
            for (int ks = 0; ks < 4; ks++) {
                const int k0 = ks * 8;
                uint32_t afr[2][4];
#pragma unroll
                for (int ma = 0; ma < 2; ma++) {
                    const int r = warp_m * 32 + ma * 16 + (lane >> 2);
                    const int kc = k0 + (lane & 3);
                    afr[ma][0] = As[r * APAD + kc];
                    afr[ma][1] = As[(r + 8) * APAD + kc];
                    afr[ma][2] = As[r * APAD + kc + 4];
                    afr[ma][3] = As[(r + 8) * APAD + kc + 4];
                }
                uint32_t bfr[4][2];
#pragma unroll
                for (int na = 0; na < 4; na++) {
                    const int n = warp_n * 32 + na * 8 + (lane >> 2);
                    const int kc = k0 + (lane & 3);
                    bfr[na][0] = Bs[kc * BPAD + n];
                    bfr[na][1] = Bs[(kc + 4) * BPAD + n];
                }
#pragma unroll
                for (int ma = 0; ma < 2; ma++)
#pragma unroll
                    for (int na = 0; na < 4; na++)
                        mma_tf32(cfr[ma][na], afr[ma], bfr[na]);
            }
        }

        __syncthreads();   // all buffer reads done before Cs overwrite

#pragma unroll
        for (int ma = 0; ma < 2; ma++) {
            const int r0 = warp_m * 32 + ma * 16 + (lane >> 2);
#pragma unroll
            for (int na = 0; na < 4; na++) {
                const int cl = warp_n * 32 + na * 8 + 2 * (lane & 3);
                const float bb0 = __ldg(b1 + col0 + cl);
                const float bb1 = __ldg(b1 + col0 + cl + 1);
                float2 v0, v1;
                v0.x = gelu_exact(cfr[ma][na][0] + bb0);
                v0.y = gelu_exact(cfr[ma][na][1] + bb1);
                v1.x = gelu_exact(cfr[ma][na][2] + bb0);
                v1.y = gelu_exact(cfr[ma][na][3] + bb1);
                *reinterpret_cast<float2*>(&Cs[r0 * CPAD + cl]) = v0;
                *reinterpret_cast<float2*>(&Cs[(r0 + 8) * CPAD + cl]) = v1;
            }
        }
        *reinterpret_cast<float4*>(&W2s[(tid >> 2) * 16 + (tid & 3) * 4]) =
            *reinterpret_cast<const float4*>(W2 + (size_t)(col0 + (tid >> 2)) * 16 + (tid & 3) * 4);
        __syncthreads();

#pragma unroll 8
        for (int c = 0; c < 64; c++) {
            const float cv = Cs[p2row * CPAD + c];
            const float4 wa = *reinterpret_cast<const float4*>(&W2s[c * 16 + p2n]);
            const float4 wb = *reinterpret_cast<const float4*>(&W2s[c * 16 + p2n + 4]);
            out_acc[0] = fmaf(cv, wa.x, out_acc[0]);
            out_acc[1] = fmaf(cv, wa.y, out_acc[1]);
            out_acc[2] = fmaf(cv, wa.z, out_acc[2]);
            out_acc[3] = fmaf(cv, wa.w, out_acc[3]);
            out_acc[4] = fmaf(cv, wb.x, out_acc[4]);
            out_acc[5] = fmaf(cv, wb.y, out_acc[5]);
            out_acc[6] = fmaf(cv, wb.z, out_acc[6]);
            out_acc[7] = fmaf(cv, wb.w, out_acc[7]);
        }
        __syncthreads();   // phase-2 reads done before next chunk's stores
    }

    float* prow = &g_partial[cg][(size_t)(row0 + p2row) * OUT + p2n];
    *reinterpret_cast<float4*>(prow)     = make_float4(out_acc[0], out_acc[1], out_acc[2], out_acc[3]);
    *reinterpret_cast<float4*>(prow + 4) = make_float4(out_acc[4], out_acc[5], out_acc[6], out_acc[7]);
}

// ---------------------------------------------------------------------------
// K4: out = gelu(sum_cg partial + b2). Fixed summation order -> deterministic.
// ---------------------------------------------------------------------------
__global__ __launch_bounds__(256) void out_reduce(const float* __restrict__ b2,
                                                  float* __restrict__ out) {
    const int gid = blockIdx.x * 256 + threadIdx.x;
    const int n = gid & (OUT - 1);
    float s = g_partial[0][gid];
#pragma unroll
    for (int cg = 1; cg < NCG; cg++) s += g_partial[cg][gid];
    out[gid] = gelu_exact(s + b2[n]);
}

// ---------------------------------------------------------------------------
extern "C" void kernel_launch(void* const* d_in, const int* in_sizes, int n_in,
                              void* d_out, int out_size) {
    const float* x      = (const float*)d_in[0];
    const float* ct     = (const float*)d_in[1];
    const float* cs     = (const float*)d_in[2];
    const float* pe_w1  = (const float*)d_in[3];
    const float* pe_b1  = (const float*)d_in[4];
    const float* pe_w2  = (const float*)d_in[5];
    const float* pe_b2  = (const float*)d_in[6];
    const float* ln_g   = (const float*)d_in[7];
    const float* ln_b   = (const float*)d_in[8];
    const float* q_w    = (const float*)d_in[9];
    const float* k_w    = (const float*)d_in[10];
    const float* v_w    = (const float*)d_in[11];
    const float* ls     = (const float*)d_in[12];
    const float* out_w  = (const float*)d_in[13];
    const float* mnh_w1 = (const float*)d_in[14];
    const float* mnh_b1 = (const float*)d_in[15];
    const float* mnh_w2 = (const float*)d_in[16];
    const float* mnh_b2 = (const float*)d_in[17];
    const float* mo_w1  = (const float*)d_in[18];
    const float* mo_b1  = (const float*)d_in[19];
    const float* mo_w2  = (const float*)d_in[20];
    const float* mo_b2  = (const float*)d_in[21];

    // opt-in to >48KB dynamic smem (immediate host call; graph-capture-safe)
    cudaFuncSetAttribute(fused_mlp_kernel,
                         cudaFuncAttributeMaxDynamicSharedMemorySize, FUSED_SMEM);

    grid_build<<<B, 256>>>(cs);
    knn_kernel<<<dim3(T / 64, B), 128>>>(ct);
    token_kernel<<<NTOK / 16, 256>>>(x, ct, cs, pe_w1, pe_b1, pe_w2, pe_b2,
                                     ln_g, ln_b, q_w, k_w, v_w, ls, out_w,
                                     mnh_w1, mnh_b1, mnh_w2, mnh_b2);
    fused_mlp_kernel<<<dim3(NTOK / 128, NCG), 256, FUSED_SMEM>>>(mo_w1, mo_b1, mo_w2);
    out_reduce<<<NTOK * OUT / 256, 256>>>(mo_b2, (float*)d_out);
}

// round 11
// speedup vs baseline: 1.9174x; 1.0013x over previous
#include <cuda_runtime.h>
#include <math.h>
#include <stdint.h>

constexpr int B = 4, T = 4096, S = 4096, E = 16;
constexpr int NH = 16, H = 4, FFNH = 64;
constexpr int MD = 256, FF = 1024, OUT = 16;
constexpr int NTOK = B * T;
constexpr int GC = 16;                 // knn grid cells per axis
constexpr int NCG = 8;                 // fused-MLP column groups

// Scratch (static device allocations — no cudaMalloc allowed)
__device__ int    g_idx[NTOK * NH];                // 1 MB
__device__ float  g_oflat[(size_t)NTOK * MD];      // 16.8 MB (L2-resident)
__device__ float2 g_gxy[B][S];
__device__ int    g_gid[B][S];
__device__ int    g_cstart[B][GC * GC + 1];
__device__ float  g_partial[NCG][(size_t)NTOK * OUT];  // 16 MB

__device__ __forceinline__ float gelu_exact(float x) { return x * normcdff(x); }

__device__ __forceinline__ uint32_t f2tf32(float f) {
    uint32_t u;
    asm("cvt.rna.tf32.f32 %0, %1;" : "=r"(u) : "f"(f));
    return u;
}

// ---------------------------------------------------------------------------
// K0: bin sources into a 16x16 uniform grid (counting sort). One block/batch.
// ---------------------------------------------------------------------------
__global__ __launch_bounds__(256) void grid_build(const float* __restrict__ cs) {
    __shared__ int cnt[GC * GC];
    __shared__ int start[GC * GC + 1];
    const int b = blockIdx.x, tid = threadIdx.x;
    cnt[tid] = 0;
    __syncthreads();
    const float2* csb = reinterpret_cast<const float2*>(cs) + (size_t)b * S;
    for (int i = tid; i < S; i += 256) {
        float2 c = csb[i];
        int cx = min(GC - 1, (int)(c.x * GC));
        int cy = min(GC - 1, (int)(c.y * GC));
        atomicAdd(&cnt[cy * GC + cx], 1);
    }
    __syncthreads();
    if (tid == 0) {
        int acc = 0;
        for (int i = 0; i < GC * GC; i++) { start[i] = acc; acc += cnt[i]; }
        start[GC * GC] = acc;
    }
    __syncthreads();
    cnt[tid] = start[tid];
    g_cstart[b][tid] = start[tid];
    if (tid == 0) g_cstart[b][GC * GC] = start[GC * GC];
    __syncthreads();
    for (int i = tid; i < S; i += 256) {
        float2 c = csb[i];
        int cx = min(GC - 1, (int)(c.x * GC));
        int cy = min(GC - 1, (int)(c.y * GC));
        int pos = atomicAdd(&cnt[cy * GC + cx], 1);
        g_gxy[b][pos] = c;
        g_gid[b][pos] = i;
    }
}

// ---------------------------------------------------------------------------
// K1: exact 16-NN via expanding grid rings. TWO lanes per target, cells
// partitioned by (ax+ay)&1; snapshot-then-merge (race-free). Unchanged.
// ---------------------------------------------------------------------------
__global__ __launch_bounds__(128) void knn_kernel(const float* __restrict__ ct) {
    const int b = blockIdx.y;
    const int lane = threadIdx.x & 31;
    const int par = threadIdx.x & 1;
    const unsigned pairmask = 3u << (lane & ~1);
    const int t = blockIdx.x * 64 + (threadIdx.x >> 1);
    const float tx = ct[((size_t)b * T + t) * 2 + 0];
    const float ty = ct[((size_t)b * T + t) * 2 + 1];
    const int cx = min(GC - 1, (int)(tx * GC));
    const int cy = min(GC - 1, (int)(ty * GC));

    const float2* __restrict__ gxy = g_gxy[b];
    const int*    __restrict__ gid = g_gid[b];
    const int*    __restrict__ cst = g_cstart[b];
    constexpr float hcell = 1.0f / GC;
    constexpr unsigned long long KMAX = 0xFFFFFFFFFFFFFFFFull;

    unsigned long long key[NH];
#pragma unroll
    for (int i = 0; i < NH; i++) key[i] = KMAX;

    for (int rho = 0; rho <= GC - 1; rho++) {
        if (rho > 1) {
            float wl = __uint_as_float((unsigned)(key[NH - 1] >> 32));
            float wo = __shfl_xor_sync(pairmask, wl, 1);
            float wd2 = fminf(wl, wo);
            const float bound = (rho - 1) * hcell;
            if (wd2 < bound * bound) break;
        }
        const int ylo = max(cy - rho, 0), yhi = min(cy + rho, GC - 1);
        for (int ay = ylo; ay <= yhi; ay++) {
            const bool fullrow = (ay == cy - rho) || (ay == cy + rho);
            const int step = fullrow ? 1 : (rho > 0 ? 2 * rho : 1);
            for (int ax = cx - rho; ax <= cx + rho; ax += step) {
                if (ax < 0 || ax >= GC) continue;
                if (((ax + ay) & 1) != par) continue;
                const int cell = ay * GC + ax;
                const int c1 = cst[cell + 1];
                for (int j = cst[cell]; j < c1; j++) {
                    const float2 p = gxy[j];
                    const float dxx = tx - p.x, dyy = ty - p.y;
                    const float d2 = fmaf(dyy, dyy, dxx * dxx);
                    unsigned long long ck =
                        ((unsigned long long)__float_as_uint(d2) << 32) |
                        (unsigned)gid[j];
                    if (ck < key[NH - 1]) {
                        bool ins = false;
#pragma unroll
                        for (int q = 0; q < NH; q++) {
                            bool sm = ins | (ck < key[q]);
                            unsigned long long tk = key[q];
                            key[q] = sm ? ck : tk;
                            ck = sm ? tk : ck;
                            ins = sm;
                        }
                    }
                }
            }
        }
    }

    unsigned long long pk[NH];
#pragma unroll
    for (int i = 0; i < NH; i++)
        pk[i] = __shfl_xor_sync(pairmask, key[i], 1);
#pragma unroll
    for (int i = 0; i < NH; i++) {
        unsigned long long ck = pk[i];
        if (ck < key[NH - 1]) {
            bool ins = false;
#pragma unroll
            for (int q = 0; q < NH; q++) {
                bool sm = ins | (ck < key[q]);
                unsigned long long tk = key[q];
                key[q] = sm ? ck : tk;
                ck = sm ? tk : ck;
                ins = sm;
            }
        }
    }

    if (par == 0) {
        const int base = (b * T + t) * NH;
#pragma unroll
        for (int i = 0; i < NH; i++)
            g_idx[base + i] = (int)(key[i] & 0xFFFFFFFFull);
    }
}

// ---------------------------------------------------------------------------
// K2: per-token local pipeline. This round: (a) mnh MLP kk-outer float4 rows
// (1024 scalar LDS -> 256 LDS.128), (b) attention k/v staged in SMEM
// (512 SHFL -> ~136 LDS.128), (c) PE scalar loads vectorized. All FP
// accumulation orders preserved -> bit-identical output.
// ---------------------------------------------------------------------------
constexpr int O_PEW1 = 0;
constexpr int O_PEB1 = 128;
constexpr int O_PEW2 = 192;
constexpr int O_PEB2 = 1216;
constexpr int O_LNG  = 1232;
constexpr int O_LNB  = 1248;
constexpr int O_QW   = 1264;
constexpr int O_KW   = 1520;
constexpr int O_VW   = 1776;
constexpr int O_OW   = 2032;
constexpr int O_MW1  = 2288;
constexpr int O_MB1  = 3312;
constexpr int O_MW2  = 3376;
constexpr int O_MB2  = 3440;
constexpr int O_SC   = 3444;   // 16B-aligned
constexpr int O_KV   = 3448;   // 16B-aligned; 16 groups * 132 floats
constexpr int SM_TOT = 3448 + 16 * 132;

__device__ __forceinline__ void mat16(const float* __restrict__ Wsh,
                                      const float* __restrict__ vin,
                                      float* __restrict__ vout) {
#pragma unroll
    for (int k = 0; k < 16; k++) {
        const float hv = vin[k];
#pragma unroll
        for (int dq = 0; dq < 4; dq++) {
            float4 w = *reinterpret_cast<const float4*>(Wsh + k * 16 + dq * 4);
            vout[dq * 4 + 0] = fmaf(hv, w.x, vout[dq * 4 + 0]);
            vout[dq * 4 + 1] = fmaf(hv, w.y, vout[dq * 4 + 1]);
            vout[dq * 4 + 2] = fmaf(hv, w.z, vout[dq * 4 + 2]);
            vout[dq * 4 + 3] = fmaf(hv, w.w, vout[dq * 4 + 3]);
        }
    }
}

__global__ __launch_bounds__(256) void token_kernel(
    const float* __restrict__ x, const float* __restrict__ ct, const float* __restrict__ cs,
    const float* __restrict__ pe_w1, const float* __restrict__ pe_b1,
    const float* __restrict__ pe_w2, const float* __restrict__ pe_b2,
    const float* __restrict__ ln_g, const float* __restrict__ ln_b,
    const float* __restrict__ q_w, const float* __restrict__ k_w,
    const float* __restrict__ v_w, const float* __restrict__ lscale,
    const float* __restrict__ out_w,
    const float* __restrict__ mnh_w1, const float* __restrict__ mnh_b1,
    const float* __restrict__ mnh_w2, const float* __restrict__ mnh_b2) {
    __shared__ float sm[SM_TOT];
    const int tid = threadIdx.x;
    for (int i = tid; i < 128;  i += 256) sm[O_PEW1 + i] = pe_w1[i];
    for (int i = tid; i < 64;   i += 256) sm[O_PEB1 + i] = pe_b1[i];
    for (int i = tid; i < 1024; i += 256) sm[O_PEW2 + i] = pe_w2[i];
    for (int i = tid; i < 16;   i += 256) sm[O_PEB2 + i] = pe_b2[i];
    for (int i = tid; i < 16;   i += 256) sm[O_LNG + i]  = ln_g[i];
    for (int i = tid; i < 16;   i += 256) sm[O_LNB + i]  = ln_b[i];
    for (int i = tid; i < 256;  i += 256) sm[O_QW + i]   = q_w[i];
    for (int i = tid; i < 256;  i += 256) sm[O_KW + i]   = k_w[i];
    for (int i = tid; i < 256;  i += 256) sm[O_VW + i]   = v_w[i];
    for (int i = tid; i < 256;  i += 256) sm[O_OW + i]   = out_w[i];
    for (int i = tid; i < 1024; i += 256) sm[O_MW1 + i]  = mnh_w1[i];
    for (int i = tid; i < 64;   i += 256) sm[O_MB1 + i]  = mnh_b1[i];
    for (int i = tid; i < 64;   i += 256) sm[O_MW2 + i]  = mnh_w2[i];
    if (tid == 0) sm[O_MB2] = mnh_b2[0];
    if (tid < 4)  sm[O_SC + tid] = expf(fminf(lscale[tid], 4.6051702f));
    __syncthreads();

    const int tok = blockIdx.x * 16 + (tid >> 4);
    const int g   = tid >> 4;                       // token group in block
    const int i   = tid & 15;                       // neighbor slot
    const int b   = tok / T;
    const int nidx = g_idx[tok * NH + i];

    float xr[16];
    const float4* xrow = reinterpret_cast<const float4*>(x + ((size_t)b * S + nidx) * E);
#pragma unroll
    for (int q4 = 0; q4 < 4; q4++) {
        float4 v4 = __ldg(xrow + q4);
        xr[q4 * 4 + 0] = v4.x; xr[q4 * 4 + 1] = v4.y;
        xr[q4 * 4 + 2] = v4.z; xr[q4 * 4 + 3] = v4.w;
    }
    const float2 scoord = __ldg(reinterpret_cast<const float2*>(cs) + (size_t)b * S + nidx);
    const float2 tcoord = __ldg(reinterpret_cast<const float2*>(ct) + tok);
    const float c0 = scoord.x - tcoord.x, c1 = scoord.y - tcoord.y;

    // positional-embedding MLP -> h (j ascending, same FP order)
    float h[16];
#pragma unroll
    for (int d = 0; d < 16; d++) h[d] = sm[O_PEB2 + d];
#pragma unroll
    for (int j4 = 0; j4 < FFNH; j4 += 4) {
        const float4 wa = *reinterpret_cast<const float4*>(sm + O_PEW1 + j4);
        const float4 wb = *reinterpret_cast<const float4*>(sm + O_PEW1 + 64 + j4);
        const float4 bb = *reinterpret_cast<const float4*>(sm + O_PEB1 + j4);
        float zq[4];
        zq[0] = fmaf(c0, wa.x, fmaf(c1, wb.x, bb.x));
        zq[1] = fmaf(c0, wa.y, fmaf(c1, wb.y, bb.y));
        zq[2] = fmaf(c0, wa.z, fmaf(c1, wb.z, bb.z));
        zq[3] = fmaf(c0, wa.w, fmaf(c1, wb.w, bb.w));
#pragma unroll
        for (int s = 0; s < 4; s++) {
            const float z = gelu_exact(zq[s]);
            const int j = j4 + s;
#pragma unroll
            for (int dq = 0; dq < 4; dq++) {
                float4 w = *reinterpret_cast<const float4*>(sm + O_PEW2 + j * 16 + dq * 4);
                h[dq * 4 + 0] = fmaf(z, w.x, h[dq * 4 + 0]);
                h[dq * 4 + 1] = fmaf(z, w.y, h[dq * 4 + 1]);
                h[dq * 4 + 2] = fmaf(z, w.z, h[dq * 4 + 2]);
                h[dq * 4 + 3] = fmaf(z, w.w, h[dq * 4 + 3]);
            }
        }
    }

    // residual + LayerNorm
    float mu = 0.f;
#pragma unroll
    for (int d = 0; d < 16; d++) { h[d] += xr[d]; mu += h[d]; }
    mu *= (1.f / 16.f);
    float var = 0.f;
#pragma unroll
    for (int d = 0; d < 16; d++) { float c = h[d] - mu; var = fmaf(c, c, var); }
    var *= (1.f / 16.f);
    const float rstd = 1.f / sqrtf(var + 1e-5f);
#pragma unroll
    for (int d = 0; d < 16; d++)
        h[d] = (h[d] - mu) * rstd * sm[O_LNG + d] + sm[O_LNB + d];

    float q[16], k[16], v[16];
#pragma unroll
    for (int d = 0; d < 16; d++) { q[d] = 0.f; k[d] = 0.f; v[d] = 0.f; }
    mat16(sm + O_QW, h, q);
    mat16(sm + O_KW, h, k);
    mat16(sm + O_VW, xr, v);

    // cosine attention; k/v staged per head in SMEM (group-padded stride)
    float4* myslot = reinterpret_cast<float4*>(sm + O_KV + g * 132 + i * 8);
    float o[16];
#pragma unroll
    for (int hh = 0; hh < H; hh++) {
        float qh[4], kh[4], vh[4];
#pragma unroll
        for (int c = 0; c < 4; c++) {
            qh[c] = q[hh * 4 + c]; kh[c] = k[hh * 4 + c]; vh[c] = v[hh * 4 + c];
        }
        float qs = fmaf(qh[3], qh[3], fmaf(qh[2], qh[2], fmaf(qh[1], qh[1], qh[0] * qh[0])));
        float ks = fmaf(kh[3], kh[3], fmaf(kh[2], kh[2], fmaf(kh[1], kh[1], kh[0] * kh[0])));
        const float qi = 1.f / (sqrtf(qs) + 1e-6f);
        const float ki = 1.f / (sqrtf(ks) + 1e-6f);
#pragma unroll
        for (int c = 0; c < 4; c++) { qh[c] *= qi; kh[c] *= ki; }

        __syncwarp();                                 // prior head's reads done
        myslot[0] = make_float4(kh[0], kh[1], kh[2], kh[3]);
        myslot[1] = make_float4(vh[0], vh[1], vh[2], vh[3]);
        __syncwarp();                                 // stores visible

        const float scl = sm[O_SC + hh];
        float lg[16];
#pragma unroll
        for (int j = 0; j < 16; j++) {
            const float4 kj = *reinterpret_cast<const float4*>(sm + O_KV + g * 132 + j * 8);
            float dot = 0.f;
            dot = fmaf(qh[0], kj.x, dot);
            dot = fmaf(qh[1], kj.y, dot);
            dot = fmaf(qh[2], kj.z, dot);
            dot = fmaf(qh[3], kj.w, dot);
            lg[j] = dot * scl;
        }
        float mx = lg[0];
#pragma unroll
        for (int j = 1; j < 16; j++) mx = fmaxf(mx, lg[j]);
        float ssum = 0.f;
#pragma unroll
        for (int j = 0; j < 16; j++) { lg[j] = expf(lg[j] - mx); ssum += lg[j]; }
        const float inv = 1.f / ssum;
        float oh[4] = {0.f, 0.f, 0.f, 0.f};
#pragma unroll
        for (int j = 0; j < 16; j++) {
            const float a = lg[j] * inv;
            const float4 vj = *reinterpret_cast<const float4*>(sm + O_KV + g * 132 + j * 8 + 4);
            oh[0] = fmaf(a, vj.x, oh[0]);
            oh[1] = fmaf(a, vj.y, oh[1]);
            oh[2] = fmaf(a, vj.z, oh[2]);
            oh[3] = fmaf(a, vj.w, oh[3]);
        }
#pragma unroll
        for (int c = 0; c < 4; c++) o[hh * 4 + c] = oh[c];
    }

    // attention out-projection
    float o2[16];
#pragma unroll
    for (int d = 0; d < 16; d++) o2[d] = 0.f;
    mat16(sm + O_OW, o, o2);

    // per-neighbor MLP: kk-outer, float4 rows of mnh_w1 (same FP order)
    float acc2 = 0.f;
#pragma unroll
    for (int jc = 0; jc < 2; jc++) {
        float z[32];
#pragma unroll
        for (int jq = 0; jq < 8; jq++) {
            const float4 bb = *reinterpret_cast<const float4*>(sm + O_MB1 + jc * 32 + jq * 4);
            z[jq * 4 + 0] = bb.x; z[jq * 4 + 1] = bb.y;
            z[jq * 4 + 2] = bb.z; z[jq * 4 + 3] = bb.w;
        }
#pragma unroll
        for (int kk = 0; kk < 16; kk++) {
            const float ov = o2[kk];
#pragma unroll
            for (int jq = 0; jq < 8; jq++) {
                const float4 w = *reinterpret_cast<const float4*>(
                    sm + O_MW1 + kk * 64 + jc * 32 + jq * 4);
                z[jq * 4 + 0] = fmaf(ov, w.x, z[jq * 4 + 0]);
                z[jq * 4 + 1] = fmaf(ov, w.y, z[jq * 4 + 1]);
                z[jq * 4 + 2] = fmaf(ov, w.z, z[jq * 4 + 2]);
                z[jq * 4 + 3] = fmaf(ov, w.w, z[jq * 4 + 3]);
            }
        }
#pragma unroll
        for (int j = 0; j < 32; j++)
            acc2 = fmaf(gelu_exact(z[j]), sm[O_MW2 + jc * 32 + j], acc2);
    }
    const float m = gelu_exact(acc2 + sm[O_MB2]);

    float4* dst = reinterpret_cast<float4*>(g_oflat + (size_t)tok * MD + i * 16);
#pragma unroll
    for (int dq = 0; dq < 4; dq++)
        dst[dq] = make_float4(o2[dq * 4 + 0] + m, o2[dq * 4 + 1] + m,
                              o2[dq * 4 + 2] + m, o2[dq * 4 + 3] + m);
}

// ---------------------------------------------------------------------------
// K3 (fused, tf32, double-buffered dynamic smem): unchanged (passing).
// ---------------------------------------------------------------------------
__device__ __forceinline__ void mma_tf32(float* c, const uint32_t* a, const uint32_t* bb) {
    asm volatile(
        "mma.sync.aligned.m16n8k8.row.col.f32.tf32.tf32.f32 "
        "{%0,%1,%2,%3}, {%4,%5,%6,%7}, {%8,%9}, {%0,%1,%2,%3};"
        : "+f"(c[0]), "+f"(c[1]), "+f"(c[2]), "+f"(c[3])
        : "r"(a[0]), "r"(a[1]), "r"(a[2]), "r"(a[3]), "r"(bb[0]), "r"(bb[1]));
}

constexpr int APAD = 36;
constexpr int BPAD = 72;
constexpr int CPAD = 66;
constexpr int BUFU = 128 * APAD + 32 * BPAD;       // 6912 u32 per buffer
constexpr int FUSED_SMEM = 2 * BUFU * 4;           // 55296 B

__global__ __launch_bounds__(256) void fused_mlp_kernel(
    const float* __restrict__ W1, const float* __restrict__ b1,
    const float* __restrict__ W2) {
    extern __shared__ __align__(16) uint32_t smem_u[];
    float* Cs  = reinterpret_cast<float*>(smem_u);
    float* W2s = reinterpret_cast<float*>(smem_u) + 128 * CPAD;

    const int tid  = threadIdx.x;
    const int lane = tid & 31;
    const int wid  = tid >> 5;
    const int warp_m = wid & 3;
    const int warp_n = wid >> 2;
    const int row0 = blockIdx.x * 128;
    const int cg   = blockIdx.y;

    const int a_row  = tid >> 1;
    const int a_kofs = (tid & 1) * 16;
    const int b_krow = tid >> 3;
    const int b_ncol = (tid & 7) * 8;
    const int p2row = tid >> 1;
    const int p2n   = (tid & 1) * 8;

    const float* arow_g = g_oflat + (size_t)(row0 + a_row) * MD + a_kofs;

    float out_acc[8];
#pragma unroll
    for (int i = 0; i < 8; i++) out_acc[i] = 0.f;

    for (int ch = cg * 2; ch < cg * 2 + 2; ch++) {
        const int col0 = ch * 64;
        float cfr[2][4][4];
#pragma unroll
        for (int ma = 0; ma < 2; ma++)
#pragma unroll
            for (int na = 0; na < 4; na++)
#pragma unroll
                for (int i = 0; i < 4; i++) cfr[ma][na][i] = 0.f;

#pragma unroll 1
        for (int kt = 0; kt < 8; kt++) {
            uint32_t* buf = smem_u + (kt & 1) * BUFU;
            uint32_t* As = buf;
            uint32_t* Bs = buf + 128 * APAD;

            float4 av[4], bv[2];
#pragma unroll
            for (int q = 0; q < 4; q++)
                av[q] = *reinterpret_cast<const float4*>(arow_g + kt * 32 + q * 4);
#pragma unroll
            for (int q = 0; q < 2; q++)
                bv[q] = *reinterpret_cast<const float4*>(
                    W1 + (size_t)(kt * 32 + b_krow) * FF + col0 + b_ncol + q * 4);
#pragma unroll
            for (int q = 0; q < 4; q++) {
                uint4 at = make_uint4(f2tf32(av[q].x), f2tf32(av[q].y),
                                      f2tf32(av[q].z), f2tf32(av[q].w));
                *reinterpret_cast<uint4*>(&As[a_row * APAD + a_kofs + q * 4]) = at;
            }
#pragma unroll
            for (int q = 0; q < 2; q++) {
                uint4 bt = make_uint4(f2tf32(bv[q].x), f2tf32(bv[q].y),
                                      f2tf32(bv[q].z), f2tf32(bv[q].w));
                *reinterpret_cast<uint4*>(&Bs[b_krow * BPAD + b_ncol + q * 4]) = bt;
            }
            __syncthreads();

#pragma unroll
            for (int ks = 0; ks < 4; ks++) {
                const int k0 = ks * 8;
                uint32_t afr[2][4];
#pragma unroll
                for (int ma = 0; ma < 2; ma++) {
                    const int r = warp_m * 32 + ma * 16 + (lane >> 2);
                    const int kc = k0 + (lane & 3);
                    afr[ma][0] = As[r * APAD + kc];
                    afr[ma][1] = As[(r + 8) * APAD + kc];
                    afr[ma][2] = As[r * APAD + kc + 4];
                    afr[ma][3] = As[(r + 8) * APAD + kc + 4];
                }
                uint32_t bfr[4][2];
#pragma unroll
                for (int na = 0; na < 4; na++) {
                    const int n = warp_n * 32 + na * 8 + (lane >> 2);
                    const int kc = k0 + (lane & 3);
                    bfr[na][0] = Bs[kc * BPAD + n];
                    bfr[na][1] = Bs[(kc + 4) * BPAD + n];
                }
#pragma unroll
                for (int ma = 0; ma < 2; ma++)
#pragma unroll
                    for (int na = 0; na < 4; na++)
                        mma_tf32(cfr[ma][na], afr[ma], bfr[na]);
            }
        }

        __syncthreads();

#pragma unroll
        for (int ma = 0; ma < 2; ma++) {
            const int r0 = warp_m * 32 + ma * 16 + (lane >> 2);
#pragma unroll
            for (int na = 0; na < 4; na++) {
                const int cl = warp_n * 32 + na * 8 + 2 * (lane & 3);
                const float bb0 = __ldg(b1 + col0 + cl);
                const float bb1 = __ldg(b1 + col0 + cl + 1);
                float2 v0, v1;
                v0.x = gelu_exact(cfr[ma][na][0] + bb0);
                v0.y = gelu_exact(cfr[ma][na][1] + bb1);
                v1.x = gelu_exact(cfr[ma][na][2] + bb0);
                v1.y = gelu_exact(cfr[ma][na][3] + bb1);
                *reinterpret_cast<float2*>(&Cs[r0 * CPAD + cl]) = v0;
                *reinterpret_cast<float2*>(&Cs[(r0 + 8) * CPAD + cl]) = v1;
            }
        }
        *reinterpret_cast<float4*>(&W2s[(tid >> 2) * 16 + (tid & 3) * 4]) =
            *reinterpret_cast<const float4*>(W2 + (size_t)(col0 + (tid >> 2)) * 16 + (tid & 3) * 4);
        __syncthreads();

#pragma unroll 8
        for (int c = 0; c < 64; c++) {
            const float cv = Cs[p2row * CPAD + c];
            const float4 wa = *reinterpret_cast<const float4*>(&W2s[c * 16 + p2n]);
            const float4 wb = *reinterpret_cast<const float4*>(&W2s[c * 16 + p2n + 4]);
            out_acc[0] = fmaf(cv, wa.x, out_acc[0]);
            out_acc[1] = fmaf(cv, wa.y, out_acc[1]);
            out_acc[2] = fmaf(cv, wa.z, out_acc[2]);
            out_acc[3] = fmaf(cv, wa.w, out_acc[3]);
            out_acc[4] = fmaf(cv, wb.x, out_acc[4]);
            out_acc[5] = fmaf(cv, wb.y, out_acc[5]);
            out_acc[6] = fmaf(cv, wb.z, out_acc[6]);
            out_acc[7] = fmaf(cv, wb.w, out_acc[7]);
        }
        __syncthreads();
    }

    float* prow = &g_partial[cg][(size_t)(row0 + p2row) * OUT + p2n];
    *reinterpret_cast<float4*>(prow)     = make_float4(out_acc[0], out_acc[1], out_acc[2], out_acc[3]);
    *reinterpret_cast<float4*>(prow + 4) = make_float4(out_acc[4], out_acc[5], out_acc[6], out_acc[7]);
}

// ---------------------------------------------------------------------------
// K4: out = gelu(sum_cg partial + b2). Fixed summation order -> deterministic.
// ---------------------------------------------------------------------------
__global__ __launch_bounds__(256) void out_reduce(const float* __restrict__ b2,
                                                  float* __restrict__ out) {
    const int gid = blockIdx.x * 256 + threadIdx.x;
    const int n = gid & (OUT - 1);
    float s = g_partial[0][gid];
#pragma unroll
    for (int cg = 1; cg < NCG; cg++) s += g_partial[cg][gid];
    out[gid] = gelu_exact(s + b2[n]);
}

// ---------------------------------------------------------------------------
extern "C" void kernel_launch(void* const* d_in, const int* in_sizes, int n_in,
                              void* d_out, int out_size) {
    const float* x      = (const float*)d_in[0];
    const float* ct     = (const float*)d_in[1];
    const float* cs     = (const float*)d_in[2];
    const float* pe_w1  = (const float*)d_in[3];
    const float* pe_b1  = (const float*)d_in[4];
    const float* pe_w2  = (const float*)d_in[5];
    const float* pe_b2  = (const float*)d_in[6];
    const float* ln_g   = (const float*)d_in[7];
    const float* ln_b   = (const float*)d_in[8];
    const float* q_w    = (const float*)d_in[9];
    const float* k_w    = (const float*)d_in[10];
    const float* v_w    = (const float*)d_in[11];
    const float* ls     = (const float*)d_in[12];
    const float* out_w  = (const float*)d_in[13];
    const float* mnh_w1 = (const float*)d_in[14];
    const float* mnh_b1 = (const float*)d_in[15];
    const float* mnh_w2 = (const float*)d_in[16];
    const float* mnh_b2 = (const float*)d_in[17];
    const float* mo_w1  = (const float*)d_in[18];
    const float* mo_b1  = (const float*)d_in[19];
    const float* mo_w2  = (const float*)d_in[20];
    const float* mo_b2  = (const float*)d_in[21];

    cudaFuncSetAttribute(fused_mlp_kernel,
                         cudaFuncAttributeMaxDynamicSharedMemorySize, FUSED_SMEM);

    grid_build<<<B, 256>>>(cs);
    knn_kernel<<<dim3(T / 64, B), 128>>>(ct);
    token_kernel<<<NTOK / 16, 256>>>(x, ct, cs, pe_w1, pe_b1, pe_w2, pe_b2,
                                     ln_g, ln_b, q_w, k_w, v_w, ls, out_w,
                                     mnh_w1, mnh_b1, mnh_w2, mnh_b2);
    fused_mlp_kernel<<<dim3(NTOK / 128, NCG), 256, FUSED_SMEM>>>(mo_w1, mo_b1, mo_w2);
    out_reduce<<<NTOK * OUT / 256, 256>>>(mo_b2, (float*)d_out);
}

// round 13
// speedup vs baseline: 1.9742x; 1.0296x over previous
#include <cuda_runtime.h>
#include <math.h>
#include <stdint.h>

constexpr int B = 4, T = 4096, S = 4096, E = 16;
constexpr int NH = 16, H = 4, FFNH = 64;
constexpr int MD = 256, FF = 1024, OUT = 16;
constexpr int NTOK = B * T;
constexpr int GC = 16;                 // knn grid cells per axis
constexpr int NCG = 8;                 // fused-MLP column groups

// Scratch (static device allocations — no cudaMalloc allowed)
__device__ int    g_idx[NTOK * NH];                // 1 MB
__device__ float  g_oflat[(size_t)NTOK * MD];      // 16.8 MB (L2-resident)
__device__ float2 g_gxy[B][S];
__device__ int    g_gid[B][S];
__device__ int    g_cstart[B][GC * GC + 1];
__device__ float2 g_txy[B][T];                     // spatially-sorted targets
__device__ int    g_tid_[B][T];
__device__ float  g_partial[NCG][(size_t)NTOK * OUT];

__device__ __forceinline__ float gelu_exact(float x) { return x * normcdff(x); }

__device__ __forceinline__ void cp_async16(uint32_t dst, const void* src) {
    asm volatile("cp.async.cg.shared.global [%0], [%1], 16;\n" :: "r"(dst), "l"(src));
}
__device__ __forceinline__ void cp_commit() {
    asm volatile("cp.async.commit_group;\n" ::);
}
__device__ __forceinline__ void cp_wait1() {
    asm volatile("cp.async.wait_group 1;\n" ::);
}

// ---------------------------------------------------------------------------
// K0a/K0b: counting-sort sources AND targets into the 16x16 grid.
// ---------------------------------------------------------------------------
__global__ __launch_bounds__(256) void grid_build(const float* __restrict__ cs) {
    __shared__ int cnt[GC * GC];
    __shared__ int start[GC * GC + 1];
    const int b = blockIdx.x, tid = threadIdx.x;
    cnt[tid] = 0;
    __syncthreads();
    const float2* csb = reinterpret_cast<const float2*>(cs) + (size_t)b * S;
    for (int i = tid; i < S; i += 256) {
        float2 c = csb[i];
        int cx = min(GC - 1, (int)(c.x * GC));
        int cy = min(GC - 1, (int)(c.y * GC));
        atomicAdd(&cnt[cy * GC + cx], 1);
    }
    __syncthreads();
    if (tid == 0) {
        int acc = 0;
        for (int i = 0; i < GC * GC; i++) { start[i] = acc; acc += cnt[i]; }
        start[GC * GC] = acc;
    }
    __syncthreads();
    cnt[tid] = start[tid];
    g_cstart[b][tid] = start[tid];
    if (tid == 0) g_cstart[b][GC * GC] = start[GC * GC];
    __syncthreads();
    for (int i = tid; i < S; i += 256) {
        float2 c = csb[i];
        int cx = min(GC - 1, (int)(c.x * GC));
        int cy = min(GC - 1, (int)(c.y * GC));
        int pos = atomicAdd(&cnt[cy * GC + cx], 1);
        g_gxy[b][pos] = c;
        g_gid[b][pos] = i;
    }
}

__global__ __launch_bounds__(256) void grid_build_t(const float* __restrict__ ct) {
    __shared__ int cnt[GC * GC];
    __shared__ int start[GC * GC + 1];
    const int b = blockIdx.x, tid = threadIdx.x;
    cnt[tid] = 0;
    __syncthreads();
    const float2* ctb = reinterpret_cast<const float2*>(ct) + (size_t)b * T;
    for (int i = tid; i < T; i += 256) {
        float2 c = ctb[i];
        int cx = min(GC - 1, (int)(c.x * GC));
        int cy = min(GC - 1, (int)(c.y * GC));
        atomicAdd(&cnt[cy * GC + cx], 1);
    }
    __syncthreads();
    if (tid == 0) {
        int acc = 0;
        for (int i = 0; i < GC * GC; i++) { start[i] = acc; acc += cnt[i]; }
        start[GC * GC] = acc;
    }
    __syncthreads();
    cnt[tid] = start[tid];
    __syncthreads();
    for (int i = tid; i < T; i += 256) {
        float2 c = ctb[i];
        int cx = min(GC - 1, (int)(c.x * GC));
        int cy = min(GC - 1, (int)(c.y * GC));
        int pos = atomicAdd(&cnt[cy * GC + cx], 1);
        g_txy[b][pos] = c;
        g_tid_[b][pos] = i;
    }
}

// ---------------------------------------------------------------------------
// K1: exact 16-NN via expanding grid rings, over SPATIALLY SORTED targets
// (warp-coherent cells/trip-counts). TWO lanes per target, parity split;
// snapshot-then-merge. Output scattered to original target index.
// ---------------------------------------------------------------------------
__global__ __launch_bounds__(128) void knn_kernel() {
    const int b = blockIdx.y;
    const int lane = threadIdx.x & 31;
    const int par = threadIdx.x & 1;
    const unsigned pairmask = 3u << (lane & ~1);
    const int s = blockIdx.x * 64 + (threadIdx.x >> 1);   // sorted slot
    const float2 tc = g_txy[b][s];
    const int torig = g_tid_[b][s];
    const float tx = tc.x, ty = tc.y;
    const int cx = min(GC - 1, (int)(tx * GC));
    const int cy = min(GC - 1, (int)(ty * GC));

    const float2* __restrict__ gxy = g_gxy[b];
    const int*    __restrict__ gid = g_gid[b];
    const int*    __restrict__ cst = g_cstart[b];
    constexpr float hcell = 1.0f / GC;
    constexpr unsigned long long KMAX = 0xFFFFFFFFFFFFFFFFull;

    unsigned long long key[NH];
#pragma unroll
    for (int i = 0; i < NH; i++) key[i] = KMAX;

    for (int rho = 0; rho <= GC - 1; rho++) {
        if (rho > 1) {
            float wl = __uint_as_float((unsigned)(key[NH - 1] >> 32));
            float wo = __shfl_xor_sync(pairmask, wl, 1);
            float wd2 = fminf(wl, wo);
            const float bound = (rho - 1) * hcell;
            if (wd2 < bound * bound) break;
        }
        const int ylo = max(cy - rho, 0), yhi = min(cy + rho, GC - 1);
        for (int ay = ylo; ay <= yhi; ay++) {
            const bool fullrow = (ay == cy - rho) || (ay == cy + rho);
            const int step = fullrow ? 1 : (rho > 0 ? 2 * rho : 1);
            for (int ax = cx - rho; ax <= cx + rho; ax += step) {
                if (ax < 0 || ax >= GC) continue;
                if (((ax + ay) & 1) != par) continue;
                const int cell = ay * GC + ax;
                const int c1 = cst[cell + 1];
                for (int j = cst[cell]; j < c1; j++) {
                    const float2 p = gxy[j];
                    const float dxx = tx - p.x, dyy = ty - p.y;
                    const float d2 = fmaf(dyy, dyy, dxx * dxx);
                    unsigned long long ck =
                        ((unsigned long long)__float_as_uint(d2) << 32) |
                        (unsigned)gid[j];
                    if (ck < key[NH - 1]) {
                        bool ins = false;
#pragma unroll
                        for (int q = 0; q < NH; q++) {
                            bool sm = ins | (ck < key[q]);
                            unsigned long long tk = key[q];
                            key[q] = sm ? ck : tk;
                            ck = sm ? tk : ck;
                            ins = sm;
                        }
                    }
                }
            }
        }
    }

    unsigned long long pk[NH];
#pragma unroll
    for (int i = 0; i < NH; i++)
        pk[i] = __shfl_xor_sync(pairmask, key[i], 1);
#pragma unroll
    for (int i = 0; i < NH; i++) {
        unsigned long long ck = pk[i];
        if (ck < key[NH - 1]) {
            bool ins = false;
#pragma unroll
            for (int q = 0; q < NH; q++) {
                bool sm = ins | (ck < key[q]);
                unsigned long long tk = key[q];
                key[q] = sm ? ck : tk;
                ck = sm ? tk : ck;
                ins = sm;
            }
        }
    }

    if (par == 0) {
        const int base = (b * T + torig) * NH;
#pragma unroll
        for (int i = 0; i < NH; i++)
            g_idx[base + i] = (int)(key[i] & 0xFFFFFFFFull);
    }
}

// ---------------------------------------------------------------------------
// K2: per-token local pipeline (unchanged from R11, passing).
// ---------------------------------------------------------------------------
constexpr int O_PEW1 = 0;
constexpr int O_PEB1 = 128;
constexpr int O_PEW2 = 192;
constexpr int O_PEB2 = 1216;
constexpr int O_LNG  = 1232;
constexpr int O_LNB  = 1248;
constexpr int O_QW   = 1264;
constexpr int O_KW   = 1520;
constexpr int O_VW   = 1776;
constexpr int O_OW   = 2032;
constexpr int O_MW1  = 2288;
constexpr int O_MB1  = 3312;
constexpr int O_MW2  = 3376;
constexpr int O_MB2  = 3440;
constexpr int O_SC   = 3444;
constexpr int O_KV   = 3448;
constexpr int SM_TOT = 3448 + 16 * 132;

__device__ __forceinline__ void mat16(const float* __restrict__ Wsh,
                                      const float* __restrict__ vin,
                                      float* __restrict__ vout) {
#pragma unroll
    for (int k = 0; k < 16; k++) {
        const float hv = vin[k];
#pragma unroll
        for (int dq = 0; dq < 4; dq++) {
            float4 w = *reinterpret_cast<const float4*>(Wsh + k * 16 + dq * 4);
            vout[dq * 4 + 0] = fmaf(hv, w.x, vout[dq * 4 + 0]);
            vout[dq * 4 + 1] = fmaf(hv, w.y, vout[dq * 4 + 1]);
            vout[dq * 4 + 2] = fmaf(hv, w.z, vout[dq * 4 + 2]);
            vout[dq * 4 + 3] = fmaf(hv, w.w, vout[dq * 4 + 3]);
        }
    }
}

__global__ __launch_bounds__(256) void token_kernel(
    const float* __restrict__ x, const float* __restrict__ ct, const float* __restrict__ cs,
    const float* __restrict__ pe_w1, const float* __restrict__ pe_b1,
    const float* __restrict__ pe_w2, const float* __restrict__ pe_b2,
    const float* __restrict__ ln_g, const float* __restrict__ ln_b,
    const float* __restrict__ q_w, const float* __restrict__ k_w,
    const float* __restrict__ v_w, const float* __restrict__ lscale,
    const float* __restrict__ out_w,
    const float* __restrict__ mnh_w1, const float* __restrict__ mnh_b1,
    const float* __restrict__ mnh_w2, const float* __restrict__ mnh_b2) {
    __shared__ float sm[SM_TOT];
    const int tid = threadIdx.x;
    for (int i = tid; i < 128;  i += 256) sm[O_PEW1 + i] = pe_w1[i];
    for (int i = tid; i < 64;   i += 256) sm[O_PEB1 + i] = pe_b1[i];
    for (int i = tid; i < 1024; i += 256) sm[O_PEW2 + i] = pe_w2[i];
    for (int i = tid; i < 16;   i += 256) sm[O_PEB2 + i] = pe_b2[i];
    for (int i = tid; i < 16;   i += 256) sm[O_LNG + i]  = ln_g[i];
    for (int i = tid; i < 16;   i += 256) sm[O_LNB + i]  = ln_b[i];
    for (int i = tid; i < 256;  i += 256) sm[O_QW + i]   = q_w[i];
    for (int i = tid; i < 256;  i += 256) sm[O_KW + i]   = k_w[i];
    for (int i = tid; i < 256;  i += 256) sm[O_VW + i]   = v_w[i];
    for (int i = tid; i < 256;  i += 256) sm[O_OW + i]   = out_w[i];
    for (int i = tid; i < 1024; i += 256) sm[O_MW1 + i]  = mnh_w1[i];
    for (int i = tid; i < 64;   i += 256) sm[O_MB1 + i]  = mnh_b1[i];
    for (int i = tid; i < 64;   i += 256) sm[O_MW2 + i]  = mnh_w2[i];
    if (tid == 0) sm[O_MB2] = mnh_b2[0];
    if (tid < 4)  sm[O_SC + tid] = expf(fminf(lscale[tid], 4.6051702f));
    __syncthreads();

    const int tok = blockIdx.x * 16 + (tid >> 4);
    const int g   = tid >> 4;
    const int i   = tid & 15;
    const int b   = tok / T;
    const int nidx = g_idx[tok * NH + i];

    float xr[16];
    const float4* xrow = reinterpret_cast<const float4*>(x + ((size_t)b * S + nidx) * E);
#pragma unroll
    for (int q4 = 0; q4 < 4; q4++) {
        float4 v4 = __ldg(xrow + q4);
        xr[q4 * 4 + 0] = v4.x; xr[q4 * 4 + 1] = v4.y;
        xr[q4 * 4 + 2] = v4.z; xr[q4 * 4 + 3] = v4.w;
    }
    const float2 scoord = __ldg(reinterpret_cast<const float2*>(cs) + (size_t)b * S + nidx);
    const float2 tcoord = __ldg(reinterpret_cast<const float2*>(ct) + tok);
    const float c0 = scoord.x - tcoord.x, c1 = scoord.y - tcoord.y;

    float h[16];
#pragma unroll
    for (int d = 0; d < 16; d++) h[d] = sm[O_PEB2 + d];
#pragma unroll
    for (int j4 = 0; j4 < FFNH; j4 += 4) {
        const float4 wa = *reinterpret_cast<const float4*>(sm + O_PEW1 + j4);
        const float4 wb = *reinterpret_cast<const float4*>(sm + O_PEW1 + 64 + j4);
        const float4 bb = *reinterpret_cast<const float4*>(sm + O_PEB1 + j4);
        float zq[4];
        zq[0] = fmaf(c0, wa.x, fmaf(c1, wb.x, bb.x));
        zq[1] = fmaf(c0, wa.y, fmaf(c1, wb.y, bb.y));
        zq[2] = fmaf(c0, wa.z, fmaf(c1, wb.z, bb.z));
        zq[3] = fmaf(c0, wa.w, fmaf(c1, wb.w, bb.w));
#pragma unroll
        for (int ss = 0; ss < 4; ss++) {
            const float z = gelu_exact(zq[ss]);
            const int j = j4 + ss;
#pragma unroll
            for (int dq = 0; dq < 4; dq++) {
                float4 w = *reinterpret_cast<const float4*>(sm + O_PEW2 + j * 16 + dq * 4);
                h[dq * 4 + 0] = fmaf(z, w.x, h[dq * 4 + 0]);
                h[dq * 4 + 1] = fmaf(z, w.y, h[dq * 4 + 1]);
                h[dq * 4 + 2] = fmaf(z, w.z, h[dq * 4 + 2]);
                h[dq * 4 + 3] = fmaf(z, w.w, h[dq * 4 + 3]);
            }
        }
    }

    float mu = 0.f;
#pragma unroll
    for (int d = 0; d < 16; d++) { h[d] += xr[d]; mu += h[d]; }
    mu *= (1.f / 16.f);
    float var = 0.f;
#pragma unroll
    for (int d = 0; d < 16; d++) { float c = h[d] - mu; var = fmaf(c, c, var); }
    var *= (1.f / 16.f);
    const float rstd = 1.f / sqrtf(var + 1e-5f);
#pragma unroll
    for (int d = 0; d < 16; d++)
        h[d] = (h[d] - mu) * rstd * sm[O_LNG + d] + sm[O_LNB + d];

    float q[16], k[16], v[16];
#pragma unroll
    for (int d = 0; d < 16; d++) { q[d] = 0.f; k[d] = 0.f; v[d] = 0.f; }
    mat16(sm + O_QW, h, q);
    mat16(sm + O_KW, h, k);
    mat16(sm + O_VW, xr, v);

    float4* myslot = reinterpret_cast<float4*>(sm + O_KV + g * 132 + i * 8);
    float o[16];
#pragma unroll
    for (int hh = 0; hh < H; hh++) {
        float qh[4], kh[4], vh[4];
#pragma unroll
        for (int c = 0; c < 4; c++) {
            qh[c] = q[hh * 4 + c]; kh[c] = k[hh * 4 + c]; vh[c] = v[hh * 4 + c];
        }
        float qs = fmaf(qh[3], qh[3], fmaf(qh[2], qh[2], fmaf(qh[1], qh[1], qh[0] * qh[0])));
        float ks = fmaf(kh[3], kh[3], fmaf(kh[2], kh[2], fmaf(kh[1], kh[1], kh[0] * kh[0])));
        const float qi = 1.f / (sqrtf(qs) + 1e-6f);
        const float ki = 1.f / (sqrtf(ks) + 1e-6f);
#pragma unroll
        for (int c = 0; c < 4; c++) { qh[c] *= qi; kh[c] *= ki; }

        __syncwarp();
        myslot[0] = make_float4(kh[0], kh[1], kh[2], kh[3]);
        myslot[1] = make_float4(vh[0], vh[1], vh[2], vh[3]);
        __syncwarp();

        const float scl = sm[O_SC + hh];
        float lg[16];
#pragma unroll
        for (int j = 0; j < 16; j++) {
            const float4 kj = *reinterpret_cast<const float4*>(sm + O_KV + g * 132 + j * 8);
            float dot = 0.f;
            dot = fmaf(qh[0], kj.x, dot);
            dot = fmaf(qh[1], kj.y, dot);
            dot = fmaf(qh[2], kj.z, dot);
            dot = fmaf(qh[3], kj.w, dot);
            lg[j] = dot * scl;
        }
        float mx = lg[0];
#pragma unroll
        for (int j = 1; j < 16; j++) mx = fmaxf(mx, lg[j]);
        float ssum = 0.f;
#pragma unroll
        for (int j = 0; j < 16; j++) { lg[j] = expf(lg[j] - mx); ssum += lg[j]; }
        const float inv = 1.f / ssum;
        float oh[4] = {0.f, 0.f, 0.f, 0.f};
#pragma unroll
        for (int j = 0; j < 16; j++) {
            const float a = lg[j] * inv;
            const float4 vj = *reinterpret_cast<const float4*>(sm + O_KV + g * 132 + j * 8 + 4);
            oh[0] = fmaf(a, vj.x, oh[0]);
            oh[1] = fmaf(a, vj.y, oh[1]);
            oh[2] = fmaf(a, vj.z, oh[2]);
            oh[3] = fmaf(a, vj.w, oh[3]);
        }
#pragma unroll
        for (int c = 0; c < 4; c++) o[hh * 4 + c] = oh[c];
    }

    float o2[16];
#pragma unroll
    for (int d = 0; d < 16; d++) o2[d] = 0.f;
    mat16(sm + O_OW, o, o2);

    float acc2 = 0.f;
#pragma unroll
    for (int jc = 0; jc < 2; jc++) {
        float z[32];
#pragma unroll
        for (int jq = 0; jq < 8; jq++) {
            const float4 bb = *reinterpret_cast<const float4*>(sm + O_MB1 + jc * 32 + jq * 4);
            z[jq * 4 + 0] = bb.x; z[jq * 4 + 1] = bb.y;
            z[jq * 4 + 2] = bb.z; z[jq * 4 + 3] = bb.w;
        }
#pragma unroll
        for (int kk = 0; kk < 16; kk++) {
            const float ov = o2[kk];
#pragma unroll
            for (int jq = 0; jq < 8; jq++) {
                const float4 w = *reinterpret_cast<const float4*>(
                    sm + O_MW1 + kk * 64 + jc * 32 + jq * 4);
                z[jq * 4 + 0] = fmaf(ov, w.x, z[jq * 4 + 0]);
                z[jq * 4 + 1] = fmaf(ov, w.y, z[jq * 4 + 1]);
                z[jq * 4 + 2] = fmaf(ov, w.z, z[jq * 4 + 2]);
                z[jq * 4 + 3] = fmaf(ov, w.w, z[jq * 4 + 3]);
            }
        }
#pragma unroll
        for (int j = 0; j < 32; j++)
            acc2 = fmaf(gelu_exact(z[j]), sm[O_MW2 + jc * 32 + j], acc2);
    }
    const float m = gelu_exact(acc2 + sm[O_MB2]);

    float4* dst = reinterpret_cast<float4*>(g_oflat + (size_t)tok * MD + i * 16);
#pragma unroll
    for (int dq = 0; dq < 4; dq++)
        dst[dq] = make_float4(o2[dq * 4 + 0] + m, o2[dq * 4 + 1] + m,
                              o2[dq * 4 + 2] + m, o2[dq * 4 + 3] + m);
}

// ---------------------------------------------------------------------------
// K3 (fused, tf32 via raw-fp32 truncation, cp.async double-buffered staging).
// ---------------------------------------------------------------------------
__device__ __forceinline__ void mma_tf32(float* c, const uint32_t* a, const uint32_t* bb) {
    asm volatile(
        "mma.sync.aligned.m16n8k8.row.col.f32.tf32.tf32.f32 "
        "{%0,%1,%2,%3}, {%4,%5,%6,%7}, {%8,%9}, {%0,%1,%2,%3};"
        : "+f"(c[0]), "+f"(c[1]), "+f"(c[2]), "+f"(c[3])
        : "r"(a[0]), "r"(a[1]), "r"(a[2]), "r"(a[3]), "r"(bb[0]), "r"(bb[1]));
}

constexpr int APAD = 36;
constexpr int BPAD = 72;
constexpr int CPAD = 66;
constexpr int BUFU = 128 * APAD + 32 * BPAD;       // 6912 floats per buffer
constexpr int FUSED_SMEM = 2 * BUFU * 4;           // 55296 B

__global__ __launch_bounds__(256) void fused_mlp_kernel(
    const float* __restrict__ W1, const float* __restrict__ b1,
    const float* __restrict__ W2) {
    extern __shared__ __align__(16) uint32_t smem_u[];
    float* Cs  = reinterpret_cast<float*>(smem_u);
    float* W2s = reinterpret_cast<float*>(smem_u) + 128 * CPAD;
    const uint32_t smem_base = (uint32_t)__cvta_generic_to_shared(smem_u);

    const int tid  = threadIdx.x;
    const int lane = tid & 31;
    const int wid  = tid >> 5;
    const int warp_m = wid & 3;
    const int warp_n = wid >> 2;
    const int row0 = blockIdx.x * 128;
    const int cg   = blockIdx.y;

    const int a_row  = tid >> 1;
    const int a_kofs = (tid & 1) * 16;
    const int b_krow = tid >> 3;
    const int b_ncol = (tid & 7) * 8;
    const int p2row = tid >> 1;
    const int p2n   = (tid & 1) * 8;

    const float* arow_g = g_oflat + (size_t)(row0 + a_row) * MD + a_kofs;
    const uint32_t a_dst = (uint32_t)(a_row * APAD + a_kofs) * 4u;
    const uint32_t b_dst = (uint32_t)(128 * APAD + b_krow * BPAD + b_ncol) * 4u;

    float out_acc[8];
#pragma unroll
    for (int i = 0; i < 8; i++) out_acc[i] = 0.f;

    for (int ch = cg * 2; ch < cg * 2 + 2; ch++) {
        const int col0 = ch * 64;
        const float* brow_g = W1 + (size_t)b_krow * FF + col0 + b_ncol;
        float cfr[2][4][4];
#pragma unroll
        for (int ma = 0; ma < 2; ma++)
#pragma unroll
            for (int na = 0; na < 4; na++)
#pragma unroll
                for (int i = 0; i < 4; i++) cfr[ma][na][i] = 0.f;

        // prologue: stage kt=0 into buffer 0
        {
            const uint32_t base = smem_base;
#pragma unroll
            for (int q = 0; q < 4; q++)
                cp_async16(base + a_dst + q * 16, arow_g + q * 4);
#pragma unroll
            for (int q = 0; q < 2; q++)
                cp_async16(base + b_dst + q * 16, brow_g + q * 4);
            cp_commit();
        }

#pragma unroll 1
        for (int kt = 0; kt < 8; kt++) {
            __syncthreads();   // readers of the other buffer (compute kt-1) done
            if (kt < 7) {
                const uint32_t base = smem_base + (uint32_t)(((kt + 1) & 1) * BUFU) * 4u;
                const float* ag = arow_g + (kt + 1) * 32;
                const float* bg = brow_g + (size_t)(kt + 1) * 32 * FF;
#pragma unroll
                for (int q = 0; q < 4; q++)
                    cp_async16(base + a_dst + q * 16, ag + q * 4);
#pragma unroll
                for (int q = 0; q < 2; q++)
                    cp_async16(base + b_dst + q * 16, bg + q * 4);
            }
            cp_commit();       // unconditional: keeps group accounting constant
            cp_wait1();        // all but newest group done -> kt's tile resident
            __syncthreads();   // everyone's waits passed -> full tile visible

            const uint32_t* As = smem_u + (kt & 1) * BUFU;
            const uint32_t* Bs = As + 128 * APAD;
#pragma unroll
            for (int ks = 0; ks < 4; ks++) {
                const int k0 = ks * 8;
                uint32_t afr[2][4];
#pragma unroll
                for (int ma = 0; ma < 2; ma++) {
                    const int r = warp_m * 32 + ma * 16 + (lane >> 2);
                    const int kc = k0 + (lane & 3);
                    afr[ma][0] = As[r * APAD + kc];
                    afr[ma][1] = As[(r + 8) * APAD + kc];
                    afr[ma][2] = As[r * APAD + kc + 4];
                    afr[ma][3] = As[(r + 8) * APAD + kc + 4];
                }
                uint32_t bfr[4][2];
#pragma unroll
                for (int na = 0; na < 4; na++) {
                    const int n = warp_n * 32 + na * 8 + (lane >> 2);
                    const int kc = k0 + (lane & 3);
                    bfr[na][0] = Bs[kc * BPAD + n];
                    bfr[na][1] = Bs[(kc + 4) * BPAD + n];
                }
#pragma unroll
                for (int ma = 0; ma < 2; ma++)
#pragma unroll
                    for (int na = 0; na < 4; na++)
                        mma_tf32(cfr[ma][na], afr[ma], bfr[na]);
            }
        }

        __syncthreads();   // all buffer reads done before Cs overwrite

#pragma unroll
        for (int ma = 0; ma < 2; ma++) {
            const int r0 = warp_m * 32 + ma * 16 + (lane >> 2);
#pragma unroll
            for (int na = 0; na < 4; na++) {
                const int cl = warp_n * 32 + na * 8 + 2 * (lane & 3);
                const float bb0 = __ldg(b1 + col0 + cl);
                const float bb1 = __ldg(b1 + col0 + cl + 1);
                float2 v0, v1;
                v0.x = gelu_exact(cfr[ma][na][0] + bb0);
                v0.y = gelu_exact(cfr[ma][na][1] + bb1);
                v1.x = gelu_exact(cfr[ma][na][2] + bb0);
                v1.y = gelu_exact(cfr[ma][na][3] + bb1);
                *reinterpret_cast<float2*>(&Cs[r0 * CPAD + cl]) = v0;
                *reinterpret_cast<float2*>(&Cs[(r0 + 8) * CPAD + cl]) = v1;
            }
        }
        *reinterpret_cast<float4*>(&W2s[(tid >> 2) * 16 + (tid & 3) * 4]) =
            *reinterpret_cast<const float4*>(W2 + (size_t)(col0 + (tid >> 2)) * 16 + (tid & 3) * 4);
        __syncthreads();

#pragma unroll 8
        for (int c = 0; c < 64; c++) {
            const float cv = Cs[p2row * CPAD + c];
            const float4 wa = *reinterpret_cast<const float4*>(&W2s[c * 16 + p2n]);
            const float4 wb = *reinterpret_cast<const float4*>(&W2s[c * 16 + p2n + 4]);
            out_acc[0] = fmaf(cv, wa.x, out_acc[0]);
            out_acc[1] = fmaf(cv, wa.y, out_acc[1]);
            out_acc[2] = fmaf(cv, wa.z, out_acc[2]);
            out_acc[3] = fmaf(cv, wa.w, out_acc[3]);
            out_acc[4] = fmaf(cv, wb.x, out_acc[4]);
            out_acc[5] = fmaf(cv, wb.y, out_acc[5]);
            out_acc[6] = fmaf(cv, wb.z, out_acc[6]);
            out_acc[7] = fmaf(cv, wb.w, out_acc[7]);
        }
        __syncthreads();   // phase-2 reads done before next chunk's staging
    }

    float* prow = &g_partial[cg][(size_t)(row0 + p2row) * OUT + p2n];
    *reinterpret_cast<float4*>(prow)     = make_float4(out_acc[0], out_acc[1], out_acc[2], out_acc[3]);
    *reinterpret_cast<float4*>(prow + 4) = make_float4(out_acc[4], out_acc[5], out_acc[6], out_acc[7]);
}

// ---------------------------------------------------------------------------
// K4: out = gelu(sum_cg partial + b2). Fixed summation order -> deterministic.
// ---------------------------------------------------------------------------
__global__ __launch_bounds__(256) void out_reduce(const float* __restrict__ b2,
                                                  float* __restrict__ out) {
    const int gid = blockIdx.x * 256 + threadIdx.x;
    const int n = gid & (OUT - 1);
    float s = g_partial[0][gid];
#pragma unroll
    for (int cg = 1; cg < NCG; cg++) s += g_partial[cg][gid];
    out[gid] = gelu_exact(s + b2[n]);
}

// ---------------------------------------------------------------------------
extern "C" void kernel_launch(void* const* d_in, const int* in_sizes, int n_in,
                              void* d_out, int out_size) {
    const float* x      = (const float*)d_in[0];
    const float* ct     = (const float*)d_in[1];
    const float* cs     = (const float*)d_in[2];
    const float* pe_w1  = (const float*)d_in[3];
    const float* pe_b1  = (const float*)d_in[4];
    const float* pe_w2  = (const float*)d_in[5];
    const float* pe_b2  = (const float*)d_in[6];
    const float* ln_g   = (const float*)d_in[7];
    const float* ln_b   = (const float*)d_in[8];
    const float* q_w    = (const float*)d_in[9];
    const float* k_w    = (const float*)d_in[10];
    const float* v_w    = (const float*)d_in[11];
    const float* ls     = (const float*)d_in[12];
    const float* out_w  = (const float*)d_in[13];
    const float* mnh_w1 = (const float*)d_in[14];
    const float* mnh_b1 = (const float*)d_in[15];
    const float* mnh_w2 = (const float*)d_in[16];
    const float* mnh_b2 = (const float*)d_in[17];
    const float* mo_w1  = (const float*)d_in[18];
    const float* mo_b1  = (const float*)d_in[19];
    const float* mo_w2  = (const float*)d_in[20];
    const float* mo_b2  = (const float*)d_in[21];

    cudaFuncSetAttribute(fused_mlp_kernel,
                         cudaFuncAttributeMaxDynamicSharedMemorySize, FUSED_SMEM);

    grid_build<<<B, 256>>>(cs);
    grid_build_t<<<B, 256>>>(ct);
    knn_kernel<<<dim3(T / 64, B), 128>>>();
    token_kernel<<<NTOK / 16, 256>>>(x, ct, cs, pe_w1, pe_b1, pe_w2, pe_b2,
                                     ln_g, ln_b, q_w, k_w, v_w, ls, out_w,
                                     mnh_w1, mnh_b1, mnh_w2, mnh_b2);
    fused_mlp_kernel<<<dim3(NTOK / 128, NCG), 256, FUSED_SMEM>>>(mo_w1, mo_b1, mo_w2);
    out_reduce<<<NTOK * OUT / 256, 256>>>(mo_b2, (float*)d_out);
}

// round 14
// speedup vs baseline: 2.4450x; 1.2384x over previous
#include <cuda_runtime.h>
#include <math.h>
#include <stdint.h>

constexpr int B = 4, T = 4096, S = 4096, E = 16;
constexpr int NH = 16, H = 4, FFNH = 64;
constexpr int MD = 256, FF = 1024, OUT = 16;
constexpr int NTOK = B * T;
constexpr int GC = 16;                 // knn grid cells per axis
constexpr int NCG = 8;                 // fused-MLP column groups

// Scratch (static device allocations — no cudaMalloc allowed)
__device__ int    g_idx[NTOK * NH];                // 1 MB
__device__ float  g_oflat[(size_t)NTOK * MD];      // 16.8 MB (RNA-tf32 values)
__device__ float  g_w1r[MD * FF];                  // 1 MB  (RNA-tf32 W1)
__device__ float2 g_gxy[B][S];
__device__ int    g_gid[B][S];
__device__ int    g_cstart[B][GC * GC + 1];
__device__ float2 g_txy[B][T];                     // spatially-sorted targets
__device__ int    g_tid_[B][T];
__device__ float  g_partial[NCG][(size_t)NTOK * OUT];

__device__ __forceinline__ float gelu_exact(float x) {
    return 0.5f * x * (1.0f + erff(x * 0.70710678118654752f));
}

__device__ __forceinline__ float tf32_rna(float f) {
    uint32_t u;
    asm("cvt.rna.tf32.f32 %0, %1;" : "=r"(u) : "f"(f));
    return __uint_as_float(u);
}

__device__ __forceinline__ void cp_async16(uint32_t dst, const void* src) {
    asm volatile("cp.async.cg.shared.global [%0], [%1], 16;\n" :: "r"(dst), "l"(src));
}
__device__ __forceinline__ void cp_commit() {
    asm volatile("cp.async.commit_group;\n" ::);
}
__device__ __forceinline__ void cp_wait1() {
    asm volatile("cp.async.wait_group 1;\n" ::);
}

// ---------------------------------------------------------------------------
// K-1: pre-round W1 to RNA tf32 (restores round-to-nearest for the GEMM's
// B operand; fused's implicit truncation is then a no-op).
// ---------------------------------------------------------------------------
__global__ __launch_bounds__(256) void w1_round(const float* __restrict__ W1) {
    const int i = blockIdx.x * 256 + threadIdx.x;
    g_w1r[i] = tf32_rna(W1[i]);
}

// ---------------------------------------------------------------------------
// K0a/K0b: counting-sort sources AND targets into the 16x16 grid.
// ---------------------------------------------------------------------------
__global__ __launch_bounds__(256) void grid_build(const float* __restrict__ cs) {
    __shared__ int cnt[GC * GC];
    __shared__ int start[GC * GC + 1];
    const int b = blockIdx.x, tid = threadIdx.x;
    cnt[tid] = 0;
    __syncthreads();
    const float2* csb = reinterpret_cast<const float2*>(cs) + (size_t)b * S;
    for (int i = tid; i < S; i += 256) {
        float2 c = csb[i];
        int cx = min(GC - 1, (int)(c.x * GC));
        int cy = min(GC - 1, (int)(c.y * GC));
        atomicAdd(&cnt[cy * GC + cx], 1);
    }
    __syncthreads();
    if (tid == 0) {
        int acc = 0;
        for (int i = 0; i < GC * GC; i++) { start[i] = acc; acc += cnt[i]; }
        start[GC * GC] = acc;
    }
    __syncthreads();
    cnt[tid] = start[tid];
    g_cstart[b][tid] = start[tid];
    if (tid == 0) g_cstart[b][GC * GC] = start[GC * GC];
    __syncthreads();
    for (int i = tid; i < S; i += 256) {
        float2 c = csb[i];
        int cx = min(GC - 1, (int)(c.x * GC));
        int cy = min(GC - 1, (int)(c.y * GC));
        int pos = atomicAdd(&cnt[cy * GC + cx], 1);
        g_gxy[b][pos] = c;
        g_gid[b][pos] = i;
    }
}

__global__ __launch_bounds__(256) void grid_build_t(const float* __restrict__ ct) {
    __shared__ int cnt[GC * GC];
    __shared__ int start[GC * GC + 1];
    const int b = blockIdx.x, tid = threadIdx.x;
    cnt[tid] = 0;
    __syncthreads();
    const float2* ctb = reinterpret_cast<const float2*>(ct) + (size_t)b * T;
    for (int i = tid; i < T; i += 256) {
        float2 c = ctb[i];
        int cx = min(GC - 1, (int)(c.x * GC));
        int cy = min(GC - 1, (int)(c.y * GC));
        atomicAdd(&cnt[cy * GC + cx], 1);
    }
    __syncthreads();
    if (tid == 0) {
        int acc = 0;
        for (int i = 0; i < GC * GC; i++) { start[i] = acc; acc += cnt[i]; }
        start[GC * GC] = acc;
    }
    __syncthreads();
    cnt[tid] = start[tid];
    __syncthreads();
    for (int i = tid; i < T; i += 256) {
        float2 c = ctb[i];
        int cx = min(GC - 1, (int)(c.x * GC));
        int cy = min(GC - 1, (int)(c.y * GC));
        int pos = atomicAdd(&cnt[cy * GC + cx], 1);
        g_txy[b][pos] = c;
        g_tid_[b][pos] = i;
    }
}

// ---------------------------------------------------------------------------
// K1: exact 16-NN via expanding grid rings, spatially-sorted targets,
// lane-pair parity split, snapshot-then-merge. Unchanged (passing).
// ---------------------------------------------------------------------------
__global__ __launch_bounds__(128) void knn_kernel() {
    const int b = blockIdx.y;
    const int lane = threadIdx.x & 31;
    const int par = threadIdx.x & 1;
    const unsigned pairmask = 3u << (lane & ~1);
    const int s = blockIdx.x * 64 + (threadIdx.x >> 1);
    const float2 tc = g_txy[b][s];
    const int torig = g_tid_[b][s];
    const float tx = tc.x, ty = tc.y;
    const int cx = min(GC - 1, (int)(tx * GC));
    const int cy = min(GC - 1, (int)(ty * GC));

    const float2* __restrict__ gxy = g_gxy[b];
    const int*    __restrict__ gid = g_gid[b];
    const int*    __restrict__ cst = g_cstart[b];
    constexpr float hcell = 1.0f / GC;
    constexpr unsigned long long KMAX = 0xFFFFFFFFFFFFFFFFull;

    unsigned long long key[NH];
#pragma unroll
    for (int i = 0; i < NH; i++) key[i] = KMAX;

    for (int rho = 0; rho <= GC - 1; rho++) {
        if (rho > 1) {
            float wl = __uint_as_float((unsigned)(key[NH - 1] >> 32));
            float wo = __shfl_xor_sync(pairmask, wl, 1);
            float wd2 = fminf(wl, wo);
            const float bound = (rho - 1) * hcell;
            if (wd2 < bound * bound) break;
        }
        const int ylo = max(cy - rho, 0), yhi = min(cy + rho, GC - 1);
        for (int ay = ylo; ay <= yhi; ay++) {
            const bool fullrow = (ay == cy - rho) || (ay == cy + rho);
            const int step = fullrow ? 1 : (rho > 0 ? 2 * rho : 1);
            for (int ax = cx - rho; ax <= cx + rho; ax += step) {
                if (ax < 0 || ax >= GC) continue;
                if (((ax + ay) & 1) != par) continue;
                const int cell = ay * GC + ax;
                const int c1 = cst[cell + 1];
                for (int j = cst[cell]; j < c1; j++) {
                    const float2 p = gxy[j];
                    const float dxx = tx - p.x, dyy = ty - p.y;
                    const float d2 = fmaf(dyy, dyy, dxx * dxx);
                    unsigned long long ck =
                        ((unsigned long long)__float_as_uint(d2) << 32) |
                        (unsigned)gid[j];
                    if (ck < key[NH - 1]) {
                        bool ins = false;
#pragma unroll
                        for (int q = 0; q < NH; q++) {
                            bool sm = ins | (ck < key[q]);
                            unsigned long long tk = key[q];
                            key[q] = sm ? ck : tk;
                            ck = sm ? tk : ck;
                            ins = sm;
                        }
                    }
                }
            }
        }
    }

    unsigned long long pk[NH];
#pragma unroll
    for (int i = 0; i < NH; i++)
        pk[i] = __shfl_xor_sync(pairmask, key[i], 1);
#pragma unroll
    for (int i = 0; i < NH; i++) {
        unsigned long long ck = pk[i];
        if (ck < key[NH - 1]) {
            bool ins = false;
#pragma unroll
            for (int q = 0; q < NH; q++) {
                bool sm = ins | (ck < key[q]);
                unsigned long long tk = key[q];
                key[q] = sm ? ck : tk;
                ck = sm ? tk : ck;
                ins = sm;
            }
        }
    }

    if (par == 0) {
        const int base = (b * T + torig) * NH;
#pragma unroll
        for (int i = 0; i < NH; i++)
            g_idx[base + i] = (int)(key[i] & 0xFFFFFFFFull);
    }
}

// ---------------------------------------------------------------------------
// K2: per-token pipeline. This round: __launch_bounds__(256,3) (reg cap 85
// -> 3 blocks/SM), mnh in 4 chunks of 16 (lower live-reg peak, same j order),
// erff-based exact gelu, RNA-tf32 rounding of the g_oflat store.
// ---------------------------------------------------------------------------
constexpr int O_PEW1 = 0;
constexpr int O_PEB1 = 128;
constexpr int O_PEW2 = 192;
constexpr int O_PEB2 = 1216;
constexpr int O_LNG  = 1232;
constexpr int O_LNB  = 1248;
constexpr int O_QW   = 1264;
constexpr int O_KW   = 1520;
constexpr int O_VW   = 1776;
constexpr int O_OW   = 2032;
constexpr int O_MW1  = 2288;
constexpr int O_MB1  = 3312;
constexpr int O_MW2  = 3376;
constexpr int O_MB2  = 3440;
constexpr int O_SC   = 3444;
constexpr int O_KV   = 3448;
constexpr int SM_TOT = 3448 + 16 * 132;

__device__ __forceinline__ void mat16(const float* __restrict__ Wsh,
                                      const float* __restrict__ vin,
                                      float* __restrict__ vout) {
#pragma unroll
    for (int k = 0; k < 16; k++) {
        const float hv = vin[k];
#pragma unroll
        for (int dq = 0; dq < 4; dq++) {
            float4 w = *reinterpret_cast<const float4*>(Wsh + k * 16 + dq * 4);
            vout[dq * 4 + 0] = fmaf(hv, w.x, vout[dq * 4 + 0]);
            vout[dq * 4 + 1] = fmaf(hv, w.y, vout[dq * 4 + 1]);
            vout[dq * 4 + 2] = fmaf(hv, w.z, vout[dq * 4 + 2]);
            vout[dq * 4 + 3] = fmaf(hv, w.w, vout[dq * 4 + 3]);
        }
    }
}

__global__ __launch_bounds__(256, 3) void token_kernel(
    const float* __restrict__ x, const float* __restrict__ ct, const float* __restrict__ cs,
    const float* __restrict__ pe_w1, const float* __restrict__ pe_b1,
    const float* __restrict__ pe_w2, const float* __restrict__ pe_b2,
    const float* __restrict__ ln_g, const float* __restrict__ ln_b,
    const float* __restrict__ q_w, const float* __restrict__ k_w,
    const float* __restrict__ v_w, const float* __restrict__ lscale,
    const float* __restrict__ out_w,
    const float* __restrict__ mnh_w1, const float* __restrict__ mnh_b1,
    const float* __restrict__ mnh_w2, const float* __restrict__ mnh_b2) {
    __shared__ float sm[SM_TOT];
    const int tid = threadIdx.x;
    for (int i = tid; i < 128;  i += 256) sm[O_PEW1 + i] = pe_w1[i];
    for (int i = tid; i < 64;   i += 256) sm[O_PEB1 + i] = pe_b1[i];
    for (int i = tid; i < 1024; i += 256) sm[O_PEW2 + i] = pe_w2[i];
    for (int i = tid; i < 16;   i += 256) sm[O_PEB2 + i] = pe_b2[i];
    for (int i = tid; i < 16;   i += 256) sm[O_LNG + i]  = ln_g[i];
    for (int i = tid; i < 16;   i += 256) sm[O_LNB + i]  = ln_b[i];
    for (int i = tid; i < 256;  i += 256) sm[O_QW + i]   = q_w[i];
    for (int i = tid; i < 256;  i += 256) sm[O_KW + i]   = k_w[i];
    for (int i = tid; i < 256;  i += 256) sm[O_VW + i]   = v_w[i];
    for (int i = tid; i < 256;  i += 256) sm[O_OW + i]   = out_w[i];
    for (int i = tid; i < 1024; i += 256) sm[O_MW1 + i]  = mnh_w1[i];
    for (int i = tid; i < 64;   i += 256) sm[O_MB1 + i]  = mnh_b1[i];
    for (int i = tid; i < 64;   i += 256) sm[O_MW2 + i]  = mnh_w2[i];
    if (tid == 0) sm[O_MB2] = mnh_b2[0];
    if (tid < 4)  sm[O_SC + tid] = expf(fminf(lscale[tid], 4.6051702f));
    __syncthreads();

    const int tok = blockIdx.x * 16 + (tid >> 4);
    const int g   = tid >> 4;
    const int i   = tid & 15;
    const int b   = tok / T;
    const int nidx = g_idx[tok * NH + i];

    float xr[16];
    const float4* xrow = reinterpret_cast<const float4*>(x + ((size_t)b * S + nidx) * E);
#pragma unroll
    for (int q4 = 0; q4 < 4; q4++) {
        float4 v4 = __ldg(xrow + q4);
        xr[q4 * 4 + 0] = v4.x; xr[q4 * 4 + 1] = v4.y;
        xr[q4 * 4 + 2] = v4.z; xr[q4 * 4 + 3] = v4.w;
    }
    const float2 scoord = __ldg(reinterpret_cast<const float2*>(cs) + (size_t)b * S + nidx);
    const float2 tcoord = __ldg(reinterpret_cast<const float2*>(ct) + tok);
    const float c0 = scoord.x - tcoord.x, c1 = scoord.y - tcoord.y;

    float h[16];
#pragma unroll
    for (int d = 0; d < 16; d++) h[d] = sm[O_PEB2 + d];
#pragma unroll
    for (int j4 = 0; j4 < FFNH; j4 += 4) {
        const float4 wa = *reinterpret_cast<const float4*>(sm + O_PEW1 + j4);
        const float4 wb = *reinterpret_cast<const float4*>(sm + O_PEW1 + 64 + j4);
        const float4 bb = *reinterpret_cast<const float4*>(sm + O_PEB1 + j4);
        float zq[4];
        zq[0] = fmaf(c0, wa.x, fmaf(c1, wb.x, bb.x));
        zq[1] = fmaf(c0, wa.y, fmaf(c1, wb.y, bb.y));
        zq[2] = fmaf(c0, wa.z, fmaf(c1, wb.z, bb.z));
        zq[3] = fmaf(c0, wa.w, fmaf(c1, wb.w, bb.w));
#pragma unroll
        for (int ss = 0; ss < 4; ss++) {
            const float z = gelu_exact(zq[ss]);
            const int j = j4 + ss;
#pragma unroll
            for (int dq = 0; dq < 4; dq++) {
                float4 w = *reinterpret_cast<const float4*>(sm + O_PEW2 + j * 16 + dq * 4);
                h[dq * 4 + 0] = fmaf(z, w.x, h[dq * 4 + 0]);
                h[dq * 4 + 1] = fmaf(z, w.y, h[dq * 4 + 1]);
                h[dq * 4 + 2] = fmaf(z, w.z, h[dq * 4 + 2]);
                h[dq * 4 + 3] = fmaf(z, w.w, h[dq * 4 + 3]);
            }
        }
    }

    float mu = 0.f;
#pragma unroll
    for (int d = 0; d < 16; d++) { h[d] += xr[d]; mu += h[d]; }
    mu *= (1.f / 16.f);
    float var = 0.f;
#pragma unroll
    for (int d = 0; d < 16; d++) { float c = h[d] - mu; var = fmaf(c, c, var); }
    var *= (1.f / 16.f);
    const float rstd = 1.f / sqrtf(var + 1e-5f);
#pragma unroll
    for (int d = 0; d < 16; d++)
        h[d] = (h[d] - mu) * rstd * sm[O_LNG + d] + sm[O_LNB + d];

    float q[16], k[16], v[16];
#pragma unroll
    for (int d = 0; d < 16; d++) { q[d] = 0.f; k[d] = 0.f; v[d] = 0.f; }
    mat16(sm + O_QW, h, q);
    mat16(sm + O_KW, h, k);
    mat16(sm + O_VW, xr, v);

    float4* myslot = reinterpret_cast<float4*>(sm + O_KV + g * 132 + i * 8);
    float o[16];
#pragma unroll
    for (int hh = 0; hh < H; hh++) {
        float qh[4], kh[4], vh[4];
#pragma unroll
        for (int c = 0; c < 4; c++) {
            qh[c] = q[hh * 4 + c]; kh[c] = k[hh * 4 + c]; vh[c] = v[hh * 4 + c];
        }
        float qs = fmaf(qh[3], qh[3], fmaf(qh[2], qh[2], fmaf(qh[1], qh[1], qh[0] * qh[0])));
        float ks = fmaf(kh[3], kh[3], fmaf(kh[2], kh[2], fmaf(kh[1], kh[1], kh[0] * kh[0])));
        const float qi = 1.f / (sqrtf(qs) + 1e-6f);
        const float ki = 1.f / (sqrtf(ks) + 1e-6f);
#pragma unroll
        for (int c = 0; c < 4; c++) { qh[c] *= qi; kh[c] *= ki; }

        __syncwarp();
        myslot[0] = make_float4(kh[0], kh[1], kh[2], kh[3]);
        myslot[1] = make_float4(vh[0], vh[1], vh[2], vh[3]);
        __syncwarp();

        const float scl = sm[O_SC + hh];
        float lg[16];
#pragma unroll
        for (int j = 0; j < 16; j++) {
            const float4 kj = *reinterpret_cast<const float4*>(sm + O_KV + g * 132 + j * 8);
            float dot = 0.f;
            dot = fmaf(qh[0], kj.x, dot);
            dot = fmaf(qh[1], kj.y, dot);
            dot = fmaf(qh[2], kj.z, dot);
            dot = fmaf(qh[3], kj.w, dot);
            lg[j] = dot * scl;
        }
        float mx = lg[0];
#pragma unroll
        for (int j = 1; j < 16; j++) mx = fmaxf(mx, lg[j]);
        float ssum = 0.f;
#pragma unroll
        for (int j = 0; j < 16; j++) { lg[j] = expf(lg[j] - mx); ssum += lg[j]; }
        const float inv = 1.f / ssum;
        float oh[4] = {0.f, 0.f, 0.f, 0.f};
#pragma unroll
        for (int j = 0; j < 16; j++) {
            const float a = lg[j] * inv;
            const float4 vj = *reinterpret_cast<const float4*>(sm + O_KV + g * 132 + j * 8 + 4);
            oh[0] = fmaf(a, vj.x, oh[0]);
            oh[1] = fmaf(a, vj.y, oh[1]);
            oh[2] = fmaf(a, vj.z, oh[2]);
            oh[3] = fmaf(a, vj.w, oh[3]);
        }
#pragma unroll
        for (int c = 0; c < 4; c++) o[hh * 4 + c] = oh[c];
    }

    float o2[16];
#pragma unroll
    for (int d = 0; d < 16; d++) o2[d] = 0.f;
    mat16(sm + O_OW, o, o2);

    // per-neighbor MLP: 4 chunks of 16 (lower live-register peak, same order)
    float acc2 = 0.f;
#pragma unroll
    for (int jc = 0; jc < 4; jc++) {
        float z[16];
#pragma unroll
        for (int jq = 0; jq < 4; jq++) {
            const float4 bb = *reinterpret_cast<const float4*>(sm + O_MB1 + jc * 16 + jq * 4);
            z[jq * 4 + 0] = bb.x; z[jq * 4 + 1] = bb.y;
            z[jq * 4 + 2] = bb.z; z[jq * 4 + 3] = bb.w;
        }
#pragma unroll
        for (int kk = 0; kk < 16; kk++) {
            const float ov = o2[kk];
#pragma unroll
            for (int jq = 0; jq < 4; jq++) {
                const float4 w = *reinterpret_cast<const float4*>(
                    sm + O_MW1 + kk * 64 + jc * 16 + jq * 4);
                z[jq * 4 + 0] = fmaf(ov, w.x, z[jq * 4 + 0]);
                z[jq * 4 + 1] = fmaf(ov, w.y, z[jq * 4 + 1]);
                z[jq * 4 + 2] = fmaf(ov, w.z, z[jq * 4 + 2]);
                z[jq * 4 + 3] = fmaf(ov, w.w, z[jq * 4 + 3]);
            }
        }
#pragma unroll
        for (int j = 0; j < 16; j++)
            acc2 = fmaf(gelu_exact(z[j]), sm[O_MW2 + jc * 16 + j], acc2);
    }
    const float m = gelu_exact(acc2 + sm[O_MB2]);

    // store RNA-tf32-rounded (fused truncation then becomes a no-op)
    float4* dst = reinterpret_cast<float4*>(g_oflat + (size_t)tok * MD + i * 16);
#pragma unroll
    for (int dq = 0; dq < 4; dq++)
        dst[dq] = make_float4(tf32_rna(o2[dq * 4 + 0] + m), tf32_rna(o2[dq * 4 + 1] + m),
                              tf32_rna(o2[dq * 4 + 2] + m), tf32_rna(o2[dq * 4 + 3] + m));
}

// ---------------------------------------------------------------------------
// K3 (fused, RNA-tf32 operands staged via cp.async, double-buffered).
// ---------------------------------------------------------------------------
__device__ __forceinline__ void mma_tf32(float* c, const uint32_t* a, const uint32_t* bb) {
    asm volatile(
        "mma.sync.aligned.m16n8k8.row.col.f32.tf32.tf32.f32 "
        "{%0,%1,%2,%3}, {%4,%5,%6,%7}, {%8,%9}, {%0,%1,%2,%3};"
        : "+f"(c[0]), "+f"(c[1]), "+f"(c[2]), "+f"(c[3])
        : "r"(a[0]), "r"(a[1]), "r"(a[2]), "r"(a[3]), "r"(bb[0]), "r"(bb[1]));
}

constexpr int APAD = 36;
constexpr int BPAD = 72;
constexpr int CPAD = 66;
constexpr int BUFU = 128 * APAD + 32 * BPAD;       // 6912 floats per buffer
constexpr int FUSED_SMEM = 2 * BUFU * 4;           // 55296 B

__global__ __launch_bounds__(256) void fused_mlp_kernel(
    const float* __restrict__ b1, const float* __restrict__ W2) {
    extern __shared__ __align__(16) uint32_t smem_u[];
    float* Cs  = reinterpret_cast<float*>(smem_u);
    float* W2s = reinterpret_cast<float*>(smem_u) + 128 * CPAD;
    const uint32_t smem_base = (uint32_t)__cvta_generic_to_shared(smem_u);

    const int tid  = threadIdx.x;
    const int lane = tid & 31;
    const int wid  = tid >> 5;
    const int warp_m = wid & 3;
    const int warp_n = wid >> 2;
    const int row0 = blockIdx.x * 128;
    const int cg   = blockIdx.y;

    const int a_row  = tid >> 1;
    const int a_kofs = (tid & 1) * 16;
    const int b_krow = tid >> 3;
    const int b_ncol = (tid & 7) * 8;
    const int p2row = tid >> 1;
    const int p2n   = (tid & 1) * 8;

    const float* arow_g = g_oflat + (size_t)(row0 + a_row) * MD + a_kofs;
    const uint32_t a_dst = (uint32_t)(a_row * APAD + a_kofs) * 4u;
    const uint32_t b_dst = (uint32_t)(128 * APAD + b_krow * BPAD + b_ncol) * 4u;

    float out_acc[8];
#pragma unroll
    for (int i = 0; i < 8; i++) out_acc[i] = 0.f;

    for (int ch = cg * 2; ch < cg * 2 + 2; ch++) {
        const int col0 = ch * 64;
        const float* brow_g = g_w1r + (size_t)b_krow * FF + col0 + b_ncol;
        float cfr[2][4][4];
#pragma unroll
        for (int ma = 0; ma < 2; ma++)
#pragma unroll
            for (int na = 0; na < 4; na++)
#pragma unroll
                for (int i = 0; i < 4; i++) cfr[ma][na][i] = 0.f;

        // prologue: stage kt=0 into buffer 0
        {
            const uint32_t base = smem_base;
#pragma unroll
            for (int q = 0; q < 4; q++)
                cp_async16(base + a_dst + q * 16, arow_g + q * 4);
#pragma unroll
            for (int q = 0; q < 2; q++)
                cp_async16(base + b_dst + q * 16, brow_g + q * 4);
            cp_commit();
        }

#pragma unroll 1
        for (int kt = 0; kt < 8; kt++) {
            __syncthreads();   // readers of the other buffer (compute kt-1) done
            if (kt < 7) {
                const uint32_t base = smem_base + (uint32_t)(((kt + 1) & 1) * BUFU) * 4u;
                const float* ag = arow_g + (kt + 1) * 32;
                const float* bg = brow_g + (size_t)(kt + 1) * 32 * FF;
#pragma unroll
                for (int q = 0; q < 4; q++)
                    cp_async16(base + a_dst + q * 16, ag + q * 4);
#pragma unroll
                for (int q = 0; q < 2; q++)
                    cp_async16(base + b_dst + q * 16, bg + q * 4);
            }
            cp_commit();       // unconditional: keeps group accounting constant
            cp_wait1();        // all but newest group done -> kt's tile resident
            __syncthreads();   // everyone's waits passed -> full tile visible

            const uint32_t* As = smem_u + (kt & 1) * BUFU;
            const uint32_t* Bs = As + 128 * APAD;
#pragma unroll
            for (int ks = 0; ks < 4; ks++) {
                const int k0 = ks * 8;
                uint32_t afr[2][4];
#pragma unroll
                for (int ma = 0; ma < 2; ma++) {
                    const int r = warp_m * 32 + ma * 16 + (lane >> 2);
                    const int kc = k0 + (lane & 3);
                    afr[ma][0] = As[r * APAD + kc];
                    afr[ma][1] = As[(r + 8) * APAD + kc];
                    afr[ma][2] = As[r * APAD + kc + 4];
                    afr[ma][3] = As[(r + 8) * APAD + kc + 4];
                }
                uint32_t bfr[4][2];
#pragma unroll
                for (int na = 0; na < 4; na++) {
                    const int n = warp_n * 32 + na * 8 + (lane >> 2);
                    const int kc = k0 + (lane & 3);
                    bfr[na][0] = Bs[kc * BPAD + n];
                    bfr[na][1] = Bs[(kc + 4) * BPAD + n];
                }
#pragma unroll
                for (int ma = 0; ma < 2; ma++)
#pragma unroll
                    for (int na = 0; na < 4; na++)
                        mma_tf32(cfr[ma][na], afr[ma], bfr[na]);
            }
        }

        __syncthreads();   // all buffer reads done before Cs overwrite

#pragma unroll
        for (int ma = 0; ma < 2; ma++) {
            const int r0 = warp_m * 32 + ma * 16 + (lane >> 2);
#pragma unroll
            for (int na = 0; na < 4; na++) {
                const int cl = warp_n * 32 + na * 8 + 2 * (lane & 3);
                const float bb0 = __ldg(b1 + col0 + cl);
                const float bb1 = __ldg(b1 + col0 + cl + 1);
                float2 v0, v1;
                v0.x = gelu_exact(cfr[ma][na][0] + bb0);
                v0.y = gelu_exact(cfr[ma][na][1] + bb1);
                v1.x = gelu_exact(cfr[ma][na][2] + bb0);
                v1.y = gelu_exact(cfr[ma][na][3] + bb1);
                *reinterpret_cast<float2*>(&Cs[r0 * CPAD + cl]) = v0;
                *reinterpret_cast<float2*>(&Cs[(r0 + 8) * CPAD + cl]) = v1;
            }
        }
        *reinterpret_cast<float4*>(&W2s[(tid >> 2) * 16 + (tid & 3) * 4]) =
            *reinterpret_cast<const float4*>(W2 + (size_t)(col0 + (tid >> 2)) * 16 + (tid & 3) * 4);
        __syncthreads();

#pragma unroll 8
        for (int c = 0; c < 64; c++) {
            const float cv = Cs[p2row * CPAD + c];
            const float4 wa = *reinterpret_cast<const float4*>(&W2s[c * 16 + p2n]);
            const float4 wb = *reinterpret_cast<const float4*>(&W2s[c * 16 + p2n + 4]);
            out_acc[0] = fmaf(cv, wa.x, out_acc[0]);
            out_acc[1] = fmaf(cv, wa.y, out_acc[1]);
            out_acc[2] = fmaf(cv, wa.z, out_acc[2]);
            out_acc[3] = fmaf(cv, wa.w, out_acc[3]);
            out_acc[4] = fmaf(cv, wb.x, out_acc[4]);
            out_acc[5] = fmaf(cv, wb.y, out_acc[5]);
            out_acc[6] = fmaf(cv, wb.z, out_acc[6]);
            out_acc[7] = fmaf(cv, wb.w, out_acc[7]);
        }
        __syncthreads();   // phase-2 reads done before next chunk's staging
    }

    float* prow = &g_partial[cg][(size_t)(row0 + p2row) * OUT + p2n];
    *reinterpret_cast<float4*>(prow)     = make_float4(out_acc[0], out_acc[1], out_acc[2], out_acc[3]);
    *reinterpret_cast<float4*>(prow + 4) = make_float4(out_acc[4], out_acc[5], out_acc[6], out_acc[7]);
}

// ---------------------------------------------------------------------------
// K4: out = gelu(sum_cg partial + b2). Fixed summation order -> deterministic.
// ---------------------------------------------------------------------------
__global__ __launch_bounds__(256) void out_reduce(const float* __restrict__ b2,
                                                  float* __restrict__ out) {
    const int gid = blockIdx.x * 256 + threadIdx.x;
    const int n = gid & (OUT - 1);
    float s = g_partial[0][gid];
#pragma unroll
    for (int cg = 1; cg < NCG; cg++) s += g_partial[cg][gid];
    out[gid] = gelu_exact(s + b2[n]);
}

// ---------------------------------------------------------------------------
extern "C" void kernel_launch(void* const* d_in, const int* in_sizes, int n_in,
                              void* d_out, int out_size) {
    const float* x      = (const float*)d_in[0];
    const float* ct     = (const float*)d_in[1];
    const float* cs     = (const float*)d_in[2];
    const float* pe_w1  = (const float*)d_in[3];
    const float* pe_b1  = (const float*)d_in[4];
    const float* pe_w2  = (const float*)d_in[5];
    const float* pe_b2  = (const float*)d_in[6];
    const float* ln_g   = (const float*)d_in[7];
    const float* ln_b   = (const float*)d_in[8];
    const float* q_w    = (const float*)d_in[9];
    const float* k_w    = (const float*)d_in[10];
    const float* v_w    = (const float*)d_in[11];
    const float* ls     = (const float*)d_in[12];
    const float* out_w  = (const float*)d_in[13];
    const float* mnh_w1 = (const float*)d_in[14];
    const float* mnh_b1 = (const float*)d_in[15];
    const float* mnh_w2 = (const float*)d_in[16];
    const float* mnh_b2 = (const float*)d_in[17];
    const float* mo_w1  = (const float*)d_in[18];
    const float* mo_b1  = (const float*)d_in[19];
    const float* mo_w2  = (const float*)d_in[20];
    const float* mo_b2  = (const float*)d_in[21];

    cudaFuncSetAttribute(fused_mlp_kernel,
                         cudaFuncAttributeMaxDynamicSharedMemorySize, FUSED_SMEM);

    w1_round<<<MD * FF / 256, 256>>>(mo_w1);
    grid_build<<<B, 256>>>(cs);
    grid_build_t<<<B, 256>>>(ct);
    knn_kernel<<<dim3(T / 64, B), 128>>>();
    token_kernel<<<NTOK / 16, 256>>>(x, ct, cs, pe_w1, pe_b1, pe_w2, pe_b2,
                                     ln_g, ln_b, q_w, k_w, v_w, ls, out_w,
                                     mnh_w1, mnh_b1, mnh_w2, mnh_b2);
    fused_mlp_kernel<<<dim3(NTOK / 128, NCG), 256, FUSED_SMEM>>>(mo_b1, mo_w2);
    out_reduce<<<NTOK * OUT / 256, 256>>>(mo_b2, (float*)d_out);
}